// round 1
// baseline (speedup 1.0000x reference)
#include <cuda_runtime.h>
#include <cuda_bf16.h>

#define S     6561
#define Dm    34
#define HD    17
#define PH    20      // padded head-dim stride (floats), 80B = float4-aligned
#define FFd   2048
#define NH    2
#define NSEG  8
#define SEG   821     // ceil(6561/8)
#define NFSEG 8
#define FSEG  256     // 2048/8
#define FCHK  128
#define CHK   256
#define HW    81
#define EPSV  1e-5f

// ---- device-global scratch (zero-initialized at module load; no runtime allocs) ----
__device__ __align__(16) float g_emb[HW * 16];
__device__ int   g_agent;
__device__ __align__(16) float g_x[S * Dm];
__device__ __align__(16) float g_q[NH * S * PH];
__device__ __align__(16) float g_k[NH * S * PH];
__device__ __align__(16) float g_v[NH * S * PH];
__device__ __align__(16) float g_pacc[NH * NSEG * S * HD];
__device__ float g_psum[NH * NSEG * S];
__device__ __align__(16) float g_o[S * Dm];
__device__ __align__(16) float g_yp[NFSEG * S * Dm];

// ---------------------------------------------------------------------------
// Kernel 1: conv1 -> relu -> conv2 -> relu -> cell_emb[81][16]; argmax(obs[0])
// ---------------------------------------------------------------------------
__global__ void conv_prep(const float* __restrict__ obs,
                          const float* __restrict__ w1, const float* __restrict__ b1,
                          const float* __restrict__ w2, const float* __restrict__ b2) {
    __shared__ float so[2 * 81];
    __shared__ float c1[16 * 81];
    int tid = threadIdx.x;
    for (int i = tid; i < 162; i += blockDim.x) so[i] = obs[i];
    __syncthreads();
    if (tid == 0) {
        float mx = so[0]; int mi = 0;
        for (int i = 1; i < 81; i++) if (so[i] > mx) { mx = so[i]; mi = i; }
        g_agent = mi;
    }
    // conv1: 2 -> 16, 3x3 SAME, cross-correlation
    for (int idx = tid; idx < 16 * 81; idx += blockDim.x) {
        int ch = idx / 81, pos = idx % 81, r = pos / 9, c = pos % 9;
        float acc = b1[ch];
        for (int ci = 0; ci < 2; ci++)
            for (int dr = 0; dr < 3; dr++) {
                int rr = r + dr - 1; if (rr < 0 || rr >= 9) continue;
                for (int dc = 0; dc < 3; dc++) {
                    int cc = c + dc - 1; if (cc < 0 || cc >= 9) continue;
                    acc += so[ci * 81 + rr * 9 + cc] * w1[((ch * 2 + ci) * 3 + dr) * 3 + dc];
                }
            }
        c1[idx] = fmaxf(acc, 0.f);
    }
    __syncthreads();
    // conv2: 16 -> 16; write emb[pos][ch]
    for (int idx = tid; idx < 16 * 81; idx += blockDim.x) {
        int ch = idx / 81, pos = idx % 81, r = pos / 9, c = pos % 9;
        float acc = b2[ch];
        for (int ci = 0; ci < 16; ci++)
            for (int dr = 0; dr < 3; dr++) {
                int rr = r + dr - 1; if (rr < 0 || rr >= 9) continue;
                for (int dc = 0; dc < 3; dc++) {
                    int cc = c + dc - 1; if (cc < 0 || cc >= 9) continue;
                    acc += c1[ci * 81 + rr * 9 + cc] * w2[((ch * 16 + ci) * 3 + dr) * 3 + dc];
                }
            }
        g_emb[pos * 16 + ch] = fmaxf(acc, 0.f);
    }
}

// ---------------------------------------------------------------------------
// Kernel 2: tokens[t=i*81+j] = [emb_i(16), emb_j(16), dx, dy]
// ---------------------------------------------------------------------------
__global__ void build_tokens() {
    int t = blockIdx.x * blockDim.x + threadIdx.x;
    if (t >= S) return;
    int i = t / HW, j = t % HW;
    float* xr = g_x + t * Dm;
#pragma unroll
    for (int d = 0; d < 16; d++) xr[d] = g_emb[i * 16 + d];
#pragma unroll
    for (int d = 0; d < 16; d++) xr[16 + d] = g_emb[j * 16 + d];
    float ri = (float)(i / 9), ci = (float)(i % 9);
    float rj = (float)(j / 9), cj = (float)(j % 9);
    xr[32] = (ri - rj) * 0.25f;
    xr[33] = (ci - cj) * 0.25f;
}

// ---------------------------------------------------------------------------
// Kernel 3: QKV projection for one layer.  q pre-scaled by 1/sqrt(17).
// Each warp owns one output column cc (weights broadcast); lanes own rows.
// ---------------------------------------------------------------------------
__global__ void qkv_kernel(const float* __restrict__ ipw, const float* __restrict__ ipb) {
    __shared__ float xs[Dm * 32];       // transposed: xs[d*32 + r]
    __shared__ float ws[102 * Dm];
    __shared__ float bs[102];
    int tid = threadIdx.x;
    int row0 = blockIdx.x * 32;
    for (int i = tid; i < 102 * Dm; i += blockDim.x) ws[i] = ipw[i];
    for (int i = tid; i < 102; i += blockDim.x) bs[i] = ipb[i];
    for (int i = tid; i < Dm * 32; i += blockDim.x) {
        int d = i >> 5, r = i & 31;
        xs[i] = (row0 + r < S) ? g_x[(row0 + r) * Dm + d] : 0.f;
    }
    __syncthreads();
    const float scale = rsqrtf(17.f);
    int lane = tid & 31, w = tid >> 5;        // 8 warps
    int s = row0 + lane;
    for (int cc = w; cc < 102; cc += 8) {
        float acc = bs[cc];
        const float* wp = ws + cc * Dm;
#pragma unroll
        for (int d = 0; d < Dm; d++) acc = fmaf(xs[d * 32 + lane], wp[d], acc);
        if (s < S) {
            int kind = cc / Dm;
            int c2 = cc % Dm;
            int h = c2 / HD, dd = c2 % HD;
            int off = (h * S + s) * PH + dd;
            if (kind == 0)      g_q[off] = acc * scale;
            else if (kind == 1) g_k[off] = acc;
            else                g_v[off] = acc;
        }
    }
}

// ---------------------------------------------------------------------------
// Kernel 4: attention partial (no max subtraction; logits are tiny here).
// grid = (qtiles, heads, key-segments). One query per thread; whole warp walks
// the same key -> broadcast float4 smem loads.
// ---------------------------------------------------------------------------
__global__ void __launch_bounds__(128) attn_kernel() {
    __shared__ float4 Ks[CHK * 5];
    __shared__ float4 Vs[CHK * 5];
    int tid = threadIdx.x;
    int tq = blockIdx.x * 128 + tid;
    int h = blockIdx.y;
    int seg = blockIdx.z;
    int k0 = seg * SEG;
    int k1 = min(S, k0 + SEG);
    bool act = tq < S;

    float q[HD];
    if (act) {
        const float* qp = g_q + (h * S + tq) * PH;
#pragma unroll
        for (int d = 0; d < HD; d++) q[d] = qp[d];
    } else {
#pragma unroll
        for (int d = 0; d < HD; d++) q[d] = 0.f;
    }
    float acc[HD];
#pragma unroll
    for (int d = 0; d < HD; d++) acc[d] = 0.f;
    float ssum = 0.f;

    for (int kb = k0; kb < k1; kb += CHK) {
        int n = min(CHK, k1 - kb);
        const float4* ksrc = (const float4*)(g_k + (h * S + kb) * PH);
        const float4* vsrc = (const float4*)(g_v + (h * S + kb) * PH);
        for (int i = tid; i < n * 5; i += 128) { Ks[i] = ksrc[i]; Vs[i] = vsrc[i]; }
        __syncthreads();
        if (act) {
            const float* kf = (const float*)Ks;
            const float* vf = (const float*)Vs;
#pragma unroll 2
            for (int kk = 0; kk < n; kk++) {
                const float4* kp = Ks + kk * 5;
                float4 a = kp[0], b = kp[1], c = kp[2], d4 = kp[3];
                float e16 = kf[kk * 20 + 16];
                float p0 = fmaf(q[3], a.w,  fmaf(q[2], a.z,  fmaf(q[1], a.y,  q[0] * a.x)));
                float p1 = fmaf(q[7], b.w,  fmaf(q[6], b.z,  fmaf(q[5], b.y,  q[4] * b.x)));
                float p2 = fmaf(q[11], c.w, fmaf(q[10], c.z, fmaf(q[9], c.y,  q[8] * c.x)));
                float p3 = fmaf(q[15], d4.w, fmaf(q[14], d4.z, fmaf(q[13], d4.y, q[12] * d4.x)));
                float dot = (p0 + p1) + (p2 + p3) + q[16] * e16;
                float p = __expf(dot);
                ssum += p;
                const float4* vp = Vs + kk * 5;
                float4 va = vp[0], vb = vp[1], vc = vp[2], vd = vp[3];
                float ve = vf[kk * 20 + 16];
                acc[0]  = fmaf(p, va.x, acc[0]);  acc[1]  = fmaf(p, va.y, acc[1]);
                acc[2]  = fmaf(p, va.z, acc[2]);  acc[3]  = fmaf(p, va.w, acc[3]);
                acc[4]  = fmaf(p, vb.x, acc[4]);  acc[5]  = fmaf(p, vb.y, acc[5]);
                acc[6]  = fmaf(p, vb.z, acc[6]);  acc[7]  = fmaf(p, vb.w, acc[7]);
                acc[8]  = fmaf(p, vc.x, acc[8]);  acc[9]  = fmaf(p, vc.y, acc[9]);
                acc[10] = fmaf(p, vc.z, acc[10]); acc[11] = fmaf(p, vc.w, acc[11]);
                acc[12] = fmaf(p, vd.x, acc[12]); acc[13] = fmaf(p, vd.y, acc[13]);
                acc[14] = fmaf(p, vd.z, acc[14]); acc[15] = fmaf(p, vd.w, acc[15]);
                acc[16] = fmaf(p, ve,  acc[16]);
            }
        }
        __syncthreads();
    }
    if (act) {
        float* pa = g_pacc + ((h * NSEG + seg) * S + tq) * HD;
#pragma unroll
        for (int d = 0; d < HD; d++) pa[d] = acc[d];
        g_psum[(h * NSEG + seg) * S + tq] = ssum;
    }
}

// ---------------------------------------------------------------------------
// Kernel 5: combine attention segments -> o[s][34]
// ---------------------------------------------------------------------------
__global__ void attn_reduce() {
    int e = blockIdx.x * blockDim.x + threadIdx.x;
    if (e >= S * Dm) return;
    int s = e / Dm, c = e % Dm;
    int h = c / HD, d = c % HD;
    float a = 0.f, sm = 0.f;
#pragma unroll
    for (int g = 0; g < NSEG; g++) {
        a  += g_pacc[((h * NSEG + g) * S + s) * HD + d];
        sm += g_psum[(h * NSEG + g) * S + s];
    }
    g_o[s * Dm + c] = a / sm;
}

// ---------------------------------------------------------------------------
// Kernel 6: out_proj + residual + LayerNorm1 (in-place on g_x)
// ---------------------------------------------------------------------------
__global__ void __launch_bounds__(128) proj_ln(const float* __restrict__ opw,
                                               const float* __restrict__ opb,
                                               const float* __restrict__ gg,
                                               const float* __restrict__ bb) {
    __shared__ float ws[Dm * Dm];
    __shared__ float bs[Dm], gs[Dm], bts[Dm];
    int tid = threadIdx.x;
    for (int i = tid; i < Dm * Dm; i += blockDim.x) ws[i] = opw[i];
    if (tid < Dm) { bs[tid] = opb[tid]; gs[tid] = gg[tid]; bts[tid] = bb[tid]; }
    __syncthreads();
    int s = blockIdx.x * 128 + tid;
    if (s >= S) return;
    float orow[Dm], y[Dm];
#pragma unroll
    for (int d = 0; d < Dm; d++) orow[d] = g_o[s * Dm + d];
#pragma unroll 2
    for (int d = 0; d < Dm; d++) {
        float a = bs[d] + g_x[s * Dm + d];
        const float* wp = ws + d * Dm;
#pragma unroll
        for (int k = 0; k < Dm; k++) a = fmaf(orow[k], wp[k], a);
        y[d] = a;
    }
    float m = 0.f;
#pragma unroll
    for (int d = 0; d < Dm; d++) m += y[d];
    m *= (1.0f / Dm);
    float v = 0.f;
#pragma unroll
    for (int d = 0; d < Dm; d++) { float t = y[d] - m; v = fmaf(t, t, v); }
    v *= (1.0f / Dm);
    float inv = rsqrtf(v + EPSV);
#pragma unroll
    for (int d = 0; d < Dm; d++) g_x[s * Dm + d] = (y[d] - m) * inv * gs[d] + bts[d];
}

// ---------------------------------------------------------------------------
// Kernel 7: FFN partial: y_seg = relu(x@W1_seg^T + b1_seg) @ W2_seg^T
// grid.z = FF segment; one row per thread; weights staged in smem (broadcast)
// ---------------------------------------------------------------------------
__global__ void __launch_bounds__(128) ffn_kernel(const float* __restrict__ l1w,
                                                  const float* __restrict__ l1b,
                                                  const float* __restrict__ l2w) {
    __shared__ __align__(16) float W1s[FCHK * 36];
    __shared__ __align__(16) float W2s[FCHK * 36];
    __shared__ float b1s[FCHK];
    int tid = threadIdx.x;
    int s = blockIdx.x * 128 + tid;
    int fbase = blockIdx.z * FSEG;
    bool act = s < S;
    float xr[Dm], y[Dm];
    if (act) {
#pragma unroll
        for (int d = 0; d < Dm; d++) xr[d] = g_x[s * Dm + d];
    } else {
#pragma unroll
        for (int d = 0; d < Dm; d++) xr[d] = 0.f;
    }
#pragma unroll
    for (int d = 0; d < Dm; d++) y[d] = 0.f;

    for (int fc = fbase; fc < fbase + FSEG; fc += FCHK) {
        for (int e2 = tid; e2 < FCHK * Dm; e2 += 128) {
            int f = e2 / Dm, d = e2 % Dm;
            W1s[f * 36 + d] = l1w[(fc + f) * Dm + d];
        }
        for (int e2 = tid; e2 < Dm * FCHK; e2 += 128) {
            int d = e2 / FCHK, f = e2 % FCHK;
            W2s[f * 36 + d] = l2w[d * FFd + fc + f];
        }
        for (int e2 = tid; e2 < FCHK; e2 += 128) b1s[e2] = l1b[fc + e2];
        __syncthreads();
        if (act) {
#pragma unroll 2
            for (int f = 0; f < FCHK; f++) {
                const float4* wp = (const float4*)(W1s + f * 36);
                float p0 = 0.f, p1 = 0.f, p2 = 0.f, p3 = 0.f;
#pragma unroll
                for (int g = 0; g < 8; g++) {
                    float4 w = wp[g];
                    p0 = fmaf(xr[4 * g + 0], w.x, p0);
                    p1 = fmaf(xr[4 * g + 1], w.y, p1);
                    p2 = fmaf(xr[4 * g + 2], w.z, p2);
                    p3 = fmaf(xr[4 * g + 3], w.w, p3);
                }
                float hsum = (p0 + p1) + (p2 + p3)
                           + xr[32] * W1s[f * 36 + 32] + xr[33] * W1s[f * 36 + 33] + b1s[f];
                float hrelu = fmaxf(hsum, 0.f);
                const float4* vp = (const float4*)(W2s + f * 36);
#pragma unroll
                for (int g = 0; g < 8; g++) {
                    float4 w = vp[g];
                    y[4 * g + 0] = fmaf(hrelu, w.x, y[4 * g + 0]);
                    y[4 * g + 1] = fmaf(hrelu, w.y, y[4 * g + 1]);
                    y[4 * g + 2] = fmaf(hrelu, w.z, y[4 * g + 2]);
                    y[4 * g + 3] = fmaf(hrelu, w.w, y[4 * g + 3]);
                }
                y[32] = fmaf(hrelu, W2s[f * 36 + 32], y[32]);
                y[33] = fmaf(hrelu, W2s[f * 36 + 33], y[33]);
            }
        }
        __syncthreads();
    }
    if (act) {
        float* yo = g_yp + ((size_t)blockIdx.z * S + s) * Dm;
#pragma unroll
        for (int d = 0; d < Dm; d++) yo[d] = y[d];
    }
}

// ---------------------------------------------------------------------------
// Kernel 8: FFN reduce + b2 + residual + LayerNorm2 (in-place on g_x)
// ---------------------------------------------------------------------------
__global__ void __launch_bounds__(128) ffn_reduce(const float* __restrict__ l2b,
                                                  const float* __restrict__ gg,
                                                  const float* __restrict__ bb) {
    __shared__ float bs[Dm], gs[Dm], bts[Dm];
    int tid = threadIdx.x;
    if (tid < Dm) { bs[tid] = l2b[tid]; gs[tid] = gg[tid]; bts[tid] = bb[tid]; }
    __syncthreads();
    int s = blockIdx.x * 128 + tid;
    if (s >= S) return;
    float y[Dm];
#pragma unroll
    for (int d = 0; d < Dm; d++) y[d] = g_x[s * Dm + d] + bs[d];
#pragma unroll
    for (int g = 0; g < NFSEG; g++) {
        const float* yp = g_yp + ((size_t)g * S + s) * Dm;
#pragma unroll
        for (int d = 0; d < Dm; d++) y[d] += yp[d];
    }
    float m = 0.f;
#pragma unroll
    for (int d = 0; d < Dm; d++) m += y[d];
    m *= (1.0f / Dm);
    float v = 0.f;
#pragma unroll
    for (int d = 0; d < Dm; d++) { float t = y[d] - m; v = fmaf(t, t, v); }
    v *= (1.0f / Dm);
    float inv = rsqrtf(v + EPSV);
#pragma unroll
    for (int d = 0; d < Dm; d++) g_x[s * Dm + d] = (y[d] - m) * inv * gs[d] + bts[d];
}

// ---------------------------------------------------------------------------
// Kernel 9: mean of 81 agent tokens -> out[34]
// ---------------------------------------------------------------------------
__global__ void final_out(float* __restrict__ out) {
    int d = threadIdx.x;
    if (d >= Dm) return;
    int start = g_agent * HW;
    float sum = 0.f;
    for (int r = 0; r < HW; r++) sum += g_x[(start + r) * Dm + d];
    out[d] = sum * (1.0f / 81.0f);
}

// ---------------------------------------------------------------------------
extern "C" void kernel_launch(void* const* d_in, const int* in_sizes, int n_in,
                              void* d_out, int out_size) {
    const float* obs = (const float*)d_in[0];
    const float* c1w = (const float*)d_in[1];
    const float* c1b = (const float*)d_in[2];
    const float* c2w = (const float*)d_in[3];
    const float* c2b = (const float*)d_in[4];
    const float* ipw = (const float*)d_in[5];
    const float* ipb = (const float*)d_in[6];
    const float* opw = (const float*)d_in[7];
    const float* opb = (const float*)d_in[8];
    const float* l1w = (const float*)d_in[9];
    const float* l1b = (const float*)d_in[10];
    const float* l2w = (const float*)d_in[11];
    const float* l2b = (const float*)d_in[12];
    const float* g1  = (const float*)d_in[13];
    const float* b1  = (const float*)d_in[14];
    const float* g2  = (const float*)d_in[15];
    const float* b2  = (const float*)d_in[16];
    float* out = (float*)d_out;

    conv_prep<<<1, 128>>>(obs, c1w, c1b, c2w, c2b);
    build_tokens<<<(S + 127) / 128, 128>>>();
    for (int l = 0; l < 2; l++) {
        qkv_kernel<<<(S + 31) / 32, 256>>>(ipw + l * 102 * Dm, ipb + l * 102);
        attn_kernel<<<dim3((S + 127) / 128, NH, NSEG), 128>>>();
        attn_reduce<<<(S * Dm + 255) / 256, 256>>>();
        proj_ln<<<(S + 127) / 128, 128>>>(opw + l * Dm * Dm, opb + l * Dm,
                                          g1 + l * Dm, b1 + l * Dm);
        ffn_kernel<<<dim3((S + 127) / 128, 1, NFSEG), 128>>>(
            l1w + l * FFd * Dm, l1b + l * FFd, l2w + l * Dm * FFd);
        ffn_reduce<<<(S + 127) / 128, 128>>>(l2b + l * Dm, g2 + l * Dm, b2 + l * Dm);
    }
    final_out<<<1, 64>>>(out);
}

// round 2
// speedup vs baseline: 1.1782x; 1.1782x over previous
#include <cuda_runtime.h>
#include <cuda_bf16.h>

#define S     6561
#define Dm    34
#define HD    17
#define PH    20      // padded head-dim stride (floats), 80B
#define PAC   18      // pacc row stride (floats), 72B = 9 u64
#define FFd   2048
#define NH    2
#define NSEG  16
#define SEG   411     // 16*411 = 6576 >= 6561
#define NFSEG 8
#define FSEG  256
#define FCHK  128
#define CHK   256
#define HW    81
#define EPSV  1e-5f

typedef unsigned long long u64;

// ---- packed fp32 helpers (FFMA2 path, PTX-only) ----
__device__ __forceinline__ u64 fma2(u64 a, u64 b, u64 c) {
    u64 d; asm("fma.rn.f32x2 %0, %1, %2, %3;" : "=l"(d) : "l"(a), "l"(b), "l"(c)); return d;
}
__device__ __forceinline__ u64 mul2(u64 a, u64 b) {
    u64 d; asm("mul.rn.f32x2 %0, %1, %2;" : "=l"(d) : "l"(a), "l"(b)); return d;
}
__device__ __forceinline__ u64 add2(u64 a, u64 b) {
    u64 d; asm("add.rn.f32x2 %0, %1, %2;" : "=l"(d) : "l"(a), "l"(b)); return d;
}
__device__ __forceinline__ float2 unpk(u64 v) {
    float2 f; asm("mov.b64 {%0, %1}, %2;" : "=f"(f.x), "=f"(f.y) : "l"(v)); return f;
}
__device__ __forceinline__ u64 pk(float x, float y) {
    u64 v; asm("mov.b64 %0, {%1, %2};" : "=l"(v) : "f"(x), "f"(y)); return v;
}

// ---- device-global scratch ----
__device__ __align__(16) float g_emb[HW * 16];
__device__ int   g_agent;
__device__ __align__(16) float g_x[S * Dm];
__device__ __align__(16) float g_q[NH * S * PH];
__device__ __align__(16) float g_k[NH * S * PH];
__device__ __align__(16) float g_v[NH * S * PH];
__device__ __align__(16) float g_pacc[NH * NSEG * S * PAC];
__device__ float g_psum[NH * NSEG * S];
__device__ __align__(16) float g_o[S * Dm];
__device__ __align__(16) float g_yp[NFSEG * S * Dm];

// ---------------------------------------------------------------------------
// Kernel 1: convs + argmax
// ---------------------------------------------------------------------------
__global__ void conv_prep(const float* __restrict__ obs,
                          const float* __restrict__ w1, const float* __restrict__ b1,
                          const float* __restrict__ w2, const float* __restrict__ b2) {
    __shared__ float so[2 * 81];
    __shared__ float c1[16 * 81];
    int tid = threadIdx.x;
    for (int i = tid; i < 162; i += blockDim.x) so[i] = obs[i];
    __syncthreads();
    if (tid == 0) {
        float mx = so[0]; int mi = 0;
        for (int i = 1; i < 81; i++) if (so[i] > mx) { mx = so[i]; mi = i; }
        g_agent = mi;
    }
    for (int idx = tid; idx < 16 * 81; idx += blockDim.x) {
        int ch = idx / 81, pos = idx % 81, r = pos / 9, c = pos % 9;
        float acc = b1[ch];
        for (int ci = 0; ci < 2; ci++)
            for (int dr = 0; dr < 3; dr++) {
                int rr = r + dr - 1; if (rr < 0 || rr >= 9) continue;
                for (int dc = 0; dc < 3; dc++) {
                    int cc = c + dc - 1; if (cc < 0 || cc >= 9) continue;
                    acc += so[ci * 81 + rr * 9 + cc] * w1[((ch * 2 + ci) * 3 + dr) * 3 + dc];
                }
            }
        c1[idx] = fmaxf(acc, 0.f);
    }
    __syncthreads();
    for (int idx = tid; idx < 16 * 81; idx += blockDim.x) {
        int ch = idx / 81, pos = idx % 81, r = pos / 9, c = pos % 9;
        float acc = b2[ch];
        for (int ci = 0; ci < 16; ci++)
            for (int dr = 0; dr < 3; dr++) {
                int rr = r + dr - 1; if (rr < 0 || rr >= 9) continue;
                for (int dc = 0; dc < 3; dc++) {
                    int cc = c + dc - 1; if (cc < 0 || cc >= 9) continue;
                    acc += c1[ci * 81 + rr * 9 + cc] * w2[((ch * 16 + ci) * 3 + dr) * 3 + dc];
                }
            }
        g_emb[pos * 16 + ch] = fmaxf(acc, 0.f);
    }
}

// ---------------------------------------------------------------------------
// Kernel 2: tokens
// ---------------------------------------------------------------------------
__global__ void build_tokens() {
    int t = blockIdx.x * blockDim.x + threadIdx.x;
    if (t >= S) return;
    int i = t / HW, j = t % HW;
    float* xr = g_x + t * Dm;
#pragma unroll
    for (int d = 0; d < 16; d++) xr[d] = g_emb[i * 16 + d];
#pragma unroll
    for (int d = 0; d < 16; d++) xr[16 + d] = g_emb[j * 16 + d];
    float ri = (float)(i / 9), ci = (float)(i % 9);
    float rj = (float)(j / 9), cj = (float)(j % 9);
    xr[32] = (ri - rj) * 0.25f;
    xr[33] = (ci - cj) * 0.25f;
}

// ---------------------------------------------------------------------------
// Kernel 3: QKV projection (q pre-scaled by 1/sqrt(17))
// ---------------------------------------------------------------------------
__global__ void qkv_kernel(const float* __restrict__ ipw, const float* __restrict__ ipb) {
    __shared__ float xs[Dm * 32];
    __shared__ float ws[102 * Dm];
    __shared__ float bs[102];
    int tid = threadIdx.x;
    int row0 = blockIdx.x * 32;
    for (int i = tid; i < 102 * Dm; i += blockDim.x) ws[i] = ipw[i];
    for (int i = tid; i < 102; i += blockDim.x) bs[i] = ipb[i];
    for (int i = tid; i < Dm * 32; i += blockDim.x) {
        int d = i >> 5, r = i & 31;
        xs[i] = (row0 + r < S) ? g_x[(row0 + r) * Dm + d] : 0.f;
    }
    __syncthreads();
    const float scale = rsqrtf(17.f);
    int lane = tid & 31, w = tid >> 5;
    int s = row0 + lane;
    for (int cc = w; cc < 102; cc += 8) {
        float acc = bs[cc];
        const float* wp = ws + cc * Dm;
#pragma unroll
        for (int d = 0; d < Dm; d++) acc = fmaf(xs[d * 32 + lane], wp[d], acc);
        if (s < S) {
            int kind = cc / Dm;
            int c2 = cc % Dm;
            int h = c2 / HD, dd = c2 % HD;
            int off = (h * S + s) * PH + dd;
            if (kind == 0)      g_q[off] = acc * scale;
            else if (kind == 1) g_k[off] = acc;
            else                g_v[off] = acc;
        }
    }
}

// ---------------------------------------------------------------------------
// Kernel 4: attention partial — 2 queries/thread, packed f32x2 math.
// Pads (dims 17..19 of PH rows) are zero, so pair (16,17) folds in exactly.
// ---------------------------------------------------------------------------
__global__ void __launch_bounds__(128) attn_kernel() {
    __shared__ __align__(16) float Ks[CHK * PH];
    __shared__ __align__(16) float Vs[CHK * PH];
    int tid = threadIdx.x;
    int h = blockIdx.y, seg = blockIdx.z;
    int base = blockIdx.x * 256;
    int tq0 = base + tid, tq1 = base + 128 + tid;
    bool a0 = tq0 < S, a1 = tq1 < S;

    u64 q0[9], q1[9], acc0[9], acc1[9];
#pragma unroll
    for (int i = 0; i < 9; i++) { q0[i] = 0ULL; q1[i] = 0ULL; acc0[i] = 0ULL; acc1[i] = 0ULL; }
    if (a0) {
        const u64* p = (const u64*)(g_q + (h * S + tq0) * PH);
#pragma unroll
        for (int i = 0; i < 9; i++) q0[i] = p[i];
    }
    if (a1) {
        const u64* p = (const u64*)(g_q + (h * S + tq1) * PH);
#pragma unroll
        for (int i = 0; i < 9; i++) q1[i] = p[i];
    }
    float s0 = 0.f, s1 = 0.f;
    int k0 = seg * SEG, k1 = min(S, k0 + SEG);

    for (int kb = k0; kb < k1; kb += CHK) {
        int n = min(CHK, k1 - kb);
        const float4* ksrc = (const float4*)(g_k + (h * S + kb) * PH);
        const float4* vsrc = (const float4*)(g_v + (h * S + kb) * PH);
        float4* kdst = (float4*)Ks; float4* vdst = (float4*)Vs;
        for (int i = tid; i < n * 5; i += 128) { kdst[i] = ksrc[i]; vdst[i] = vsrc[i]; }
        __syncthreads();
        const ulonglong2* K2 = (const ulonglong2*)Ks;
        const u64*        K1 = (const u64*)Ks;
        const ulonglong2* V2 = (const ulonglong2*)Vs;
        const u64*        V1 = (const u64*)Vs;
#pragma unroll 2
        for (int kk = 0; kk < n; kk++) {
            ulonglong2 ka = K2[kk * 5 + 0], kb2 = K2[kk * 5 + 1];
            ulonglong2 kc = K2[kk * 5 + 2], kd2 = K2[kk * 5 + 3];
            u64 ke = K1[kk * 10 + 8];
            u64 t0 = mul2(q0[0], ka.x),  t1 = mul2(q0[1], ka.y);
            u64 u0 = mul2(q1[0], ka.x),  u1 = mul2(q1[1], ka.y);
            t0 = fma2(q0[2], kb2.x, t0); t1 = fma2(q0[3], kb2.y, t1);
            u0 = fma2(q1[2], kb2.x, u0); u1 = fma2(q1[3], kb2.y, u1);
            t0 = fma2(q0[4], kc.x, t0);  t1 = fma2(q0[5], kc.y, t1);
            u0 = fma2(q1[4], kc.x, u0);  u1 = fma2(q1[5], kc.y, u1);
            t0 = fma2(q0[6], kd2.x, t0); t1 = fma2(q0[7], kd2.y, t1);
            u0 = fma2(q1[6], kd2.x, u0); u1 = fma2(q1[7], kd2.y, u1);
            t0 = fma2(q0[8], ke, t0);
            u0 = fma2(q1[8], ke, u0);
            t0 = add2(t0, t1);
            u0 = add2(u0, u1);
            float2 f0 = unpk(t0), f1 = unpk(u0);
            float p0 = __expf(f0.x + f0.y);
            float p1 = __expf(f1.x + f1.y);
            s0 += p0; s1 += p1;
            u64 pp0 = pk(p0, p0), pp1 = pk(p1, p1);
            ulonglong2 va = V2[kk * 5 + 0], vb = V2[kk * 5 + 1];
            ulonglong2 vc = V2[kk * 5 + 2], vd2 = V2[kk * 5 + 3];
            u64 ve = V1[kk * 10 + 8];
            acc0[0] = fma2(pp0, va.x, acc0[0]);  acc1[0] = fma2(pp1, va.x, acc1[0]);
            acc0[1] = fma2(pp0, va.y, acc0[1]);  acc1[1] = fma2(pp1, va.y, acc1[1]);
            acc0[2] = fma2(pp0, vb.x, acc0[2]);  acc1[2] = fma2(pp1, vb.x, acc1[2]);
            acc0[3] = fma2(pp0, vb.y, acc0[3]);  acc1[3] = fma2(pp1, vb.y, acc1[3]);
            acc0[4] = fma2(pp0, vc.x, acc0[4]);  acc1[4] = fma2(pp1, vc.x, acc1[4]);
            acc0[5] = fma2(pp0, vc.y, acc0[5]);  acc1[5] = fma2(pp1, vc.y, acc1[5]);
            acc0[6] = fma2(pp0, vd2.x, acc0[6]); acc1[6] = fma2(pp1, vd2.x, acc1[6]);
            acc0[7] = fma2(pp0, vd2.y, acc0[7]); acc1[7] = fma2(pp1, vd2.y, acc1[7]);
            acc0[8] = fma2(pp0, ve, acc0[8]);    acc1[8] = fma2(pp1, ve, acc1[8]);
        }
        __syncthreads();
    }
    if (a0) {
        u64* pa = (u64*)(g_pacc + ((h * NSEG + seg) * S + tq0) * PAC);
#pragma unroll
        for (int i = 0; i < 9; i++) pa[i] = acc0[i];
        g_psum[(h * NSEG + seg) * S + tq0] = s0;
    }
    if (a1) {
        u64* pa = (u64*)(g_pacc + ((h * NSEG + seg) * S + tq1) * PAC);
#pragma unroll
        for (int i = 0; i < 9; i++) pa[i] = acc1[i];
        g_psum[(h * NSEG + seg) * S + tq1] = s1;
    }
}

// ---------------------------------------------------------------------------
// Kernel 5: combine attention segments
// ---------------------------------------------------------------------------
__global__ void attn_reduce() {
    int e = blockIdx.x * blockDim.x + threadIdx.x;
    if (e >= S * Dm) return;
    int s = e / Dm, c = e % Dm;
    int h = c / HD, d = c % HD;
    float a = 0.f, sm = 0.f;
#pragma unroll
    for (int g = 0; g < NSEG; g++) {
        a  += g_pacc[((h * NSEG + g) * S + s) * PAC + d];
        sm += g_psum[(h * NSEG + g) * S + s];
    }
    g_o[s * Dm + c] = a / sm;
}

// ---------------------------------------------------------------------------
// Kernel 6: out_proj + residual + LN1
// ---------------------------------------------------------------------------
__global__ void __launch_bounds__(128) proj_ln(const float* __restrict__ opw,
                                               const float* __restrict__ opb,
                                               const float* __restrict__ gg,
                                               const float* __restrict__ bb) {
    __shared__ float ws[Dm * Dm];
    __shared__ float bs[Dm], gs[Dm], bts[Dm];
    int tid = threadIdx.x;
    for (int i = tid; i < Dm * Dm; i += blockDim.x) ws[i] = opw[i];
    if (tid < Dm) { bs[tid] = opb[tid]; gs[tid] = gg[tid]; bts[tid] = bb[tid]; }
    __syncthreads();
    int s = blockIdx.x * 128 + tid;
    if (s >= S) return;
    float orow[Dm], y[Dm];
#pragma unroll
    for (int d = 0; d < Dm; d++) orow[d] = g_o[s * Dm + d];
#pragma unroll 2
    for (int d = 0; d < Dm; d++) {
        float a = bs[d] + g_x[s * Dm + d];
        const float* wp = ws + d * Dm;
#pragma unroll
        for (int k = 0; k < Dm; k++) a = fmaf(orow[k], wp[k], a);
        y[d] = a;
    }
    float m = 0.f;
#pragma unroll
    for (int d = 0; d < Dm; d++) m += y[d];
    m *= (1.0f / Dm);
    float v = 0.f;
#pragma unroll
    for (int d = 0; d < Dm; d++) { float t = y[d] - m; v = fmaf(t, t, v); }
    v *= (1.0f / Dm);
    float inv = rsqrtf(v + EPSV);
#pragma unroll
    for (int d = 0; d < Dm; d++) g_x[s * Dm + d] = (y[d] - m) * inv * gs[d] + bts[d];
}

// ---------------------------------------------------------------------------
// Kernel 7: FFN partial with packed f32x2
// ---------------------------------------------------------------------------
__global__ void __launch_bounds__(128) ffn_kernel(const float* __restrict__ l1w,
                                                  const float* __restrict__ l1b,
                                                  const float* __restrict__ l2w) {
    __shared__ __align__(16) float W1s[FCHK * 36];
    __shared__ __align__(16) float W2s[FCHK * 36];
    __shared__ float b1s[FCHK];
    int tid = threadIdx.x;
    int s = blockIdx.x * 128 + tid;
    int fbase = blockIdx.z * FSEG;
    bool act = s < S;
    u64 xr[17], y[17];
#pragma unroll
    for (int i = 0; i < 17; i++) { xr[i] = 0ULL; y[i] = 0ULL; }
    if (act) {
        const u64* p = (const u64*)(g_x + s * Dm);
#pragma unroll
        for (int i = 0; i < 17; i++) xr[i] = p[i];
    }

    for (int fc = fbase; fc < fbase + FSEG; fc += FCHK) {
        for (int e2 = tid; e2 < FCHK * Dm; e2 += 128) {
            int f = e2 / Dm, d = e2 % Dm;
            W1s[f * 36 + d] = l1w[(fc + f) * Dm + d];
        }
        for (int e2 = tid; e2 < Dm * FCHK; e2 += 128) {
            int d = e2 / FCHK, f = e2 % FCHK;
            W2s[f * 36 + d] = l2w[d * FFd + fc + f];
        }
        for (int e2 = tid; e2 < FCHK; e2 += 128) b1s[e2] = l1b[fc + e2];
        __syncthreads();
        if (act) {
#pragma unroll 2
            for (int f = 0; f < FCHK; f++) {
                const ulonglong2* w2p = (const ulonglong2*)(W1s + f * 36);
                const u64*        w1p = (const u64*)(W1s + f * 36);
                ulonglong2 a0 = w2p[0], a1 = w2p[1], a2 = w2p[2], a3 = w2p[3];
                ulonglong2 a4 = w2p[4], a5 = w2p[5], a6 = w2p[6], a7 = w2p[7];
                u64 a16 = w1p[16];
                u64 t0 = mul2(xr[0], a0.x),  t1 = mul2(xr[1], a0.y);
                t0 = fma2(xr[2], a1.x, t0);  t1 = fma2(xr[3], a1.y, t1);
                t0 = fma2(xr[4], a2.x, t0);  t1 = fma2(xr[5], a2.y, t1);
                t0 = fma2(xr[6], a3.x, t0);  t1 = fma2(xr[7], a3.y, t1);
                t0 = fma2(xr[8], a4.x, t0);  t1 = fma2(xr[9], a4.y, t1);
                t0 = fma2(xr[10], a5.x, t0); t1 = fma2(xr[11], a5.y, t1);
                t0 = fma2(xr[12], a6.x, t0); t1 = fma2(xr[13], a6.y, t1);
                t0 = fma2(xr[14], a7.x, t0); t1 = fma2(xr[15], a7.y, t1);
                t0 = fma2(xr[16], a16, t0);
                t0 = add2(t0, t1);
                float2 fh = unpk(t0);
                float hsum = fh.x + fh.y + b1s[f];
                float hrelu = fmaxf(hsum, 0.f);
                u64 hp = pk(hrelu, hrelu);
                const ulonglong2* v2p = (const ulonglong2*)(W2s + f * 36);
                const u64*        v1p = (const u64*)(W2s + f * 36);
                ulonglong2 b0 = v2p[0], b1v = v2p[1], b2v = v2p[2], b3 = v2p[3];
                ulonglong2 b4 = v2p[4], b5 = v2p[5], b6 = v2p[6], b7 = v2p[7];
                u64 b16 = v1p[16];
                y[0]  = fma2(hp, b0.x, y[0]);   y[1]  = fma2(hp, b0.y, y[1]);
                y[2]  = fma2(hp, b1v.x, y[2]);  y[3]  = fma2(hp, b1v.y, y[3]);
                y[4]  = fma2(hp, b2v.x, y[4]);  y[5]  = fma2(hp, b2v.y, y[5]);
                y[6]  = fma2(hp, b3.x, y[6]);   y[7]  = fma2(hp, b3.y, y[7]);
                y[8]  = fma2(hp, b4.x, y[8]);   y[9]  = fma2(hp, b4.y, y[9]);
                y[10] = fma2(hp, b5.x, y[10]);  y[11] = fma2(hp, b5.y, y[11]);
                y[12] = fma2(hp, b6.x, y[12]);  y[13] = fma2(hp, b6.y, y[13]);
                y[14] = fma2(hp, b7.x, y[14]);  y[15] = fma2(hp, b7.y, y[15]);
                y[16] = fma2(hp, b16, y[16]);
            }
        }
        __syncthreads();
    }
    if (act) {
        u64* yo = (u64*)(g_yp + ((size_t)blockIdx.z * S + s) * Dm);
#pragma unroll
        for (int i = 0; i < 17; i++) yo[i] = y[i];
    }
}

// ---------------------------------------------------------------------------
// Kernel 8: FFN reduce + residual + LN2
// ---------------------------------------------------------------------------
__global__ void __launch_bounds__(128) ffn_reduce(const float* __restrict__ l2b,
                                                  const float* __restrict__ gg,
                                                  const float* __restrict__ bb) {
    __shared__ float bs[Dm], gs[Dm], bts[Dm];
    int tid = threadIdx.x;
    if (tid < Dm) { bs[tid] = l2b[tid]; gs[tid] = gg[tid]; bts[tid] = bb[tid]; }
    __syncthreads();
    int s = blockIdx.x * 128 + tid;
    if (s >= S) return;
    float y[Dm];
#pragma unroll
    for (int d = 0; d < Dm; d++) y[d] = g_x[s * Dm + d] + bs[d];
#pragma unroll
    for (int g = 0; g < NFSEG; g++) {
        const float* yp = g_yp + ((size_t)g * S + s) * Dm;
#pragma unroll
        for (int d = 0; d < Dm; d++) y[d] += yp[d];
    }
    float m = 0.f;
#pragma unroll
    for (int d = 0; d < Dm; d++) m += y[d];
    m *= (1.0f / Dm);
    float v = 0.f;
#pragma unroll
    for (int d = 0; d < Dm; d++) { float t = y[d] - m; v = fmaf(t, t, v); }
    v *= (1.0f / Dm);
    float inv = rsqrtf(v + EPSV);
#pragma unroll
    for (int d = 0; d < Dm; d++) g_x[s * Dm + d] = (y[d] - m) * inv * gs[d] + bts[d];
}

// ---------------------------------------------------------------------------
// Kernel 9: final mean
// ---------------------------------------------------------------------------
__global__ void final_out(float* __restrict__ out) {
    int d = threadIdx.x;
    if (d >= Dm) return;
    int start = g_agent * HW;
    float sum = 0.f;
    for (int r = 0; r < HW; r++) sum += g_x[(start + r) * Dm + d];
    out[d] = sum * (1.0f / 81.0f);
}

// ---------------------------------------------------------------------------
extern "C" void kernel_launch(void* const* d_in, const int* in_sizes, int n_in,
                              void* d_out, int out_size) {
    const float* obs = (const float*)d_in[0];
    const float* c1w = (const float*)d_in[1];
    const float* c1b = (const float*)d_in[2];
    const float* c2w = (const float*)d_in[3];
    const float* c2b = (const float*)d_in[4];
    const float* ipw = (const float*)d_in[5];
    const float* ipb = (const float*)d_in[6];
    const float* opw = (const float*)d_in[7];
    const float* opb = (const float*)d_in[8];
    const float* l1w = (const float*)d_in[9];
    const float* l1b = (const float*)d_in[10];
    const float* l2w = (const float*)d_in[11];
    const float* l2b = (const float*)d_in[12];
    const float* g1  = (const float*)d_in[13];
    const float* b1  = (const float*)d_in[14];
    const float* g2  = (const float*)d_in[15];
    const float* b2  = (const float*)d_in[16];
    float* out = (float*)d_out;

    conv_prep<<<1, 128>>>(obs, c1w, c1b, c2w, c2b);
    build_tokens<<<(S + 127) / 128, 128>>>();
    for (int l = 0; l < 2; l++) {
        qkv_kernel<<<(S + 31) / 32, 256>>>(ipw + l * 102 * Dm, ipb + l * 102);
        attn_kernel<<<dim3((S + 255) / 256, NH, NSEG), 128>>>();
        attn_reduce<<<(S * Dm + 255) / 256, 256>>>();
        proj_ln<<<(S + 127) / 128, 128>>>(opw + l * Dm * Dm, opb + l * Dm,
                                          g1 + l * Dm, b1 + l * Dm);
        ffn_kernel<<<dim3((S + 127) / 128, 1, NFSEG), 128>>>(
            l1w + l * FFd * Dm, l1b + l * FFd, l2w + l * Dm * FFd);
        ffn_reduce<<<(S + 127) / 128, 128>>>(l2b + l * Dm, g2 + l * Dm, b2 + l * Dm);
    }
    final_out<<<1, 64>>>(out);
}

// round 3
// speedup vs baseline: 1.3252x; 1.1248x over previous
#include <cuda_runtime.h>
#include <cuda_bf16.h>

#define S     6561
#define Dm    34
#define HD    17
#define PH    20      // padded head-dim stride (floats), 80B
#define PAC   18      // pacc row stride (floats), 72B = 9 u64
#define FFd   2048
#define NH    2
#define NSEG  11      // 26 qtiles * 2 heads * 11 = 572 blocks  (<= 592 = 4/SM * 148)
#define SEG   597     // 11*597 = 6567 >= 6561
#define NFSEG 8
#define FSEG  256
#define FCHK  128
#define CHK   256
#define HW    81
#define EPSV  1e-5f

typedef unsigned long long u64;

// ---- packed fp32 helpers (FFMA2 path, PTX-only) ----
__device__ __forceinline__ u64 fma2(u64 a, u64 b, u64 c) {
    u64 d; asm("fma.rn.f32x2 %0, %1, %2, %3;" : "=l"(d) : "l"(a), "l"(b), "l"(c)); return d;
}
__device__ __forceinline__ u64 mul2(u64 a, u64 b) {
    u64 d; asm("mul.rn.f32x2 %0, %1, %2;" : "=l"(d) : "l"(a), "l"(b)); return d;
}
__device__ __forceinline__ u64 add2(u64 a, u64 b) {
    u64 d; asm("add.rn.f32x2 %0, %1, %2;" : "=l"(d) : "l"(a), "l"(b)); return d;
}
__device__ __forceinline__ float2 unpk(u64 v) {
    float2 f; asm("mov.b64 {%0, %1}, %2;" : "=f"(f.x), "=f"(f.y) : "l"(v)); return f;
}
__device__ __forceinline__ u64 pk(float x, float y) {
    u64 v; asm("mov.b64 %0, {%1, %2};" : "=l"(v) : "f"(x), "f"(y)); return v;
}

// ---- device-global scratch ----
__device__ __align__(16) float g_emb[HW * 16];
__device__ int   g_agent;
__device__ __align__(16) float g_x[S * Dm];
__device__ __align__(16) float g_q[NH * S * PH];
__device__ __align__(16) float g_k[NH * S * PH];
__device__ __align__(16) float g_v[NH * S * PH];
__device__ __align__(16) float g_pacc[NH * NSEG * S * PAC];
__device__ float g_psum[NH * NSEG * S];
__device__ __align__(16) float g_o[S * Dm];
__device__ __align__(16) float g_yp[NFSEG * S * Dm];

// ---------------------------------------------------------------------------
// Kernel 1: convs + argmax
// ---------------------------------------------------------------------------
__global__ void conv_prep(const float* __restrict__ obs,
                          const float* __restrict__ w1, const float* __restrict__ b1,
                          const float* __restrict__ w2, const float* __restrict__ b2) {
    __shared__ float so[2 * 81];
    __shared__ float c1[16 * 81];
    int tid = threadIdx.x;
    for (int i = tid; i < 162; i += blockDim.x) so[i] = obs[i];
    __syncthreads();
    if (tid == 0) {
        float mx = so[0]; int mi = 0;
        for (int i = 1; i < 81; i++) if (so[i] > mx) { mx = so[i]; mi = i; }
        g_agent = mi;
    }
    for (int idx = tid; idx < 16 * 81; idx += blockDim.x) {
        int ch = idx / 81, pos = idx % 81, r = pos / 9, c = pos % 9;
        float acc = b1[ch];
        for (int ci = 0; ci < 2; ci++)
            for (int dr = 0; dr < 3; dr++) {
                int rr = r + dr - 1; if (rr < 0 || rr >= 9) continue;
                for (int dc = 0; dc < 3; dc++) {
                    int cc = c + dc - 1; if (cc < 0 || cc >= 9) continue;
                    acc += so[ci * 81 + rr * 9 + cc] * w1[((ch * 2 + ci) * 3 + dr) * 3 + dc];
                }
            }
        c1[idx] = fmaxf(acc, 0.f);
    }
    __syncthreads();
    for (int idx = tid; idx < 16 * 81; idx += blockDim.x) {
        int ch = idx / 81, pos = idx % 81, r = pos / 9, c = pos % 9;
        float acc = b2[ch];
        for (int ci = 0; ci < 16; ci++)
            for (int dr = 0; dr < 3; dr++) {
                int rr = r + dr - 1; if (rr < 0 || rr >= 9) continue;
                for (int dc = 0; dc < 3; dc++) {
                    int cc = c + dc - 1; if (cc < 0 || cc >= 9) continue;
                    acc += c1[ci * 81 + rr * 9 + cc] * w2[((ch * 16 + ci) * 3 + dr) * 3 + dc];
                }
            }
        g_emb[pos * 16 + ch] = fmaxf(acc, 0.f);
    }
}

// ---------------------------------------------------------------------------
// Kernel 2: tokens
// ---------------------------------------------------------------------------
__global__ void build_tokens() {
    int t = blockIdx.x * blockDim.x + threadIdx.x;
    if (t >= S) return;
    int i = t / HW, j = t % HW;
    float* xr = g_x + t * Dm;
#pragma unroll
    for (int d = 0; d < 16; d++) xr[d] = g_emb[i * 16 + d];
#pragma unroll
    for (int d = 0; d < 16; d++) xr[16 + d] = g_emb[j * 16 + d];
    float ri = (float)(i / 9), ci = (float)(i % 9);
    float rj = (float)(j / 9), cj = (float)(j % 9);
    xr[32] = (ri - rj) * 0.25f;
    xr[33] = (ci - cj) * 0.25f;
}

// ---------------------------------------------------------------------------
// Kernel 3: QKV projection (q pre-scaled by 1/sqrt(17))
// ---------------------------------------------------------------------------
__global__ void qkv_kernel(const float* __restrict__ ipw, const float* __restrict__ ipb) {
    __shared__ float xs[Dm * 32];
    __shared__ float ws[102 * Dm];
    __shared__ float bs[102];
    int tid = threadIdx.x;
    int row0 = blockIdx.x * 32;
    for (int i = tid; i < 102 * Dm; i += blockDim.x) ws[i] = ipw[i];
    for (int i = tid; i < 102; i += blockDim.x) bs[i] = ipb[i];
    for (int i = tid; i < Dm * 32; i += blockDim.x) {
        int d = i >> 5, r = i & 31;
        xs[i] = (row0 + r < S) ? g_x[(row0 + r) * Dm + d] : 0.f;
    }
    __syncthreads();
    const float scale = rsqrtf(17.f);
    int lane = tid & 31, w = tid >> 5;
    int s = row0 + lane;
    for (int cc = w; cc < 102; cc += 8) {
        float acc = bs[cc];
        const float* wp = ws + cc * Dm;
#pragma unroll
        for (int d = 0; d < Dm; d++) acc = fmaf(xs[d * 32 + lane], wp[d], acc);
        if (s < S) {
            int kind = cc / Dm;
            int c2 = cc % Dm;
            int h = c2 / HD, dd = c2 % HD;
            int off = (h * S + s) * PH + dd;
            if (kind == 0)      g_q[off] = acc * scale;
            else if (kind == 1) g_k[off] = acc;
            else                g_v[off] = acc;
        }
    }
}

// ---------------------------------------------------------------------------
// Kernel 4: attention partial — 2 queries/thread, packed f32x2 math,
// pointer-bump addressing. Single resident wave (572 blocks).
// ---------------------------------------------------------------------------
__global__ void __launch_bounds__(128) attn_kernel() {
    __shared__ __align__(16) float Ks[CHK * PH];
    __shared__ __align__(16) float Vs[CHK * PH];
    int tid = threadIdx.x;
    int h = blockIdx.y, seg = blockIdx.z;
    int base = blockIdx.x * 256;
    int tq0 = base + tid, tq1 = base + 128 + tid;
    bool a0 = tq0 < S, a1 = tq1 < S;

    u64 q0[9], q1[9], acc0[9], acc1[9];
#pragma unroll
    for (int i = 0; i < 9; i++) { q0[i] = 0ULL; q1[i] = 0ULL; acc0[i] = 0ULL; acc1[i] = 0ULL; }
    if (a0) {
        const u64* p = (const u64*)(g_q + (h * S + tq0) * PH);
#pragma unroll
        for (int i = 0; i < 9; i++) q0[i] = p[i];
    }
    if (a1) {
        const u64* p = (const u64*)(g_q + (h * S + tq1) * PH);
#pragma unroll
        for (int i = 0; i < 9; i++) q1[i] = p[i];
    }
    float s0 = 0.f, s1 = 0.f;
    int k0 = seg * SEG, k1 = min(S, k0 + SEG);

    for (int kb = k0; kb < k1; kb += CHK) {
        int n = min(CHK, k1 - kb);
        const float4* ksrc = (const float4*)(g_k + (h * S + kb) * PH);
        const float4* vsrc = (const float4*)(g_v + (h * S + kb) * PH);
        float4* kdst = (float4*)Ks; float4* vdst = (float4*)Vs;
        for (int i = tid; i < n * 5; i += 128) { kdst[i] = ksrc[i]; vdst[i] = vsrc[i]; }
        __syncthreads();
        const ulonglong2* K2 = (const ulonglong2*)Ks;
        const ulonglong2* V2 = (const ulonglong2*)Vs;
#pragma unroll 2
        for (int kk = 0; kk < n; kk++) {
            ulonglong2 ka = K2[0], kb2 = K2[1];
            ulonglong2 kc = K2[2], kd2 = K2[3];
            u64 ke = ((const ulonglong2*)K2)[4].x;
            u64 t0 = mul2(q0[0], ka.x),  t1 = mul2(q0[1], ka.y);
            u64 u0 = mul2(q1[0], ka.x),  u1 = mul2(q1[1], ka.y);
            t0 = fma2(q0[2], kb2.x, t0); t1 = fma2(q0[3], kb2.y, t1);
            u0 = fma2(q1[2], kb2.x, u0); u1 = fma2(q1[3], kb2.y, u1);
            t0 = fma2(q0[4], kc.x, t0);  t1 = fma2(q0[5], kc.y, t1);
            u0 = fma2(q1[4], kc.x, u0);  u1 = fma2(q1[5], kc.y, u1);
            t0 = fma2(q0[6], kd2.x, t0); t1 = fma2(q0[7], kd2.y, t1);
            u0 = fma2(q1[6], kd2.x, u0); u1 = fma2(q1[7], kd2.y, u1);
            t0 = fma2(q0[8], ke, t0);
            u0 = fma2(q1[8], ke, u0);
            t0 = add2(t0, t1);
            u0 = add2(u0, u1);
            float2 f0 = unpk(t0), f1 = unpk(u0);
            float p0 = __expf(f0.x + f0.y);
            float p1 = __expf(f1.x + f1.y);
            s0 += p0; s1 += p1;
            u64 pp0 = pk(p0, p0), pp1 = pk(p1, p1);
            ulonglong2 va = V2[0], vb = V2[1];
            ulonglong2 vc = V2[2], vd2 = V2[3];
            u64 ve = V2[4].x;
            acc0[0] = fma2(pp0, va.x, acc0[0]);  acc1[0] = fma2(pp1, va.x, acc1[0]);
            acc0[1] = fma2(pp0, va.y, acc0[1]);  acc1[1] = fma2(pp1, va.y, acc1[1]);
            acc0[2] = fma2(pp0, vb.x, acc0[2]);  acc1[2] = fma2(pp1, vb.x, acc1[2]);
            acc0[3] = fma2(pp0, vb.y, acc0[3]);  acc1[3] = fma2(pp1, vb.y, acc1[3]);
            acc0[4] = fma2(pp0, vc.x, acc0[4]);  acc1[4] = fma2(pp1, vc.x, acc1[4]);
            acc0[5] = fma2(pp0, vc.y, acc0[5]);  acc1[5] = fma2(pp1, vc.y, acc1[5]);
            acc0[6] = fma2(pp0, vd2.x, acc0[6]); acc1[6] = fma2(pp1, vd2.x, acc1[6]);
            acc0[7] = fma2(pp0, vd2.y, acc0[7]); acc1[7] = fma2(pp1, vd2.y, acc1[7]);
            acc0[8] = fma2(pp0, ve, acc0[8]);    acc1[8] = fma2(pp1, ve, acc1[8]);
            K2 += 5; V2 += 5;
        }
        __syncthreads();
    }
    if (a0) {
        u64* pa = (u64*)(g_pacc + ((h * NSEG + seg) * S + tq0) * PAC);
#pragma unroll
        for (int i = 0; i < 9; i++) pa[i] = acc0[i];
        g_psum[(h * NSEG + seg) * S + tq0] = s0;
    }
    if (a1) {
        u64* pa = (u64*)(g_pacc + ((h * NSEG + seg) * S + tq1) * PAC);
#pragma unroll
        for (int i = 0; i < 9; i++) pa[i] = acc1[i];
        g_psum[(h * NSEG + seg) * S + tq1] = s1;
    }
}

// ---------------------------------------------------------------------------
// Kernel 5: combine attention segments
// ---------------------------------------------------------------------------
__global__ void attn_reduce() {
    int e = blockIdx.x * blockDim.x + threadIdx.x;
    if (e >= S * Dm) return;
    int s = e / Dm, c = e % Dm;
    int h = c / HD, d = c % HD;
    float a = 0.f, sm = 0.f;
#pragma unroll
    for (int g = 0; g < NSEG; g++) {
        a  += g_pacc[((h * NSEG + g) * S + s) * PAC + d];
        sm += g_psum[(h * NSEG + g) * S + s];
    }
    g_o[s * Dm + c] = a / sm;
}

// ---------------------------------------------------------------------------
// Kernel 6: out_proj + residual + LN1
// ---------------------------------------------------------------------------
__global__ void __launch_bounds__(128) proj_ln(const float* __restrict__ opw,
                                               const float* __restrict__ opb,
                                               const float* __restrict__ gg,
                                               const float* __restrict__ bb) {
    __shared__ float ws[Dm * Dm];
    __shared__ float bs[Dm], gs[Dm], bts[Dm];
    int tid = threadIdx.x;
    for (int i = tid; i < Dm * Dm; i += blockDim.x) ws[i] = opw[i];
    if (tid < Dm) { bs[tid] = opb[tid]; gs[tid] = gg[tid]; bts[tid] = bb[tid]; }
    __syncthreads();
    int s = blockIdx.x * 128 + tid;
    if (s >= S) return;
    float orow[Dm], y[Dm];
#pragma unroll
    for (int d = 0; d < Dm; d++) orow[d] = g_o[s * Dm + d];
#pragma unroll 2
    for (int d = 0; d < Dm; d++) {
        float a = bs[d] + g_x[s * Dm + d];
        const float* wp = ws + d * Dm;
#pragma unroll
        for (int k = 0; k < Dm; k++) a = fmaf(orow[k], wp[k], a);
        y[d] = a;
    }
    float m = 0.f;
#pragma unroll
    for (int d = 0; d < Dm; d++) m += y[d];
    m *= (1.0f / Dm);
    float v = 0.f;
#pragma unroll
    for (int d = 0; d < Dm; d++) { float t = y[d] - m; v = fmaf(t, t, v); }
    v *= (1.0f / Dm);
    float inv = rsqrtf(v + EPSV);
#pragma unroll
    for (int d = 0; d < Dm; d++) g_x[s * Dm + d] = (y[d] - m) * inv * gs[d] + bts[d];
}

// ---------------------------------------------------------------------------
// Kernel 7: FFN partial with packed f32x2
// ---------------------------------------------------------------------------
__global__ void __launch_bounds__(128) ffn_kernel(const float* __restrict__ l1w,
                                                  const float* __restrict__ l1b,
                                                  const float* __restrict__ l2w) {
    __shared__ __align__(16) float W1s[FCHK * 36];
    __shared__ __align__(16) float W2s[FCHK * 36];
    __shared__ float b1s[FCHK];
    int tid = threadIdx.x;
    int s = blockIdx.x * 128 + tid;
    int fbase = blockIdx.z * FSEG;
    bool act = s < S;
    u64 xr[17], y[17];
#pragma unroll
    for (int i = 0; i < 17; i++) { xr[i] = 0ULL; y[i] = 0ULL; }
    if (act) {
        const u64* p = (const u64*)(g_x + s * Dm);
#pragma unroll
        for (int i = 0; i < 17; i++) xr[i] = p[i];
    }

    for (int fc = fbase; fc < fbase + FSEG; fc += FCHK) {
        for (int e2 = tid; e2 < FCHK * Dm; e2 += 128) {
            int f = e2 / Dm, d = e2 % Dm;
            W1s[f * 36 + d] = l1w[(fc + f) * Dm + d];
        }
        for (int e2 = tid; e2 < Dm * FCHK; e2 += 128) {
            int d = e2 / FCHK, f = e2 % FCHK;
            W2s[f * 36 + d] = l2w[d * FFd + fc + f];
        }
        for (int e2 = tid; e2 < FCHK; e2 += 128) b1s[e2] = l1b[fc + e2];
        __syncthreads();
        if (act) {
#pragma unroll 2
            for (int f = 0; f < FCHK; f++) {
                const ulonglong2* w2p = (const ulonglong2*)(W1s + f * 36);
                const u64*        w1p = (const u64*)(W1s + f * 36);
                ulonglong2 a0 = w2p[0], a1 = w2p[1], a2 = w2p[2], a3 = w2p[3];
                ulonglong2 a4 = w2p[4], a5 = w2p[5], a6 = w2p[6], a7 = w2p[7];
                u64 a16 = w1p[16];
                u64 t0 = mul2(xr[0], a0.x),  t1 = mul2(xr[1], a0.y);
                t0 = fma2(xr[2], a1.x, t0);  t1 = fma2(xr[3], a1.y, t1);
                t0 = fma2(xr[4], a2.x, t0);  t1 = fma2(xr[5], a2.y, t1);
                t0 = fma2(xr[6], a3.x, t0);  t1 = fma2(xr[7], a3.y, t1);
                t0 = fma2(xr[8], a4.x, t0);  t1 = fma2(xr[9], a4.y, t1);
                t0 = fma2(xr[10], a5.x, t0); t1 = fma2(xr[11], a5.y, t1);
                t0 = fma2(xr[12], a6.x, t0); t1 = fma2(xr[13], a6.y, t1);
                t0 = fma2(xr[14], a7.x, t0); t1 = fma2(xr[15], a7.y, t1);
                t0 = fma2(xr[16], a16, t0);
                t0 = add2(t0, t1);
                float2 fh = unpk(t0);
                float hsum = fh.x + fh.y + b1s[f];
                float hrelu = fmaxf(hsum, 0.f);
                u64 hp = pk(hrelu, hrelu);
                const ulonglong2* v2p = (const ulonglong2*)(W2s + f * 36);
                const u64*        v1p = (const u64*)(W2s + f * 36);
                ulonglong2 b0 = v2p[0], b1v = v2p[1], b2v = v2p[2], b3 = v2p[3];
                ulonglong2 b4 = v2p[4], b5 = v2p[5], b6 = v2p[6], b7 = v2p[7];
                u64 b16 = v1p[16];
                y[0]  = fma2(hp, b0.x, y[0]);   y[1]  = fma2(hp, b0.y, y[1]);
                y[2]  = fma2(hp, b1v.x, y[2]);  y[3]  = fma2(hp, b1v.y, y[3]);
                y[4]  = fma2(hp, b2v.x, y[4]);  y[5]  = fma2(hp, b2v.y, y[5]);
                y[6]  = fma2(hp, b3.x, y[6]);   y[7]  = fma2(hp, b3.y, y[7]);
                y[8]  = fma2(hp, b4.x, y[8]);   y[9]  = fma2(hp, b4.y, y[9]);
                y[10] = fma2(hp, b5.x, y[10]);  y[11] = fma2(hp, b5.y, y[11]);
                y[12] = fma2(hp, b6.x, y[12]);  y[13] = fma2(hp, b6.y, y[13]);
                y[14] = fma2(hp, b7.x, y[14]);  y[15] = fma2(hp, b7.y, y[15]);
                y[16] = fma2(hp, b16, y[16]);
            }
        }
        __syncthreads();
    }
    if (act) {
        u64* yo = (u64*)(g_yp + ((size_t)blockIdx.z * S + s) * Dm);
#pragma unroll
        for (int i = 0; i < 17; i++) yo[i] = y[i];
    }
}

// ---------------------------------------------------------------------------
// Kernel 8: FFN reduce + residual + LN2
// ---------------------------------------------------------------------------
__global__ void __launch_bounds__(128) ffn_reduce(const float* __restrict__ l2b,
                                                  const float* __restrict__ gg,
                                                  const float* __restrict__ bb) {
    __shared__ float bs[Dm], gs[Dm], bts[Dm];
    int tid = threadIdx.x;
    if (tid < Dm) { bs[tid] = l2b[tid]; gs[tid] = gg[tid]; bts[tid] = bb[tid]; }
    __syncthreads();
    int s = blockIdx.x * 128 + tid;
    if (s >= S) return;
    float y[Dm];
#pragma unroll
    for (int d = 0; d < Dm; d++) y[d] = g_x[s * Dm + d] + bs[d];
#pragma unroll
    for (int g = 0; g < NFSEG; g++) {
        const float* yp = g_yp + ((size_t)g * S + s) * Dm;
#pragma unroll
        for (int d = 0; d < Dm; d++) y[d] += yp[d];
    }
    float m = 0.f;
#pragma unroll
    for (int d = 0; d < Dm; d++) m += y[d];
    m *= (1.0f / Dm);
    float v = 0.f;
#pragma unroll
    for (int d = 0; d < Dm; d++) { float t = y[d] - m; v = fmaf(t, t, v); }
    v *= (1.0f / Dm);
    float inv = rsqrtf(v + EPSV);
#pragma unroll
    for (int d = 0; d < Dm; d++) g_x[s * Dm + d] = (y[d] - m) * inv * gs[d] + bts[d];
}

// ---------------------------------------------------------------------------
// Kernel 9: final mean
// ---------------------------------------------------------------------------
__global__ void final_out(float* __restrict__ out) {
    int d = threadIdx.x;
    if (d >= Dm) return;
    int start = g_agent * HW;
    float sum = 0.f;
    for (int r = 0; r < HW; r++) sum += g_x[(start + r) * Dm + d];
    out[d] = sum * (1.0f / 81.0f);
}

// ---------------------------------------------------------------------------
extern "C" void kernel_launch(void* const* d_in, const int* in_sizes, int n_in,
                              void* d_out, int out_size) {
    const float* obs = (const float*)d_in[0];
    const float* c1w = (const float*)d_in[1];
    const float* c1b = (const float*)d_in[2];
    const float* c2w = (const float*)d_in[3];
    const float* c2b = (const float*)d_in[4];
    const float* ipw = (const float*)d_in[5];
    const float* ipb = (const float*)d_in[6];
    const float* opw = (const float*)d_in[7];
    const float* opb = (const float*)d_in[8];
    const float* l1w = (const float*)d_in[9];
    const float* l1b = (const float*)d_in[10];
    const float* l2w = (const float*)d_in[11];
    const float* l2b = (const float*)d_in[12];
    const float* g1  = (const float*)d_in[13];
    const float* b1  = (const float*)d_in[14];
    const float* g2  = (const float*)d_in[15];
    const float* b2  = (const float*)d_in[16];
    float* out = (float*)d_out;

    conv_prep<<<1, 128>>>(obs, c1w, c1b, c2w, c2b);
    build_tokens<<<(S + 127) / 128, 128>>>();
    for (int l = 0; l < 2; l++) {
        qkv_kernel<<<(S + 31) / 32, 256>>>(ipw + l * 102 * Dm, ipb + l * 102);
        attn_kernel<<<dim3((S + 255) / 256, NH, NSEG), 128>>>();
        attn_reduce<<<(S * Dm + 255) / 256, 256>>>();
        proj_ln<<<(S + 127) / 128, 128>>>(opw + l * Dm * Dm, opb + l * Dm,
                                          g1 + l * Dm, b1 + l * Dm);
        ffn_kernel<<<dim3((S + 127) / 128, 1, NFSEG), 128>>>(
            l1w + l * FFd * Dm, l1b + l * FFd, l2w + l * Dm * FFd);
        ffn_reduce<<<(S + 127) / 128, 128>>>(l2b + l * Dm, g2 + l * Dm, b2 + l * Dm);
    }
    final_out<<<1, 64>>>(out);
}

// round 4
// speedup vs baseline: 1.7736x; 1.3383x over previous
#include <cuda_runtime.h>
#include <cuda_bf16.h>

#define S     6561
#define Dm    34
#define HD    17
#define PH    20
#define PAC   18
#define FFd   2048
#define NH    2
#define NSEG  11
#define SEG   597
#define NFSEG 8
#define FSEG  256
#define FCHK  128
#define CHK   256
#define HW    81
#define EPSV  1e-5f
#define ESTR  (NH * HW * HW)   // 13122, stride of one E matrix

typedef unsigned long long u64;

// ---- packed fp32 helpers ----
__device__ __forceinline__ u64 fma2(u64 a, u64 b, u64 c) {
    u64 d; asm("fma.rn.f32x2 %0, %1, %2, %3;" : "=l"(d) : "l"(a), "l"(b), "l"(c)); return d;
}
__device__ __forceinline__ u64 mul2(u64 a, u64 b) {
    u64 d; asm("mul.rn.f32x2 %0, %1, %2;" : "=l"(d) : "l"(a), "l"(b)); return d;
}
__device__ __forceinline__ u64 add2(u64 a, u64 b) {
    u64 d; asm("add.rn.f32x2 %0, %1, %2;" : "=l"(d) : "l"(a), "l"(b)); return d;
}
__device__ __forceinline__ float2 unpk(u64 v) {
    float2 f; asm("mov.b64 {%0, %1}, %2;" : "=f"(f.x), "=f"(f.y) : "l"(v)); return f;
}
__device__ __forceinline__ u64 pk(float x, float y) {
    u64 v; asm("mov.b64 %0, {%1, %2};" : "=l"(v) : "f"(x), "f"(y)); return v;
}

// ---- device-global scratch ----
__device__ __align__(16) float g_emb[HW * 16];
__device__ int   g_agent;
__device__ __align__(16) float g_x[S * Dm];
__device__ __align__(16) float g_q[NH * S * PH];
__device__ __align__(16) float g_k[NH * S * PH];
__device__ __align__(16) float g_v[NH * S * PH];
__device__ __align__(16) float g_pacc[NH * NSEG * S * PAC];
__device__ float g_psum[NH * NSEG * S];
__device__ __align__(16) float g_o[S * Dm];
__device__ __align__(16) float g_yp[NFSEG * S * Dm];
// layer-1 structured attention
__device__ __align__(16) float g_QA[NH * HW * HD];
__device__ __align__(16) float g_QB[NH * HW * HD];
__device__ __align__(16) float g_KA[NH * HW * HD];
__device__ __align__(16) float g_KB[NH * HW * HD];
__device__ __align__(16) float g_VA[NH * HW * HD];
__device__ __align__(16) float g_VB[NH * HW * HD];
__device__ __align__(16) float g_E[4 * ESTR];   // EA, EB, EC, ED

// ---------------------------------------------------------------------------
// Kernel 1: convs + argmax
// ---------------------------------------------------------------------------
__global__ void conv_prep(const float* __restrict__ obs,
                          const float* __restrict__ w1, const float* __restrict__ b1,
                          const float* __restrict__ w2, const float* __restrict__ b2) {
    __shared__ float so[2 * 81];
    __shared__ float c1[16 * 81];
    int tid = threadIdx.x;
    for (int i = tid; i < 162; i += blockDim.x) so[i] = obs[i];
    __syncthreads();
    if (tid == 0) {
        float mx = so[0]; int mi = 0;
        for (int i = 1; i < 81; i++) if (so[i] > mx) { mx = so[i]; mi = i; }
        g_agent = mi;
    }
    for (int idx = tid; idx < 16 * 81; idx += blockDim.x) {
        int ch = idx / 81, pos = idx % 81, r = pos / 9, c = pos % 9;
        float acc = b1[ch];
        for (int ci = 0; ci < 2; ci++)
            for (int dr = 0; dr < 3; dr++) {
                int rr = r + dr - 1; if (rr < 0 || rr >= 9) continue;
                for (int dc = 0; dc < 3; dc++) {
                    int cc = c + dc - 1; if (cc < 0 || cc >= 9) continue;
                    acc += so[ci * 81 + rr * 9 + cc] * w1[((ch * 2 + ci) * 3 + dr) * 3 + dc];
                }
            }
        c1[idx] = fmaxf(acc, 0.f);
    }
    __syncthreads();
    for (int idx = tid; idx < 16 * 81; idx += blockDim.x) {
        int ch = idx / 81, pos = idx % 81, r = pos / 9, c = pos % 9;
        float acc = b2[ch];
        for (int ci = 0; ci < 16; ci++)
            for (int dr = 0; dr < 3; dr++) {
                int rr = r + dr - 1; if (rr < 0 || rr >= 9) continue;
                for (int dc = 0; dc < 3; dc++) {
                    int cc = c + dc - 1; if (cc < 0 || cc >= 9) continue;
                    acc += c1[ci * 81 + rr * 9 + cc] * w2[((ch * 16 + ci) * 3 + dr) * 3 + dc];
                }
            }
        g_emb[pos * 16 + ch] = fmaxf(acc, 0.f);
    }
}

// ---------------------------------------------------------------------------
// Kernel 2: tokens (residual stream for layer 1)
// ---------------------------------------------------------------------------
__global__ void build_tokens() {
    int t = blockIdx.x * blockDim.x + threadIdx.x;
    if (t >= S) return;
    int i = t / HW, j = t % HW;
    float* xr = g_x + t * Dm;
#pragma unroll
    for (int d = 0; d < 16; d++) xr[d] = g_emb[i * 16 + d];
#pragma unroll
    for (int d = 0; d < 16; d++) xr[16 + d] = g_emb[j * 16 + d];
    float ri = (float)(i / 9), ci = (float)(i % 9);
    float rj = (float)(j / 9), cj = (float)(j % 9);
    xr[32] = (ri - rj) * 0.25f;
    xr[33] = (ci - cj) * 0.25f;
}

// ---------------------------------------------------------------------------
// L1-a: basis QKV. 162 basis vectors (xa_i, xb_j) x 102 outputs.
// Bias assigned to the xa (v<81) part only; q parts scaled by 1/sqrt(17).
// ---------------------------------------------------------------------------
__global__ void basis_qkv(const float* __restrict__ ipw, const float* __restrict__ ipb) {
    int idx = blockIdx.x * blockDim.x + threadIdx.x;
    if (idx >= 162 * 102) return;
    int v = idx / 102, c = idx % 102;
    const float* wr = ipw + c * Dm;
    float acc;
    if (v < 81) {
        int i = v;
        acc = ipb[c];
#pragma unroll
        for (int d = 0; d < 16; d++) acc = fmaf(g_emb[i * 16 + d], wr[d], acc);
        acc = fmaf((float)(i / 9) * 0.25f, wr[32], acc);
        acc = fmaf((float)(i % 9) * 0.25f, wr[33], acc);
    } else {
        int j = v - 81;
        acc = 0.f;
#pragma unroll
        for (int d = 0; d < 16; d++) acc = fmaf(g_emb[j * 16 + d], wr[16 + d], acc);
        acc = fmaf(-(float)(j / 9) * 0.25f, wr[32], acc);
        acc = fmaf(-(float)(j % 9) * 0.25f, wr[33], acc);
    }
    int kind = c / Dm;
    int cc = c % Dm;
    int h = cc / HD, dd = cc % HD;
    int off = (h * HW + (v % 81)) * HD + dd;
    if (kind == 0) {
        float sv = acc * rsqrtf(17.f);
        if (v < 81) g_QA[off] = sv; else g_QB[off] = sv;
    } else if (kind == 1) {
        if (v < 81) g_KA[off] = acc; else g_KB[off] = acc;
    } else {
        if (v < 81) g_VA[off] = acc; else g_VB[off] = acc;
    }
}

// ---------------------------------------------------------------------------
// L1-b: four 81x81 logit matrices per head, exponentiated.
// p=0: EA=exp(QA.KA^T)  p=1: EB=exp(QA.KB^T)  p=2: EC=exp(QB.KA^T)  p=3: ED=exp(QB.KB^T)
// ---------------------------------------------------------------------------
__global__ void logits_exp() {
    int idx = blockIdx.x * blockDim.x + threadIdx.x;
    if (idx >= 4 * ESTR) return;
    int p = idx / ESTR;
    int r = idx % ESTR;
    int h = r / (HW * HW);
    int q2 = r % (HW * HW);
    int i = q2 / HW, m = q2 % HW;
    const float* L = ((p < 2) ? g_QA : g_QB) + (h * HW + i) * HD;
    const float* R = ((p & 1) ? g_KB : g_KA) + (h * HW + m) * HD;
    float dot = 0.f;
#pragma unroll
    for (int d = 0; d < HD; d++) dot = fmaf(L[d], R[d], dot);
    g_E[idx] = __expf(dot);
}

// ---------------------------------------------------------------------------
// L1-c: structured attention output.
// O[t=(i,j),d] = (WA[d]*zn + WB[d]*zm) / (zm*zn)
//   zm = sum_m EA[i,m]EC[j,m],  WA[d] = sum_m EA[i,m]EC[j,m]va[m,d]
//   zn = sum_n EB[i,n]ED[j,n],  WB[d] = sum_n EB[i,n]ED[j,n]vb[n,d]
// grid (81 i, NH), thread j.
// ---------------------------------------------------------------------------
__global__ void __launch_bounds__(128) attn_struct() {
    __shared__ float sea[HW], seb[HW];
    __shared__ __align__(16) float sva[HW * 18];
    __shared__ __align__(16) float svb[HW * 18];
    int tid = threadIdx.x;
    int i = blockIdx.x, h = blockIdx.y;
    for (int t = tid; t < HW; t += 128) {
        sea[t] = g_E[0 * ESTR + (h * HW + i) * HW + t];
        seb[t] = g_E[1 * ESTR + (h * HW + i) * HW + t];
    }
    for (int t = tid; t < HW * 18; t += 128) {
        int m = t / 18, d = t % 18;
        sva[t] = (d < HD) ? g_VA[(h * HW + m) * HD + d] : 0.f;
        svb[t] = (d < HD) ? g_VB[(h * HW + m) * HD + d] : 0.f;
    }
    __syncthreads();
    int j = tid;
    if (j >= HW) return;
    const float* ecr = g_E + 2 * ESTR + (h * HW + j) * HW;
    const float* edr = g_E + 3 * ESTR + (h * HW + j) * HW;
    float zm = 0.f, zn = 0.f;
    u64 wa[9], wb[9];
#pragma unroll
    for (int k = 0; k < 9; k++) { wa[k] = 0ULL; wb[k] = 0ULL; }
    for (int m = 0; m < HW; m++) {
        float f = sea[m] * ecr[m];
        zm += f;
        u64 fp = pk(f, f);
        const u64* vr = (const u64*)(sva + m * 18);
#pragma unroll
        for (int k = 0; k < 9; k++) wa[k] = fma2(fp, vr[k], wa[k]);
    }
    for (int n = 0; n < HW; n++) {
        float g = seb[n] * edr[n];
        zn += g;
        u64 gp = pk(g, g);
        const u64* vr = (const u64*)(svb + n * 18);
#pragma unroll
        for (int k = 0; k < 9; k++) wb[k] = fma2(gp, vr[k], wb[k]);
    }
    float inv = 1.0f / (zm * zn);
    float* od = g_o + (i * HW + j) * Dm + h * HD;
#pragma unroll
    for (int k = 0; k < 9; k++) {
        float2 A = unpk(wa[k]), B = unpk(wb[k]);
        int d = 2 * k;
        od[d] = (A.x * zn + B.x * zm) * inv;
        if (d + 1 < HD) od[d + 1] = (A.y * zn + B.y * zm) * inv;
    }
}

// ---------------------------------------------------------------------------
// Layer-2 QKV projection (q pre-scaled by 1/sqrt(17))
// ---------------------------------------------------------------------------
__global__ void qkv_kernel(const float* __restrict__ ipw, const float* __restrict__ ipb) {
    __shared__ float xs[Dm * 32];
    __shared__ float ws[102 * Dm];
    __shared__ float bs[102];
    int tid = threadIdx.x;
    int row0 = blockIdx.x * 32;
    for (int i = tid; i < 102 * Dm; i += blockDim.x) ws[i] = ipw[i];
    for (int i = tid; i < 102; i += blockDim.x) bs[i] = ipb[i];
    for (int i = tid; i < Dm * 32; i += blockDim.x) {
        int d = i >> 5, r = i & 31;
        xs[i] = (row0 + r < S) ? g_x[(row0 + r) * Dm + d] : 0.f;
    }
    __syncthreads();
    const float scale = rsqrtf(17.f);
    int lane = tid & 31, w = tid >> 5;
    int s = row0 + lane;
    for (int cc = w; cc < 102; cc += 8) {
        float acc = bs[cc];
        const float* wp = ws + cc * Dm;
#pragma unroll
        for (int d = 0; d < Dm; d++) acc = fmaf(xs[d * 32 + lane], wp[d], acc);
        if (s < S) {
            int kind = cc / Dm;
            int c2 = cc % Dm;
            int h = c2 / HD, dd = c2 % HD;
            int off = (h * S + s) * PH + dd;
            if (kind == 0)      g_q[off] = acc * scale;
            else if (kind == 1) g_k[off] = acc;
            else                g_v[off] = acc;
        }
    }
}

// ---------------------------------------------------------------------------
// Layer-2 attention partial — 2 queries/thread, f32x2, single wave.
// ---------------------------------------------------------------------------
__global__ void __launch_bounds__(128) attn_kernel() {
    __shared__ __align__(16) float Ks[CHK * PH];
    __shared__ __align__(16) float Vs[CHK * PH];
    int tid = threadIdx.x;
    int h = blockIdx.y, seg = blockIdx.z;
    int base = blockIdx.x * 256;
    int tq0 = base + tid, tq1 = base + 128 + tid;
    bool a0 = tq0 < S, a1 = tq1 < S;

    u64 q0[9], q1[9], acc0[9], acc1[9];
#pragma unroll
    for (int i = 0; i < 9; i++) { q0[i] = 0ULL; q1[i] = 0ULL; acc0[i] = 0ULL; acc1[i] = 0ULL; }
    if (a0) {
        const u64* p = (const u64*)(g_q + (h * S + tq0) * PH);
#pragma unroll
        for (int i = 0; i < 9; i++) q0[i] = p[i];
    }
    if (a1) {
        const u64* p = (const u64*)(g_q + (h * S + tq1) * PH);
#pragma unroll
        for (int i = 0; i < 9; i++) q1[i] = p[i];
    }
    float s0 = 0.f, s1 = 0.f;
    int k0 = seg * SEG, k1 = min(S, k0 + SEG);

    for (int kb = k0; kb < k1; kb += CHK) {
        int n = min(CHK, k1 - kb);
        const float4* ksrc = (const float4*)(g_k + (h * S + kb) * PH);
        const float4* vsrc = (const float4*)(g_v + (h * S + kb) * PH);
        float4* kdst = (float4*)Ks; float4* vdst = (float4*)Vs;
        for (int i = tid; i < n * 5; i += 128) { kdst[i] = ksrc[i]; vdst[i] = vsrc[i]; }
        __syncthreads();
        const ulonglong2* K2 = (const ulonglong2*)Ks;
        const ulonglong2* V2 = (const ulonglong2*)Vs;
#pragma unroll 2
        for (int kk = 0; kk < n; kk++) {
            ulonglong2 ka = K2[0], kb2 = K2[1];
            ulonglong2 kc = K2[2], kd2 = K2[3];
            u64 ke = K2[4].x;
            u64 t0 = mul2(q0[0], ka.x),  t1 = mul2(q0[1], ka.y);
            u64 u0 = mul2(q1[0], ka.x),  u1 = mul2(q1[1], ka.y);
            t0 = fma2(q0[2], kb2.x, t0); t1 = fma2(q0[3], kb2.y, t1);
            u0 = fma2(q1[2], kb2.x, u0); u1 = fma2(q1[3], kb2.y, u1);
            t0 = fma2(q0[4], kc.x, t0);  t1 = fma2(q0[5], kc.y, t1);
            u0 = fma2(q1[4], kc.x, u0);  u1 = fma2(q1[5], kc.y, u1);
            t0 = fma2(q0[6], kd2.x, t0); t1 = fma2(q0[7], kd2.y, t1);
            u0 = fma2(q1[6], kd2.x, u0); u1 = fma2(q1[7], kd2.y, u1);
            t0 = fma2(q0[8], ke, t0);
            u0 = fma2(q1[8], ke, u0);
            t0 = add2(t0, t1);
            u0 = add2(u0, u1);
            float2 f0 = unpk(t0), f1 = unpk(u0);
            float p0 = __expf(f0.x + f0.y);
            float p1 = __expf(f1.x + f1.y);
            s0 += p0; s1 += p1;
            u64 pp0 = pk(p0, p0), pp1 = pk(p1, p1);
            ulonglong2 va = V2[0], vb = V2[1];
            ulonglong2 vc = V2[2], vd2 = V2[3];
            u64 ve = V2[4].x;
            acc0[0] = fma2(pp0, va.x, acc0[0]);  acc1[0] = fma2(pp1, va.x, acc1[0]);
            acc0[1] = fma2(pp0, va.y, acc0[1]);  acc1[1] = fma2(pp1, va.y, acc1[1]);
            acc0[2] = fma2(pp0, vb.x, acc0[2]);  acc1[2] = fma2(pp1, vb.x, acc1[2]);
            acc0[3] = fma2(pp0, vb.y, acc0[3]);  acc1[3] = fma2(pp1, vb.y, acc1[3]);
            acc0[4] = fma2(pp0, vc.x, acc0[4]);  acc1[4] = fma2(pp1, vc.x, acc1[4]);
            acc0[5] = fma2(pp0, vc.y, acc0[5]);  acc1[5] = fma2(pp1, vc.y, acc1[5]);
            acc0[6] = fma2(pp0, vd2.x, acc0[6]); acc1[6] = fma2(pp1, vd2.x, acc1[6]);
            acc0[7] = fma2(pp0, vd2.y, acc0[7]); acc1[7] = fma2(pp1, vd2.y, acc1[7]);
            acc0[8] = fma2(pp0, ve, acc0[8]);    acc1[8] = fma2(pp1, ve, acc1[8]);
            K2 += 5; V2 += 5;
        }
        __syncthreads();
    }
    if (a0) {
        u64* pa = (u64*)(g_pacc + ((h * NSEG + seg) * S + tq0) * PAC);
#pragma unroll
        for (int i = 0; i < 9; i++) pa[i] = acc0[i];
        g_psum[(h * NSEG + seg) * S + tq0] = s0;
    }
    if (a1) {
        u64* pa = (u64*)(g_pacc + ((h * NSEG + seg) * S + tq1) * PAC);
#pragma unroll
        for (int i = 0; i < 9; i++) pa[i] = acc1[i];
        g_psum[(h * NSEG + seg) * S + tq1] = s1;
    }
}

// ---------------------------------------------------------------------------
// Layer-2: combine attention segments
// ---------------------------------------------------------------------------
__global__ void attn_reduce() {
    int e = blockIdx.x * blockDim.x + threadIdx.x;
    if (e >= S * Dm) return;
    int s = e / Dm, c = e % Dm;
    int h = c / HD, d = c % HD;
    float a = 0.f, sm = 0.f;
#pragma unroll
    for (int g = 0; g < NSEG; g++) {
        a  += g_pacc[((h * NSEG + g) * S + s) * PAC + d];
        sm += g_psum[(h * NSEG + g) * S + s];
    }
    g_o[s * Dm + c] = a / sm;
}

// ---------------------------------------------------------------------------
// out_proj + residual + LN1
// ---------------------------------------------------------------------------
__global__ void __launch_bounds__(128) proj_ln(const float* __restrict__ opw,
                                               const float* __restrict__ opb,
                                               const float* __restrict__ gg,
                                               const float* __restrict__ bb) {
    __shared__ float ws[Dm * Dm];
    __shared__ float bs[Dm], gs[Dm], bts[Dm];
    int tid = threadIdx.x;
    for (int i = tid; i < Dm * Dm; i += blockDim.x) ws[i] = opw[i];
    if (tid < Dm) { bs[tid] = opb[tid]; gs[tid] = gg[tid]; bts[tid] = bb[tid]; }
    __syncthreads();
    int s = blockIdx.x * 128 + tid;
    if (s >= S) return;
    float orow[Dm], y[Dm];
#pragma unroll
    for (int d = 0; d < Dm; d++) orow[d] = g_o[s * Dm + d];
#pragma unroll 2
    for (int d = 0; d < Dm; d++) {
        float a = bs[d] + g_x[s * Dm + d];
        const float* wp = ws + d * Dm;
#pragma unroll
        for (int k = 0; k < Dm; k++) a = fmaf(orow[k], wp[k], a);
        y[d] = a;
    }
    float m = 0.f;
#pragma unroll
    for (int d = 0; d < Dm; d++) m += y[d];
    m *= (1.0f / Dm);
    float v = 0.f;
#pragma unroll
    for (int d = 0; d < Dm; d++) { float t = y[d] - m; v = fmaf(t, t, v); }
    v *= (1.0f / Dm);
    float inv = rsqrtf(v + EPSV);
#pragma unroll
    for (int d = 0; d < Dm; d++) g_x[s * Dm + d] = (y[d] - m) * inv * gs[d] + bts[d];
}

// ---------------------------------------------------------------------------
// FFN partial with packed f32x2
// ---------------------------------------------------------------------------
__global__ void __launch_bounds__(128) ffn_kernel(const float* __restrict__ l1w,
                                                  const float* __restrict__ l1b,
                                                  const float* __restrict__ l2w) {
    __shared__ __align__(16) float W1s[FCHK * 36];
    __shared__ __align__(16) float W2s[FCHK * 36];
    __shared__ float b1s[FCHK];
    int tid = threadIdx.x;
    int s = blockIdx.x * 128 + tid;
    int fbase = blockIdx.z * FSEG;
    bool act = s < S;
    u64 xr[17], y[17];
#pragma unroll
    for (int i = 0; i < 17; i++) { xr[i] = 0ULL; y[i] = 0ULL; }
    if (act) {
        const u64* p = (const u64*)(g_x + s * Dm);
#pragma unroll
        for (int i = 0; i < 17; i++) xr[i] = p[i];
    }

    for (int fc = fbase; fc < fbase + FSEG; fc += FCHK) {
        for (int e2 = tid; e2 < FCHK * Dm; e2 += 128) {
            int f = e2 / Dm, d = e2 % Dm;
            W1s[f * 36 + d] = l1w[(fc + f) * Dm + d];
        }
        for (int e2 = tid; e2 < Dm * FCHK; e2 += 128) {
            int d = e2 / FCHK, f = e2 % FCHK;
            W2s[f * 36 + d] = l2w[d * FFd + fc + f];
        }
        for (int e2 = tid; e2 < FCHK; e2 += 128) b1s[e2] = l1b[fc + e2];
        __syncthreads();
        if (act) {
#pragma unroll 2
            for (int f = 0; f < FCHK; f++) {
                const ulonglong2* w2p = (const ulonglong2*)(W1s + f * 36);
                const u64*        w1p = (const u64*)(W1s + f * 36);
                ulonglong2 a0 = w2p[0], a1 = w2p[1], a2 = w2p[2], a3 = w2p[3];
                ulonglong2 a4 = w2p[4], a5 = w2p[5], a6 = w2p[6], a7 = w2p[7];
                u64 a16 = w1p[16];
                u64 t0 = mul2(xr[0], a0.x),  t1 = mul2(xr[1], a0.y);
                t0 = fma2(xr[2], a1.x, t0);  t1 = fma2(xr[3], a1.y, t1);
                t0 = fma2(xr[4], a2.x, t0);  t1 = fma2(xr[5], a2.y, t1);
                t0 = fma2(xr[6], a3.x, t0);  t1 = fma2(xr[7], a3.y, t1);
                t0 = fma2(xr[8], a4.x, t0);  t1 = fma2(xr[9], a4.y, t1);
                t0 = fma2(xr[10], a5.x, t0); t1 = fma2(xr[11], a5.y, t1);
                t0 = fma2(xr[12], a6.x, t0); t1 = fma2(xr[13], a6.y, t1);
                t0 = fma2(xr[14], a7.x, t0); t1 = fma2(xr[15], a7.y, t1);
                t0 = fma2(xr[16], a16, t0);
                t0 = add2(t0, t1);
                float2 fh = unpk(t0);
                float hsum = fh.x + fh.y + b1s[f];
                float hrelu = fmaxf(hsum, 0.f);
                u64 hp = pk(hrelu, hrelu);
                const ulonglong2* v2p = (const ulonglong2*)(W2s + f * 36);
                const u64*        v1p = (const u64*)(W2s + f * 36);
                ulonglong2 b0 = v2p[0], b1v = v2p[1], b2v = v2p[2], b3 = v2p[3];
                ulonglong2 b4 = v2p[4], b5 = v2p[5], b6 = v2p[6], b7 = v2p[7];
                u64 b16 = v1p[16];
                y[0]  = fma2(hp, b0.x, y[0]);   y[1]  = fma2(hp, b0.y, y[1]);
                y[2]  = fma2(hp, b1v.x, y[2]);  y[3]  = fma2(hp, b1v.y, y[3]);
                y[4]  = fma2(hp, b2v.x, y[4]);  y[5]  = fma2(hp, b2v.y, y[5]);
                y[6]  = fma2(hp, b3.x, y[6]);   y[7]  = fma2(hp, b3.y, y[7]);
                y[8]  = fma2(hp, b4.x, y[8]);   y[9]  = fma2(hp, b4.y, y[9]);
                y[10] = fma2(hp, b5.x, y[10]);  y[11] = fma2(hp, b5.y, y[11]);
                y[12] = fma2(hp, b6.x, y[12]);  y[13] = fma2(hp, b6.y, y[13]);
                y[14] = fma2(hp, b7.x, y[14]);  y[15] = fma2(hp, b7.y, y[15]);
                y[16] = fma2(hp, b16, y[16]);
            }
        }
        __syncthreads();
    }
    if (act) {
        u64* yo = (u64*)(g_yp + ((size_t)blockIdx.z * S + s) * Dm);
#pragma unroll
        for (int i = 0; i < 17; i++) yo[i] = y[i];
    }
}

// ---------------------------------------------------------------------------
// FFN reduce + residual + LN2
// ---------------------------------------------------------------------------
__global__ void __launch_bounds__(128) ffn_reduce(const float* __restrict__ l2b,
                                                  const float* __restrict__ gg,
                                                  const float* __restrict__ bb) {
    __shared__ float bs[Dm], gs[Dm], bts[Dm];
    int tid = threadIdx.x;
    if (tid < Dm) { bs[tid] = l2b[tid]; gs[tid] = gg[tid]; bts[tid] = bb[tid]; }
    __syncthreads();
    int s = blockIdx.x * 128 + tid;
    if (s >= S) return;
    float y[Dm];
#pragma unroll
    for (int d = 0; d < Dm; d++) y[d] = g_x[s * Dm + d] + bs[d];
#pragma unroll
    for (int g = 0; g < NFSEG; g++) {
        const float* yp = g_yp + ((size_t)g * S + s) * Dm;
#pragma unroll
        for (int d = 0; d < Dm; d++) y[d] += yp[d];
    }
    float m = 0.f;
#pragma unroll
    for (int d = 0; d < Dm; d++) m += y[d];
    m *= (1.0f / Dm);
    float v = 0.f;
#pragma unroll
    for (int d = 0; d < Dm; d++) { float t = y[d] - m; v = fmaf(t, t, v); }
    v *= (1.0f / Dm);
    float inv = rsqrtf(v + EPSV);
#pragma unroll
    for (int d = 0; d < Dm; d++) g_x[s * Dm + d] = (y[d] - m) * inv * gs[d] + bts[d];
}

// ---------------------------------------------------------------------------
// final mean
// ---------------------------------------------------------------------------
__global__ void final_out(float* __restrict__ out) {
    int d = threadIdx.x;
    if (d >= Dm) return;
    int start = g_agent * HW;
    float sum = 0.f;
    for (int r = 0; r < HW; r++) sum += g_x[(start + r) * Dm + d];
    out[d] = sum * (1.0f / 81.0f);
}

// ---------------------------------------------------------------------------
extern "C" void kernel_launch(void* const* d_in, const int* in_sizes, int n_in,
                              void* d_out, int out_size) {
    const float* obs = (const float*)d_in[0];
    const float* c1w = (const float*)d_in[1];
    const float* c1b = (const float*)d_in[2];
    const float* c2w = (const float*)d_in[3];
    const float* c2b = (const float*)d_in[4];
    const float* ipw = (const float*)d_in[5];
    const float* ipb = (const float*)d_in[6];
    const float* opw = (const float*)d_in[7];
    const float* opb = (const float*)d_in[8];
    const float* l1w = (const float*)d_in[9];
    const float* l1b = (const float*)d_in[10];
    const float* l2w = (const float*)d_in[11];
    const float* l2b = (const float*)d_in[12];
    const float* g1  = (const float*)d_in[13];
    const float* b1  = (const float*)d_in[14];
    const float* g2  = (const float*)d_in[15];
    const float* b2  = (const float*)d_in[16];
    float* out = (float*)d_out;

    conv_prep<<<1, 128>>>(obs, c1w, c1b, c2w, c2b);
    build_tokens<<<(S + 127) / 128, 128>>>();

    // ---- layer 0: structured attention (tokens are separable) ----
    basis_qkv<<<(162 * 102 + 127) / 128, 128>>>(ipw, ipb);
    logits_exp<<<(4 * ESTR + 127) / 128, 128>>>();
    attn_struct<<<dim3(HW, NH), 128>>>();
    proj_ln<<<(S + 127) / 128, 128>>>(opw, opb, g1, b1);
    ffn_kernel<<<dim3((S + 127) / 128, 1, NFSEG), 128>>>(l1w, l1b, l2w);
    ffn_reduce<<<(S + 127) / 128, 128>>>(l2b, g2, b2);

    // ---- layer 1: general path ----
    qkv_kernel<<<(S + 31) / 32, 256>>>(ipw + 102 * Dm, ipb + 102);
    attn_kernel<<<dim3((S + 255) / 256, NH, NSEG), 128>>>();
    attn_reduce<<<(S * Dm + 255) / 256, 256>>>();
    proj_ln<<<(S + 127) / 128, 128>>>(opw + Dm * Dm, opb + Dm,
                                      g1 + Dm, b1 + Dm);
    ffn_kernel<<<dim3((S + 127) / 128, 1, NFSEG), 128>>>(
        l1w + FFd * Dm, l1b + FFd, l2w + Dm * FFd);
    ffn_reduce<<<(S + 127) / 128, 128>>>(l2b + Dm, g2 + Dm, b2 + Dm);

    final_out<<<1, 64>>>(out);
}

// round 5
// speedup vs baseline: 2.8857x; 1.6270x over previous
#include <cuda_runtime.h>
#include <cuda_bf16.h>

#define S      6561
#define Dm     34
#define HD     17
#define PH     20
#define PAC    18
#define FFd    2048
#define NH     2
#define NFSEG  8
#define FSEG   256
#define FCHK   128
#define HW     81
#define EPSV   1e-5f
#define ESTR   (NH * HW * HW)
// agent-attention key split
#define NSEG2  127
#define KSEG2  52
// agent FFN split
#define NFSEG2 32
#define FSEG2  64

typedef unsigned long long u64;

// ---- packed fp32 helpers ----
__device__ __forceinline__ u64 fma2(u64 a, u64 b, u64 c) {
    u64 d; asm("fma.rn.f32x2 %0, %1, %2, %3;" : "=l"(d) : "l"(a), "l"(b), "l"(c)); return d;
}
__device__ __forceinline__ u64 mul2(u64 a, u64 b) {
    u64 d; asm("mul.rn.f32x2 %0, %1, %2;" : "=l"(d) : "l"(a), "l"(b)); return d;
}
__device__ __forceinline__ u64 add2(u64 a, u64 b) {
    u64 d; asm("add.rn.f32x2 %0, %1, %2;" : "=l"(d) : "l"(a), "l"(b)); return d;
}
__device__ __forceinline__ float2 unpk(u64 v) {
    float2 f; asm("mov.b64 {%0, %1}, %2;" : "=f"(f.x), "=f"(f.y) : "l"(v)); return f;
}
__device__ __forceinline__ u64 pk(float x, float y) {
    u64 v; asm("mov.b64 %0, {%1, %2};" : "=l"(v) : "f"(x), "f"(y)); return v;
}

// ---- device-global scratch ----
__device__ __align__(16) float g_emb[HW * 16];
__device__ int   g_agent;
__device__ __align__(16) float g_x[S * Dm];
__device__ __align__(16) float g_q[NH * S * PH];
__device__ __align__(16) float g_k[NH * S * PH];
__device__ __align__(16) float g_v[NH * S * PH];
__device__ __align__(16) float g_o[S * Dm];
__device__ __align__(16) float g_yp[NFSEG * S * Dm];
// layer-0 structured attention
__device__ __align__(16) float g_QA[NH * HW * HD];
__device__ __align__(16) float g_QB[NH * HW * HD];
__device__ __align__(16) float g_KA[NH * HW * HD];
__device__ __align__(16) float g_KB[NH * HW * HD];
__device__ __align__(16) float g_VA[NH * HW * HD];
__device__ __align__(16) float g_VB[NH * HW * HD];
__device__ __align__(16) float g_E[4 * ESTR];
// layer-1 agent-only path
__device__ __align__(16) float g_pacca[NH * NSEG2 * HW * PAC];
__device__ float g_psuma[NH * NSEG2 * HW];
__device__ __align__(16) float g_oa[HW * Dm];
__device__ __align__(16) float g_xa[HW * Dm];
__device__ __align__(16) float g_ypa[NFSEG2 * HW * Dm];

// ---------------------------------------------------------------------------
// convs + argmax
// ---------------------------------------------------------------------------
__global__ void conv_prep(const float* __restrict__ obs,
                          const float* __restrict__ w1, const float* __restrict__ b1,
                          const float* __restrict__ w2, const float* __restrict__ b2) {
    __shared__ float so[2 * 81];
    __shared__ float c1[16 * 81];
    int tid = threadIdx.x;
    for (int i = tid; i < 162; i += blockDim.x) so[i] = obs[i];
    __syncthreads();
    if (tid == 0) {
        float mx = so[0]; int mi = 0;
        for (int i = 1; i < 81; i++) if (so[i] > mx) { mx = so[i]; mi = i; }
        g_agent = mi;
    }
    for (int idx = tid; idx < 16 * 81; idx += blockDim.x) {
        int ch = idx / 81, pos = idx % 81, r = pos / 9, c = pos % 9;
        float acc = b1[ch];
        for (int ci = 0; ci < 2; ci++)
            for (int dr = 0; dr < 3; dr++) {
                int rr = r + dr - 1; if (rr < 0 || rr >= 9) continue;
                for (int dc = 0; dc < 3; dc++) {
                    int cc = c + dc - 1; if (cc < 0 || cc >= 9) continue;
                    acc += so[ci * 81 + rr * 9 + cc] * w1[((ch * 2 + ci) * 3 + dr) * 3 + dc];
                }
            }
        c1[idx] = fmaxf(acc, 0.f);
    }
    __syncthreads();
    for (int idx = tid; idx < 16 * 81; idx += blockDim.x) {
        int ch = idx / 81, pos = idx % 81, r = pos / 9, c = pos % 9;
        float acc = b2[ch];
        for (int ci = 0; ci < 16; ci++)
            for (int dr = 0; dr < 3; dr++) {
                int rr = r + dr - 1; if (rr < 0 || rr >= 9) continue;
                for (int dc = 0; dc < 3; dc++) {
                    int cc = c + dc - 1; if (cc < 0 || cc >= 9) continue;
                    acc += c1[ci * 81 + rr * 9 + cc] * w2[((ch * 16 + ci) * 3 + dr) * 3 + dc];
                }
            }
        g_emb[pos * 16 + ch] = fmaxf(acc, 0.f);
    }
}

// ---------------------------------------------------------------------------
// tokens
// ---------------------------------------------------------------------------
__global__ void build_tokens() {
    int t = blockIdx.x * blockDim.x + threadIdx.x;
    if (t >= S) return;
    int i = t / HW, j = t % HW;
    float* xr = g_x + t * Dm;
#pragma unroll
    for (int d = 0; d < 16; d++) xr[d] = g_emb[i * 16 + d];
#pragma unroll
    for (int d = 0; d < 16; d++) xr[16 + d] = g_emb[j * 16 + d];
    float ri = (float)(i / 9), ci = (float)(i % 9);
    float rj = (float)(j / 9), cj = (float)(j % 9);
    xr[32] = (ri - rj) * 0.25f;
    xr[33] = (ci - cj) * 0.25f;
}

// ---------------------------------------------------------------------------
// L0-a: basis QKV
// ---------------------------------------------------------------------------
__global__ void basis_qkv(const float* __restrict__ ipw, const float* __restrict__ ipb) {
    int idx = blockIdx.x * blockDim.x + threadIdx.x;
    if (idx >= 162 * 102) return;
    int v = idx / 102, c = idx % 102;
    const float* wr = ipw + c * Dm;
    float acc;
    if (v < 81) {
        int i = v;
        acc = ipb[c];
#pragma unroll
        for (int d = 0; d < 16; d++) acc = fmaf(g_emb[i * 16 + d], wr[d], acc);
        acc = fmaf((float)(i / 9) * 0.25f, wr[32], acc);
        acc = fmaf((float)(i % 9) * 0.25f, wr[33], acc);
    } else {
        int j = v - 81;
        acc = 0.f;
#pragma unroll
        for (int d = 0; d < 16; d++) acc = fmaf(g_emb[j * 16 + d], wr[16 + d], acc);
        acc = fmaf(-(float)(j / 9) * 0.25f, wr[32], acc);
        acc = fmaf(-(float)(j % 9) * 0.25f, wr[33], acc);
    }
    int kind = c / Dm;
    int cc = c % Dm;
    int h = cc / HD, dd = cc % HD;
    int off = (h * HW + (v % 81)) * HD + dd;
    if (kind == 0) {
        float sv = acc * rsqrtf(17.f);
        if (v < 81) g_QA[off] = sv; else g_QB[off] = sv;
    } else if (kind == 1) {
        if (v < 81) g_KA[off] = acc; else g_KB[off] = acc;
    } else {
        if (v < 81) g_VA[off] = acc; else g_VB[off] = acc;
    }
}

// ---------------------------------------------------------------------------
// L0-b: four 81x81 exp(logit) matrices per head
// ---------------------------------------------------------------------------
__global__ void logits_exp() {
    int idx = blockIdx.x * blockDim.x + threadIdx.x;
    if (idx >= 4 * ESTR) return;
    int p = idx / ESTR;
    int r = idx % ESTR;
    int h = r / (HW * HW);
    int q2 = r % (HW * HW);
    int i = q2 / HW, m = q2 % HW;
    const float* L = ((p < 2) ? g_QA : g_QB) + (h * HW + i) * HD;
    const float* R = ((p & 1) ? g_KB : g_KA) + (h * HW + m) * HD;
    float dot = 0.f;
#pragma unroll
    for (int d = 0; d < HD; d++) dot = fmaf(L[d], R[d], dot);
    g_E[idx] = __expf(dot);
}

// ---------------------------------------------------------------------------
// L0-c: structured attention output
// ---------------------------------------------------------------------------
__global__ void __launch_bounds__(128) attn_struct() {
    __shared__ float sea[HW], seb[HW];
    __shared__ __align__(16) float sva[HW * 18];
    __shared__ __align__(16) float svb[HW * 18];
    int tid = threadIdx.x;
    int i = blockIdx.x, h = blockIdx.y;
    for (int t = tid; t < HW; t += 128) {
        sea[t] = g_E[0 * ESTR + (h * HW + i) * HW + t];
        seb[t] = g_E[1 * ESTR + (h * HW + i) * HW + t];
    }
    for (int t = tid; t < HW * 18; t += 128) {
        int m = t / 18, d = t % 18;
        sva[t] = (d < HD) ? g_VA[(h * HW + m) * HD + d] : 0.f;
        svb[t] = (d < HD) ? g_VB[(h * HW + m) * HD + d] : 0.f;
    }
    __syncthreads();
    int j = tid;
    if (j >= HW) return;
    const float* ecr = g_E + 2 * ESTR + (h * HW + j) * HW;
    const float* edr = g_E + 3 * ESTR + (h * HW + j) * HW;
    float zm = 0.f, zn = 0.f;
    u64 wa[9], wb[9];
#pragma unroll
    for (int k = 0; k < 9; k++) { wa[k] = 0ULL; wb[k] = 0ULL; }
    for (int m = 0; m < HW; m++) {
        float f = sea[m] * ecr[m];
        zm += f;
        u64 fp = pk(f, f);
        const u64* vr = (const u64*)(sva + m * 18);
#pragma unroll
        for (int k = 0; k < 9; k++) wa[k] = fma2(fp, vr[k], wa[k]);
    }
    for (int n = 0; n < HW; n++) {
        float g = seb[n] * edr[n];
        zn += g;
        u64 gp = pk(g, g);
        const u64* vr = (const u64*)(svb + n * 18);
#pragma unroll
        for (int k = 0; k < 9; k++) wb[k] = fma2(gp, vr[k], wb[k]);
    }
    float inv = 1.0f / (zm * zn);
    float* od = g_o + (i * HW + j) * Dm + h * HD;
#pragma unroll
    for (int k = 0; k < 9; k++) {
        float2 A = unpk(wa[k]), B = unpk(wb[k]);
        int d = 2 * k;
        od[d] = (A.x * zn + B.x * zm) * inv;
        if (d + 1 < HD) od[d + 1] = (A.y * zn + B.y * zm) * inv;
    }
}

// ---------------------------------------------------------------------------
// out_proj + residual + LN (full S rows)
// ---------------------------------------------------------------------------
__global__ void __launch_bounds__(128) proj_ln(const float* __restrict__ opw,
                                               const float* __restrict__ opb,
                                               const float* __restrict__ gg,
                                               const float* __restrict__ bb) {
    __shared__ float ws[Dm * Dm];
    __shared__ float bs[Dm], gs[Dm], bts[Dm];
    int tid = threadIdx.x;
    for (int i = tid; i < Dm * Dm; i += blockDim.x) ws[i] = opw[i];
    if (tid < Dm) { bs[tid] = opb[tid]; gs[tid] = gg[tid]; bts[tid] = bb[tid]; }
    __syncthreads();
    int s = blockIdx.x * 128 + tid;
    if (s >= S) return;
    float orow[Dm], y[Dm];
#pragma unroll
    for (int d = 0; d < Dm; d++) orow[d] = g_o[s * Dm + d];
#pragma unroll 2
    for (int d = 0; d < Dm; d++) {
        float a = bs[d] + g_x[s * Dm + d];
        const float* wp = ws + d * Dm;
#pragma unroll
        for (int k = 0; k < Dm; k++) a = fmaf(orow[k], wp[k], a);
        y[d] = a;
    }
    float m = 0.f;
#pragma unroll
    for (int d = 0; d < Dm; d++) m += y[d];
    m *= (1.0f / Dm);
    float v = 0.f;
#pragma unroll
    for (int d = 0; d < Dm; d++) { float t = y[d] - m; v = fmaf(t, t, v); }
    v *= (1.0f / Dm);
    float inv = rsqrtf(v + EPSV);
#pragma unroll
    for (int d = 0; d < Dm; d++) g_x[s * Dm + d] = (y[d] - m) * inv * gs[d] + bts[d];
}

// ---------------------------------------------------------------------------
// Full-S FFN partial: 2 tokens per thread (weights amortized)
// ---------------------------------------------------------------------------
__global__ void __launch_bounds__(128) ffn_kernel(const float* __restrict__ l1w,
                                                  const float* __restrict__ l1b,
                                                  const float* __restrict__ l2w) {
    __shared__ __align__(16) float W1s[FCHK * 36];
    __shared__ __align__(16) float W2s[FCHK * 36];
    __shared__ float b1s[FCHK];
    int tid = threadIdx.x;
    int s0 = blockIdx.x * 256 + tid;
    int s1 = s0 + 128;
    int fbase = blockIdx.z * FSEG;
    bool a0 = s0 < S, a1 = s1 < S;
    u64 x0[17], x1[17], y0[17], y1[17];
#pragma unroll
    for (int i = 0; i < 17; i++) { x0[i] = 0ULL; x1[i] = 0ULL; y0[i] = 0ULL; y1[i] = 0ULL; }
    if (a0) {
        const u64* p = (const u64*)(g_x + s0 * Dm);
#pragma unroll
        for (int i = 0; i < 17; i++) x0[i] = p[i];
    }
    if (a1) {
        const u64* p = (const u64*)(g_x + s1 * Dm);
#pragma unroll
        for (int i = 0; i < 17; i++) x1[i] = p[i];
    }

    for (int fc = fbase; fc < fbase + FSEG; fc += FCHK) {
        for (int e2 = tid; e2 < FCHK * Dm; e2 += 128) {
            int f = e2 / Dm, d = e2 % Dm;
            W1s[f * 36 + d] = l1w[(fc + f) * Dm + d];
        }
        for (int e2 = tid; e2 < Dm * FCHK; e2 += 128) {
            int d = e2 / FCHK, f = e2 % FCHK;
            W2s[f * 36 + d] = l2w[d * FFd + fc + f];
        }
        for (int e2 = tid; e2 < FCHK; e2 += 128) b1s[e2] = l1b[fc + e2];
        __syncthreads();
#pragma unroll 2
        for (int f = 0; f < FCHK; f++) {
            const ulonglong2* w2p = (const ulonglong2*)(W1s + f * 36);
            const u64*        w1p = (const u64*)(W1s + f * 36);
            ulonglong2 a0v = w2p[0], a1v = w2p[1], a2v = w2p[2], a3v = w2p[3];
            ulonglong2 a4v = w2p[4], a5v = w2p[5], a6v = w2p[6], a7v = w2p[7];
            u64 a16 = w1p[16];
            u64 t0 = mul2(x0[0], a0v.x),  t1 = mul2(x0[1], a0v.y);
            u64 u0 = mul2(x1[0], a0v.x),  u1 = mul2(x1[1], a0v.y);
            t0 = fma2(x0[2], a1v.x, t0);  t1 = fma2(x0[3], a1v.y, t1);
            u0 = fma2(x1[2], a1v.x, u0);  u1 = fma2(x1[3], a1v.y, u1);
            t0 = fma2(x0[4], a2v.x, t0);  t1 = fma2(x0[5], a2v.y, t1);
            u0 = fma2(x1[4], a2v.x, u0);  u1 = fma2(x1[5], a2v.y, u1);
            t0 = fma2(x0[6], a3v.x, t0);  t1 = fma2(x0[7], a3v.y, t1);
            u0 = fma2(x1[6], a3v.x, u0);  u1 = fma2(x1[7], a3v.y, u1);
            t0 = fma2(x0[8], a4v.x, t0);  t1 = fma2(x0[9], a4v.y, t1);
            u0 = fma2(x1[8], a4v.x, u0);  u1 = fma2(x1[9], a4v.y, u1);
            t0 = fma2(x0[10], a5v.x, t0); t1 = fma2(x0[11], a5v.y, t1);
            u0 = fma2(x1[10], a5v.x, u0); u1 = fma2(x1[11], a5v.y, u1);
            t0 = fma2(x0[12], a6v.x, t0); t1 = fma2(x0[13], a6v.y, t1);
            u0 = fma2(x1[12], a6v.x, u0); u1 = fma2(x1[13], a6v.y, u1);
            t0 = fma2(x0[14], a7v.x, t0); t1 = fma2(x0[15], a7v.y, t1);
            u0 = fma2(x1[14], a7v.x, u0); u1 = fma2(x1[15], a7v.y, u1);
            t0 = fma2(x0[16], a16, t0);
            u0 = fma2(x1[16], a16, u0);
            t0 = add2(t0, t1);
            u0 = add2(u0, u1);
            float2 fh0 = unpk(t0), fh1 = unpk(u0);
            float h0 = fmaxf(fh0.x + fh0.y + b1s[f], 0.f);
            float h1 = fmaxf(fh1.x + fh1.y + b1s[f], 0.f);
            u64 hp0 = pk(h0, h0), hp1 = pk(h1, h1);
            const ulonglong2* v2p = (const ulonglong2*)(W2s + f * 36);
            const u64*        v1p = (const u64*)(W2s + f * 36);
            ulonglong2 b0v = v2p[0], b1v = v2p[1], b2v = v2p[2], b3v = v2p[3];
            ulonglong2 b4v = v2p[4], b5v = v2p[5], b6v = v2p[6], b7v = v2p[7];
            u64 b16 = v1p[16];
            y0[0]  = fma2(hp0, b0v.x, y0[0]);   y1[0]  = fma2(hp1, b0v.x, y1[0]);
            y0[1]  = fma2(hp0, b0v.y, y0[1]);   y1[1]  = fma2(hp1, b0v.y, y1[1]);
            y0[2]  = fma2(hp0, b1v.x, y0[2]);   y1[2]  = fma2(hp1, b1v.x, y1[2]);
            y0[3]  = fma2(hp0, b1v.y, y0[3]);   y1[3]  = fma2(hp1, b1v.y, y1[3]);
            y0[4]  = fma2(hp0, b2v.x, y0[4]);   y1[4]  = fma2(hp1, b2v.x, y1[4]);
            y0[5]  = fma2(hp0, b2v.y, y0[5]);   y1[5]  = fma2(hp1, b2v.y, y1[5]);
            y0[6]  = fma2(hp0, b3v.x, y0[6]);   y1[6]  = fma2(hp1, b3v.x, y1[6]);
            y0[7]  = fma2(hp0, b3v.y, y0[7]);   y1[7]  = fma2(hp1, b3v.y, y1[7]);
            y0[8]  = fma2(hp0, b4v.x, y0[8]);   y1[8]  = fma2(hp1, b4v.x, y1[8]);
            y0[9]  = fma2(hp0, b4v.y, y0[9]);   y1[9]  = fma2(hp1, b4v.y, y1[9]);
            y0[10] = fma2(hp0, b5v.x, y0[10]);  y1[10] = fma2(hp1, b5v.x, y1[10]);
            y0[11] = fma2(hp0, b5v.y, y0[11]);  y1[11] = fma2(hp1, b5v.y, y1[11]);
            y0[12] = fma2(hp0, b6v.x, y0[12]);  y1[12] = fma2(hp1, b6v.x, y1[12]);
            y0[13] = fma2(hp0, b6v.y, y0[13]);  y1[13] = fma2(hp1, b6v.y, y1[13]);
            y0[14] = fma2(hp0, b7v.x, y0[14]);  y1[14] = fma2(hp1, b7v.x, y1[14]);
            y0[15] = fma2(hp0, b7v.y, y0[15]);  y1[15] = fma2(hp1, b7v.y, y1[15]);
            y0[16] = fma2(hp0, b16, y0[16]);    y1[16] = fma2(hp1, b16, y1[16]);
        }
        __syncthreads();
    }
    if (a0) {
        u64* yo = (u64*)(g_yp + ((size_t)blockIdx.z * S + s0) * Dm);
#pragma unroll
        for (int i = 0; i < 17; i++) yo[i] = y0[i];
    }
    if (a1) {
        u64* yo = (u64*)(g_yp + ((size_t)blockIdx.z * S + s1) * Dm);
#pragma unroll
        for (int i = 0; i < 17; i++) yo[i] = y1[i];
    }
}

// ---------------------------------------------------------------------------
// Full-S FFN reduce + residual + LN
// ---------------------------------------------------------------------------
__global__ void __launch_bounds__(128) ffn_reduce(const float* __restrict__ l2b,
                                                  const float* __restrict__ gg,
                                                  const float* __restrict__ bb) {
    __shared__ float bs[Dm], gs[Dm], bts[Dm];
    int tid = threadIdx.x;
    if (tid < Dm) { bs[tid] = l2b[tid]; gs[tid] = gg[tid]; bts[tid] = bb[tid]; }
    __syncthreads();
    int s = blockIdx.x * 128 + tid;
    if (s >= S) return;
    float y[Dm];
#pragma unroll
    for (int d = 0; d < Dm; d++) y[d] = g_x[s * Dm + d] + bs[d];
#pragma unroll
    for (int g = 0; g < NFSEG; g++) {
        const float* yp = g_yp + ((size_t)g * S + s) * Dm;
#pragma unroll
        for (int d = 0; d < Dm; d++) y[d] += yp[d];
    }
    float m = 0.f;
#pragma unroll
    for (int d = 0; d < Dm; d++) m += y[d];
    m *= (1.0f / Dm);
    float v = 0.f;
#pragma unroll
    for (int d = 0; d < Dm; d++) { float t = y[d] - m; v = fmaf(t, t, v); }
    v *= (1.0f / Dm);
    float inv = rsqrtf(v + EPSV);
#pragma unroll
    for (int d = 0; d < Dm; d++) g_x[s * Dm + d] = (y[d] - m) * inv * gs[d] + bts[d];
}

// ---------------------------------------------------------------------------
// Layer-1 QKV (full S; only K/V fully used, Q used for 81 agent rows)
// ---------------------------------------------------------------------------
__global__ void qkv_kernel(const float* __restrict__ ipw, const float* __restrict__ ipb) {
    __shared__ float xs[Dm * 32];
    __shared__ float ws[102 * Dm];
    __shared__ float bs[102];
    int tid = threadIdx.x;
    int row0 = blockIdx.x * 32;
    for (int i = tid; i < 102 * Dm; i += blockDim.x) ws[i] = ipw[i];
    for (int i = tid; i < 102; i += blockDim.x) bs[i] = ipb[i];
    for (int i = tid; i < Dm * 32; i += blockDim.x) {
        int d = i >> 5, r = i & 31;
        xs[i] = (row0 + r < S) ? g_x[(row0 + r) * Dm + d] : 0.f;
    }
    __syncthreads();
    const float scale = rsqrtf(17.f);
    int lane = tid & 31, w = tid >> 5;
    int s = row0 + lane;
    for (int cc = w; cc < 102; cc += 8) {
        float acc = bs[cc];
        const float* wp = ws + cc * Dm;
#pragma unroll
        for (int d = 0; d < Dm; d++) acc = fmaf(xs[d * 32 + lane], wp[d], acc);
        if (s < S) {
            int kind = cc / Dm;
            int c2 = cc % Dm;
            int h = c2 / HD, dd = c2 % HD;
            int off = (h * S + s) * PH + dd;
            if (kind == 0)      g_q[off] = acc * scale;
            else if (kind == 1) g_k[off] = acc;
            else                g_v[off] = acc;
        }
    }
}

// ---------------------------------------------------------------------------
// Layer-1 agent attention partial: 81 queries only, keys split 127 ways.
// grid (NSEG2, NH), block 128 (81 active).
// ---------------------------------------------------------------------------
__global__ void __launch_bounds__(128) attn_agent() {
    __shared__ __align__(16) float Ks[KSEG2 * PH];
    __shared__ __align__(16) float Vs[KSEG2 * PH];
    int tid = threadIdx.x;
    int seg = blockIdx.x, h = blockIdx.y;
    int k0 = seg * KSEG2;
    int n = min(KSEG2, S - k0);
    int start = g_agent * HW;

    const float4* ksrc = (const float4*)(g_k + (h * S + k0) * PH);
    const float4* vsrc = (const float4*)(g_v + (h * S + k0) * PH);
    float4* kdst = (float4*)Ks; float4* vdst = (float4*)Vs;
    for (int i = tid; i < n * 5; i += 128) { kdst[i] = ksrc[i]; vdst[i] = vsrc[i]; }
    __syncthreads();

    if (tid >= HW) return;
    u64 q[9], acc[9];
    const u64* qp = (const u64*)(g_q + (h * S + start + tid) * PH);
#pragma unroll
    for (int i = 0; i < 9; i++) { q[i] = qp[i]; acc[i] = 0ULL; }
    float ssum = 0.f;

    const ulonglong2* K2 = (const ulonglong2*)Ks;
    const ulonglong2* V2 = (const ulonglong2*)Vs;
    for (int kk = 0; kk < n; kk++) {
        ulonglong2 ka = K2[0], kb = K2[1], kc = K2[2], kd = K2[3];
        u64 ke = K2[4].x;
        u64 t0 = mul2(q[0], ka.x),  t1 = mul2(q[1], ka.y);
        t0 = fma2(q[2], kb.x, t0);  t1 = fma2(q[3], kb.y, t1);
        t0 = fma2(q[4], kc.x, t0);  t1 = fma2(q[5], kc.y, t1);
        t0 = fma2(q[6], kd.x, t0);  t1 = fma2(q[7], kd.y, t1);
        t0 = fma2(q[8], ke, t0);
        t0 = add2(t0, t1);
        float2 f = unpk(t0);
        float p = __expf(f.x + f.y);
        ssum += p;
        u64 pp = pk(p, p);
        ulonglong2 va = V2[0], vb = V2[1], vc = V2[2], vd = V2[3];
        u64 ve = V2[4].x;
        acc[0] = fma2(pp, va.x, acc[0]); acc[1] = fma2(pp, va.y, acc[1]);
        acc[2] = fma2(pp, vb.x, acc[2]); acc[3] = fma2(pp, vb.y, acc[3]);
        acc[4] = fma2(pp, vc.x, acc[4]); acc[5] = fma2(pp, vc.y, acc[5]);
        acc[6] = fma2(pp, vd.x, acc[6]); acc[7] = fma2(pp, vd.y, acc[7]);
        acc[8] = fma2(pp, ve, acc[8]);
        K2 += 5; V2 += 5;
    }
    u64* pa = (u64*)(g_pacca + ((h * NSEG2 + seg) * HW + tid) * PAC);
#pragma unroll
    for (int i = 0; i < 9; i++) pa[i] = acc[i];
    g_psuma[(h * NSEG2 + seg) * HW + tid] = ssum;
}

// ---------------------------------------------------------------------------
// combine agent attention segments -> g_oa[81][34]
// ---------------------------------------------------------------------------
__global__ void attn_reduce_agent() {
    int e = blockIdx.x * blockDim.x + threadIdx.x;
    if (e >= HW * Dm) return;
    int r = e / Dm, c = e % Dm;
    int h = c / HD, d = c % HD;
    float a = 0.f, sm = 0.f;
    for (int g = 0; g < NSEG2; g++) {
        a  += g_pacca[((h * NSEG2 + g) * HW + r) * PAC + d];
        sm += g_psuma[(h * NSEG2 + g) * HW + r];
    }
    g_oa[r * Dm + c] = a / sm;
}

// ---------------------------------------------------------------------------
// agent out_proj + residual + LN -> g_xa[81][34]
// ---------------------------------------------------------------------------
__global__ void __launch_bounds__(128) proj_ln_agent(const float* __restrict__ opw,
                                                     const float* __restrict__ opb,
                                                     const float* __restrict__ gg,
                                                     const float* __restrict__ bb) {
    __shared__ float ws[Dm * Dm];
    __shared__ float bs[Dm], gs[Dm], bts[Dm];
    int tid = threadIdx.x;
    for (int i = tid; i < Dm * Dm; i += blockDim.x) ws[i] = opw[i];
    if (tid < Dm) { bs[tid] = opb[tid]; gs[tid] = gg[tid]; bts[tid] = bb[tid]; }
    __syncthreads();
    if (tid >= HW) return;
    int s = g_agent * HW + tid;
    float orow[Dm], y[Dm];
#pragma unroll
    for (int d = 0; d < Dm; d++) orow[d] = g_oa[tid * Dm + d];
#pragma unroll 2
    for (int d = 0; d < Dm; d++) {
        float a = bs[d] + g_x[s * Dm + d];
        const float* wp = ws + d * Dm;
#pragma unroll
        for (int k = 0; k < Dm; k++) a = fmaf(orow[k], wp[k], a);
        y[d] = a;
    }
    float m = 0.f;
#pragma unroll
    for (int d = 0; d < Dm; d++) m += y[d];
    m *= (1.0f / Dm);
    float v = 0.f;
#pragma unroll
    for (int d = 0; d < Dm; d++) { float t = y[d] - m; v = fmaf(t, t, v); }
    v *= (1.0f / Dm);
    float inv = rsqrtf(v + EPSV);
#pragma unroll
    for (int d = 0; d < Dm; d++) g_xa[tid * Dm + d] = (y[d] - m) * inv * gs[d] + bts[d];
}

// ---------------------------------------------------------------------------
// agent FFN partial: grid (NFSEG2=32), 81 rows, FSEG2=64 f's per block
// ---------------------------------------------------------------------------
__global__ void __launch_bounds__(128) ffn_agent(const float* __restrict__ l1w,
                                                 const float* __restrict__ l1b,
                                                 const float* __restrict__ l2w) {
    __shared__ __align__(16) float W1s[FSEG2 * 36];
    __shared__ __align__(16) float W2s[FSEG2 * 36];
    __shared__ float b1s[FSEG2];
    int tid = threadIdx.x;
    int fbase = blockIdx.x * FSEG2;
    for (int e2 = tid; e2 < FSEG2 * Dm; e2 += 128) {
        int f = e2 / Dm, d = e2 % Dm;
        W1s[f * 36 + d] = l1w[(fbase + f) * Dm + d];
        W2s[f * 36 + d] = l2w[d * FFd + fbase + f];
    }
    for (int e2 = tid; e2 < FSEG2; e2 += 128) b1s[e2] = l1b[fbase + e2];
    __syncthreads();
    if (tid >= HW) return;
    u64 xr[17], y[17];
    const u64* p = (const u64*)(g_xa + tid * Dm);
#pragma unroll
    for (int i = 0; i < 17; i++) { xr[i] = p[i]; y[i] = 0ULL; }
#pragma unroll 2
    for (int f = 0; f < FSEG2; f++) {
        const ulonglong2* w2p = (const ulonglong2*)(W1s + f * 36);
        const u64*        w1p = (const u64*)(W1s + f * 36);
        ulonglong2 a0 = w2p[0], a1 = w2p[1], a2 = w2p[2], a3 = w2p[3];
        ulonglong2 a4 = w2p[4], a5 = w2p[5], a6 = w2p[6], a7 = w2p[7];
        u64 a16 = w1p[16];
        u64 t0 = mul2(xr[0], a0.x),  t1 = mul2(xr[1], a0.y);
        t0 = fma2(xr[2], a1.x, t0);  t1 = fma2(xr[3], a1.y, t1);
        t0 = fma2(xr[4], a2.x, t0);  t1 = fma2(xr[5], a2.y, t1);
        t0 = fma2(xr[6], a3.x, t0);  t1 = fma2(xr[7], a3.y, t1);
        t0 = fma2(xr[8], a4.x, t0);  t1 = fma2(xr[9], a4.y, t1);
        t0 = fma2(xr[10], a5.x, t0); t1 = fma2(xr[11], a5.y, t1);
        t0 = fma2(xr[12], a6.x, t0); t1 = fma2(xr[13], a6.y, t1);
        t0 = fma2(xr[14], a7.x, t0); t1 = fma2(xr[15], a7.y, t1);
        t0 = fma2(xr[16], a16, t0);
        t0 = add2(t0, t1);
        float2 fh = unpk(t0);
        float hrelu = fmaxf(fh.x + fh.y + b1s[f], 0.f);
        u64 hp = pk(hrelu, hrelu);
        const ulonglong2* v2p = (const ulonglong2*)(W2s + f * 36);
        const u64*        v1p = (const u64*)(W2s + f * 36);
        ulonglong2 b0 = v2p[0], b1v = v2p[1], b2v = v2p[2], b3 = v2p[3];
        ulonglong2 b4 = v2p[4], b5 = v2p[5], b6 = v2p[6], b7 = v2p[7];
        u64 b16 = v1p[16];
        y[0]  = fma2(hp, b0.x, y[0]);   y[1]  = fma2(hp, b0.y, y[1]);
        y[2]  = fma2(hp, b1v.x, y[2]);  y[3]  = fma2(hp, b1v.y, y[3]);
        y[4]  = fma2(hp, b2v.x, y[4]);  y[5]  = fma2(hp, b2v.y, y[5]);
        y[6]  = fma2(hp, b3.x, y[6]);   y[7]  = fma2(hp, b3.y, y[7]);
        y[8]  = fma2(hp, b4.x, y[8]);   y[9]  = fma2(hp, b4.y, y[9]);
        y[10] = fma2(hp, b5.x, y[10]);  y[11] = fma2(hp, b5.y, y[11]);
        y[12] = fma2(hp, b6.x, y[12]);  y[13] = fma2(hp, b6.y, y[13]);
        y[14] = fma2(hp, b7.x, y[14]);  y[15] = fma2(hp, b7.y, y[15]);
        y[16] = fma2(hp, b16, y[16]);
    }
    u64* yo = (u64*)(g_ypa + ((size_t)blockIdx.x * HW + tid) * Dm);
#pragma unroll
    for (int i = 0; i < 17; i++) yo[i] = y[i];
}

// ---------------------------------------------------------------------------
// agent FFN reduce + residual + LN -> g_xa
// ---------------------------------------------------------------------------
__global__ void __launch_bounds__(128) ffn_reduce_agent(const float* __restrict__ l2b,
                                                        const float* __restrict__ gg,
                                                        const float* __restrict__ bb) {
    __shared__ float bs[Dm], gs[Dm], bts[Dm];
    int tid = threadIdx.x;
    if (tid < Dm) { bs[tid] = l2b[tid]; gs[tid] = gg[tid]; bts[tid] = bb[tid]; }
    __syncthreads();
    if (tid >= HW) return;
    float y[Dm];
#pragma unroll
    for (int d = 0; d < Dm; d++) y[d] = g_xa[tid * Dm + d] + bs[d];
    for (int g = 0; g < NFSEG2; g++) {
        const float* yp = g_ypa + ((size_t)g * HW + tid) * Dm;
#pragma unroll
        for (int d = 0; d < Dm; d++) y[d] += yp[d];
    }
    float m = 0.f;
#pragma unroll
    for (int d = 0; d < Dm; d++) m += y[d];
    m *= (1.0f / Dm);
    float v = 0.f;
#pragma unroll
    for (int d = 0; d < Dm; d++) { float t = y[d] - m; v = fmaf(t, t, v); }
    v *= (1.0f / Dm);
    float inv = rsqrtf(v + EPSV);
#pragma unroll
    for (int d = 0; d < Dm; d++) g_xa[tid * Dm + d] = (y[d] - m) * inv * gs[d] + bts[d];
}

// ---------------------------------------------------------------------------
// final mean over 81 agent rows
// ---------------------------------------------------------------------------
__global__ void final_out(float* __restrict__ out) {
    int d = threadIdx.x;
    if (d >= Dm) return;
    float sum = 0.f;
    for (int r = 0; r < HW; r++) sum += g_xa[r * Dm + d];
    out[d] = sum * (1.0f / 81.0f);
}

// ---------------------------------------------------------------------------
extern "C" void kernel_launch(void* const* d_in, const int* in_sizes, int n_in,
                              void* d_out, int out_size) {
    const float* obs = (const float*)d_in[0];
    const float* c1w = (const float*)d_in[1];
    const float* c1b = (const float*)d_in[2];
    const float* c2w = (const float*)d_in[3];
    const float* c2b = (const float*)d_in[4];
    const float* ipw = (const float*)d_in[5];
    const float* ipb = (const float*)d_in[6];
    const float* opw = (const float*)d_in[7];
    const float* opb = (const float*)d_in[8];
    const float* l1w = (const float*)d_in[9];
    const float* l1b = (const float*)d_in[10];
    const float* l2w = (const float*)d_in[11];
    const float* l2b = (const float*)d_in[12];
    const float* g1  = (const float*)d_in[13];
    const float* b1  = (const float*)d_in[14];
    const float* g2  = (const float*)d_in[15];
    const float* b2  = (const float*)d_in[16];
    float* out = (float*)d_out;

    conv_prep<<<1, 128>>>(obs, c1w, c1b, c2w, c2b);
    build_tokens<<<(S + 127) / 128, 128>>>();

    // ---- layer 0: structured attention + full FFN (all S tokens) ----
    basis_qkv<<<(162 * 102 + 127) / 128, 128>>>(ipw, ipb);
    logits_exp<<<(4 * ESTR + 127) / 128, 128>>>();
    attn_struct<<<dim3(HW, NH), 128>>>();
    proj_ln<<<(S + 127) / 128, 128>>>(opw, opb, g1, b1);
    ffn_kernel<<<dim3((S + 255) / 256, 1, NFSEG), 128>>>(l1w, l1b, l2w);
    ffn_reduce<<<(S + 127) / 128, 128>>>(l2b, g2, b2);

    // ---- layer 1: agent-only path (only 81 query rows feed the output) ----
    qkv_kernel<<<(S + 31) / 32, 256>>>(ipw + 102 * Dm, ipb + 102);
    attn_agent<<<dim3(NSEG2, NH), 128>>>();
    attn_reduce_agent<<<(HW * Dm + 127) / 128, 128>>>();
    proj_ln_agent<<<1, 128>>>(opw + Dm * Dm, opb + Dm, g1 + Dm, b1 + Dm);
    ffn_agent<<<NFSEG2, 128>>>(l1w + FFd * Dm, l1b + FFd, l2w + Dm * FFd);
    ffn_reduce_agent<<<1, 128>>>(l2b + Dm, g2 + Dm, b2 + Dm);

    final_out<<<1, 64>>>(out);
}

// round 6
// speedup vs baseline: 2.9596x; 1.0256x over previous
#include <cuda_runtime.h>

#define S      6561
#define Dm     34
#define HD     17
#define PH     20
#define PAC    18
#define FFd    2048
#define NH     2
#define HW     81
#define EPSV   1e-5f
#define ESTR   (NH * HW * HW)
#define GRID   148
#define NTHR   256
// layer-0 FFN tiling
#define NFSEG  16
#define FSEG   128
#define NROWT  26
#define NTILE  (NROWT * NFSEG)   // 416
// layer-1 agent attention: 2 heads x 74 key segments = 148 units
#define NSEG2  74
#define KSEG2  89
// agent FFN split
#define NFSEG2 32
#define FSEG2  64

typedef unsigned long long u64;

// ---- packed fp32 helpers ----
__device__ __forceinline__ u64 fma2(u64 a, u64 b, u64 c) {
    u64 d; asm("fma.rn.f32x2 %0, %1, %2, %3;" : "=l"(d) : "l"(a), "l"(b), "l"(c)); return d;
}
__device__ __forceinline__ u64 mul2(u64 a, u64 b) {
    u64 d; asm("mul.rn.f32x2 %0, %1, %2;" : "=l"(d) : "l"(a), "l"(b)); return d;
}
__device__ __forceinline__ u64 add2(u64 a, u64 b) {
    u64 d; asm("add.rn.f32x2 %0, %1, %2;" : "=l"(d) : "l"(a), "l"(b)); return d;
}
__device__ __forceinline__ float2 unpk(u64 v) {
    float2 f; asm("mov.b64 {%0, %1}, %2;" : "=f"(f.x), "=f"(f.y) : "l"(v)); return f;
}
__device__ __forceinline__ u64 pk(float x, float y) {
    u64 v; asm("mov.b64 %0, {%1, %2};" : "=l"(v) : "f"(x), "f"(y)); return v;
}

// ---- device-global scratch (zero-init at load) ----
__device__ unsigned g_cnt;     // barrier counter (returns to 0 each launch)
__device__ unsigned g_sense;   // barrier sense (even #syncs -> returns to 0)
__device__ int   g_agent;
__device__ __align__(16) float g_emb[HW * 16];
__device__ __align__(16) float g_x[S * Dm];
__device__ __align__(16) float g_q[NH * S * PH];
__device__ __align__(16) float g_k[NH * S * PH];
__device__ __align__(16) float g_v[NH * S * PH];
__device__ __align__(16) float g_o[S * Dm];
__device__ __align__(16) float g_yp[NFSEG * S * Dm];
__device__ __align__(16) float g_QA[NH * HW * HD];
__device__ __align__(16) float g_QB[NH * HW * HD];
__device__ __align__(16) float g_KA[NH * HW * HD];
__device__ __align__(16) float g_KB[NH * HW * HD];
__device__ __align__(16) float g_VA[NH * HW * HD];
__device__ __align__(16) float g_VB[NH * HW * HD];
__device__ __align__(16) float g_E[4 * ESTR];
__device__ __align__(16) float g_pacca[NH * NSEG2 * HW * PAC];
__device__ float g_psuma[NH * NSEG2 * HW];
__device__ __align__(16) float g_xa[HW * Dm];
__device__ __align__(16) float g_ypa[NFSEG2 * HW * Dm];

// ---- sense-reversing grid barrier (all GRID blocks resident -> safe) ----
__device__ __forceinline__ void gsync(unsigned& ls) {
    __syncthreads();
    if (threadIdx.x == 0) {
        unsigned ns = ls ^ 1u;
        __threadfence();
        unsigned old = atomicAdd(&g_cnt, 1u);
        if (old == gridDim.x - 1u) {
            g_cnt = 0u;                 // safe: all blocks have arrived
            __threadfence();
            atomicExch(&g_sense, ns);   // release
        } else {
            while (atomicAdd(&g_sense, 0u) != ns) { __nanosleep(64); }
        }
        ls = ns;
        __threadfence();
    }
    __syncthreads();
}

__global__ void __launch_bounds__(NTHR, 1) mega(
    const float* __restrict__ obs,
    const float* __restrict__ c1w, const float* __restrict__ c1b,
    const float* __restrict__ c2w, const float* __restrict__ c2b,
    const float* __restrict__ ipw, const float* __restrict__ ipb,
    const float* __restrict__ opw, const float* __restrict__ opb,
    const float* __restrict__ l1w, const float* __restrict__ l1b,
    const float* __restrict__ l2w, const float* __restrict__ l2b,
    const float* __restrict__ g1,  const float* __restrict__ b1,
    const float* __restrict__ g2,  const float* __restrict__ b2,
    float* __restrict__ out)
{
    __shared__ __align__(16) float sm[9600];
    int tid = threadIdx.x;
    int b = blockIdx.x;
    unsigned ls = 0;

    // ---------------- P0: conv1/conv2 + argmax (block 0) ----------------
    if (b == 0) {
        float* so  = sm;            // 162
        float* c1s = sm + 192;      // 1296
        for (int i = tid; i < 162; i += NTHR) so[i] = obs[i];
        __syncthreads();
        if (tid == 0) {
            float mx = so[0]; int mi = 0;
            for (int i = 1; i < 81; i++) if (so[i] > mx) { mx = so[i]; mi = i; }
            g_agent = mi;
        }
        for (int idx = tid; idx < 16 * 81; idx += NTHR) {
            int ch = idx / 81, pos = idx % 81, r = pos / 9, c = pos % 9;
            float acc = c1b[ch];
            for (int ci = 0; ci < 2; ci++)
                for (int dr = 0; dr < 3; dr++) {
                    int rr = r + dr - 1; if (rr < 0 || rr >= 9) continue;
                    for (int dc = 0; dc < 3; dc++) {
                        int cc = c + dc - 1; if (cc < 0 || cc >= 9) continue;
                        acc += so[ci * 81 + rr * 9 + cc] * c1w[((ch * 2 + ci) * 3 + dr) * 3 + dc];
                    }
                }
            c1s[idx] = fmaxf(acc, 0.f);
        }
        __syncthreads();
        for (int idx = tid; idx < 16 * 81; idx += NTHR) {
            int ch = idx / 81, pos = idx % 81, r = pos / 9, c = pos % 9;
            float acc = c2b[ch];
            for (int ci = 0; ci < 16; ci++)
                for (int dr = 0; dr < 3; dr++) {
                    int rr = r + dr - 1; if (rr < 0 || rr >= 9) continue;
                    for (int dc = 0; dc < 3; dc++) {
                        int cc = c + dc - 1; if (cc < 0 || cc >= 9) continue;
                        acc += c1s[ci * 81 + rr * 9 + cc] * c2w[((ch * 16 + ci) * 3 + dr) * 3 + dc];
                    }
                }
            g_emb[pos * 16 + ch] = fmaxf(acc, 0.f);
        }
    }
    gsync(ls);  // 1

    // ---------------- P1: layer-0 basis QKV ----------------
    for (int idx = b * NTHR + tid; idx < 162 * 102; idx += GRID * NTHR) {
        int v = idx / 102, c = idx % 102;
        const float* wr = ipw + c * Dm;
        float acc;
        if (v < 81) {
            int i = v;
            acc = ipb[c];
#pragma unroll
            for (int d = 0; d < 16; d++) acc = fmaf(g_emb[i * 16 + d], wr[d], acc);
            acc = fmaf((float)(i / 9) * 0.25f, wr[32], acc);
            acc = fmaf((float)(i % 9) * 0.25f, wr[33], acc);
        } else {
            int j = v - 81;
            acc = 0.f;
#pragma unroll
            for (int d = 0; d < 16; d++) acc = fmaf(g_emb[j * 16 + d], wr[16 + d], acc);
            acc = fmaf(-(float)(j / 9) * 0.25f, wr[32], acc);
            acc = fmaf(-(float)(j % 9) * 0.25f, wr[33], acc);
        }
        int kind = c / Dm;
        int cc = c % Dm;
        int h = cc / HD, dd = cc % HD;
        int off = (h * HW + (v % 81)) * HD + dd;
        if (kind == 0) {
            float sv = acc * rsqrtf(17.f);
            if (v < 81) g_QA[off] = sv; else g_QB[off] = sv;
        } else if (kind == 1) {
            if (v < 81) g_KA[off] = acc; else g_KB[off] = acc;
        } else {
            if (v < 81) g_VA[off] = acc; else g_VB[off] = acc;
        }
    }
    gsync(ls);  // 2

    // ---------------- P2: exp(logit) matrices ----------------
    for (int idx = b * NTHR + tid; idx < 4 * ESTR; idx += GRID * NTHR) {
        int p = idx / ESTR;
        int r = idx % ESTR;
        int h = r / (HW * HW);
        int q2 = r % (HW * HW);
        int i = q2 / HW, m = q2 % HW;
        const float* L = ((p < 2) ? g_QA : g_QB) + (h * HW + i) * HD;
        const float* R = ((p & 1) ? g_KB : g_KA) + (h * HW + m) * HD;
        float dot = 0.f;
#pragma unroll
        for (int d = 0; d < HD; d++) dot = fmaf(L[d], R[d], dot);
        g_E[idx] = __expf(dot);
    }
    gsync(ls);  // 3

    // ---------------- P3: structured attention -> g_o ----------------
    {
        float* sea = sm;            // 81
        float* seb = sm + 96;       // 81
        float* sva = sm + 192;      // 81*18
        float* svb = sm + 1664;     // 81*18
        for (int u = b; u < HW * NH; u += GRID) {
            int i = u % HW, h = u / HW;
            __syncthreads();
            for (int t = tid; t < HW; t += NTHR) {
                sea[t] = g_E[0 * ESTR + (h * HW + i) * HW + t];
                seb[t] = g_E[1 * ESTR + (h * HW + i) * HW + t];
            }
            for (int t = tid; t < HW * 18; t += NTHR) {
                int m = t / 18, d = t % 18;
                sva[t] = (d < HD) ? g_VA[(h * HW + m) * HD + d] : 0.f;
                svb[t] = (d < HD) ? g_VB[(h * HW + m) * HD + d] : 0.f;
            }
            __syncthreads();
            if (tid < HW) {
                int j = tid;
                const float* ecr = g_E + 2 * ESTR + (h * HW + j) * HW;
                const float* edr = g_E + 3 * ESTR + (h * HW + j) * HW;
                float zm = 0.f, zn = 0.f;
                u64 wa[9], wb[9];
#pragma unroll
                for (int k = 0; k < 9; k++) { wa[k] = 0ULL; wb[k] = 0ULL; }
                for (int m = 0; m < HW; m++) {
                    float f = sea[m] * ecr[m];
                    zm += f;
                    u64 fp = pk(f, f);
                    const u64* vr = (const u64*)(sva + m * 18);
#pragma unroll
                    for (int k = 0; k < 9; k++) wa[k] = fma2(fp, vr[k], wa[k]);
                }
                for (int n = 0; n < HW; n++) {
                    float g = seb[n] * edr[n];
                    zn += g;
                    u64 gp = pk(g, g);
                    const u64* vr = (const u64*)(svb + n * 18);
#pragma unroll
                    for (int k = 0; k < 9; k++) wb[k] = fma2(gp, vr[k], wb[k]);
                }
                float inv = 1.0f / (zm * zn);
                float* od = g_o + (i * HW + j) * Dm + h * HD;
#pragma unroll
                for (int k = 0; k < 9; k++) {
                    float2 A = unpk(wa[k]), B = unpk(wb[k]);
                    int d = 2 * k;
                    od[d] = (A.x * zn + B.x * zm) * inv;
                    if (d + 1 < HD) od[d + 1] = (A.y * zn + B.y * zm) * inv;
                }
            }
        }
    }
    gsync(ls);  // 4

    // ---------------- P4: tokens + out_proj + residual + LN1 -> g_x ----------------
    if (b * NTHR < S) {
        float* embs = sm;           // 1296
        float* ws   = sm + 1296;    // 1156
        float* obs_ = sm + 2452;    // 34 (opb)
        float* gs   = sm + 2486;    // 34
        float* bts  = sm + 2520;    // 34
        for (int i = tid; i < 1296; i += NTHR) embs[i] = g_emb[i];
        for (int i = tid; i < Dm * Dm; i += NTHR) ws[i] = opw[i];
        if (tid < Dm) { obs_[tid] = opb[tid]; gs[tid] = g1[tid]; bts[tid] = b1[tid]; }
        __syncthreads();
        int t = b * NTHR + tid;
        if (t < S) {
            int i = t / HW, j = t % HW;
            float x[Dm], orow[Dm], y[Dm];
#pragma unroll
            for (int d = 0; d < 16; d++) x[d] = embs[i * 16 + d];
#pragma unroll
            for (int d = 0; d < 16; d++) x[16 + d] = embs[j * 16 + d];
            x[32] = ((float)(i / 9) - (float)(j / 9)) * 0.25f;
            x[33] = ((float)(i % 9) - (float)(j % 9)) * 0.25f;
#pragma unroll
            for (int d = 0; d < Dm; d++) orow[d] = g_o[t * Dm + d];
#pragma unroll 2
            for (int d = 0; d < Dm; d++) {
                float a = obs_[d] + x[d];
                const float* wp = ws + d * Dm;
#pragma unroll
                for (int k = 0; k < Dm; k++) a = fmaf(orow[k], wp[k], a);
                y[d] = a;
            }
            float m = 0.f;
#pragma unroll
            for (int d = 0; d < Dm; d++) m += y[d];
            m *= (1.0f / Dm);
            float v = 0.f;
#pragma unroll
            for (int d = 0; d < Dm; d++) { float tt = y[d] - m; v = fmaf(tt, tt, v); }
            v *= (1.0f / Dm);
            float inv = rsqrtf(v + EPSV);
#pragma unroll
            for (int d = 0; d < Dm; d++) g_x[t * Dm + d] = (y[d] - m) * inv * gs[d] + bts[d];
        }
    }
    gsync(ls);  // 5

    // ---------------- P5: layer-0 FFN partials (416 tiles) ----------------
    {
        float* W1s = sm;            // 128*36
        float* W2s = sm + 4608;     // 128*36
        float* b1s = sm + 9216;     // 128
        for (int t = b; t < NTILE; t += GRID) {
            int rt = t / NFSEG;
            int fcn = t % NFSEG;
            int fbase = fcn * FSEG;
            __syncthreads();
            for (int e = tid; e < FSEG * Dm; e += NTHR) {
                int f = e / Dm, d = e % Dm;
                W1s[f * 36 + d] = l1w[(fbase + f) * Dm + d];
                W2s[f * 36 + d] = l2w[d * FFd + fbase + f];
            }
            for (int e = tid; e < FSEG; e += NTHR) b1s[e] = l1b[fbase + e];
            __syncthreads();
            int row = rt * NTHR + tid;
            if (row < S) {
                u64 xr[17], y[17];
                const u64* p = (const u64*)(g_x + row * Dm);
#pragma unroll
                for (int i = 0; i < 17; i++) { xr[i] = p[i]; y[i] = 0ULL; }
#pragma unroll 2
                for (int f = 0; f < FSEG; f++) {
                    const ulonglong2* w2p = (const ulonglong2*)(W1s + f * 36);
                    const u64*        w1p = (const u64*)(W1s + f * 36);
                    ulonglong2 a0 = w2p[0], a1 = w2p[1], a2 = w2p[2], a3 = w2p[3];
                    ulonglong2 a4 = w2p[4], a5 = w2p[5], a6 = w2p[6], a7 = w2p[7];
                    u64 a16 = w1p[16];
                    u64 t0 = mul2(xr[0], a0.x),  t1 = mul2(xr[1], a0.y);
                    t0 = fma2(xr[2], a1.x, t0);  t1 = fma2(xr[3], a1.y, t1);
                    t0 = fma2(xr[4], a2.x, t0);  t1 = fma2(xr[5], a2.y, t1);
                    t0 = fma2(xr[6], a3.x, t0);  t1 = fma2(xr[7], a3.y, t1);
                    t0 = fma2(xr[8], a4.x, t0);  t1 = fma2(xr[9], a4.y, t1);
                    t0 = fma2(xr[10], a5.x, t0); t1 = fma2(xr[11], a5.y, t1);
                    t0 = fma2(xr[12], a6.x, t0); t1 = fma2(xr[13], a6.y, t1);
                    t0 = fma2(xr[14], a7.x, t0); t1 = fma2(xr[15], a7.y, t1);
                    t0 = fma2(xr[16], a16, t0);
                    t0 = add2(t0, t1);
                    float2 fh = unpk(t0);
                    float hrelu = fmaxf(fh.x + fh.y + b1s[f], 0.f);
                    u64 hp = pk(hrelu, hrelu);
                    const ulonglong2* v2p = (const ulonglong2*)(W2s + f * 36);
                    const u64*        v1p = (const u64*)(W2s + f * 36);
                    ulonglong2 b0 = v2p[0], b1v = v2p[1], b2v = v2p[2], b3 = v2p[3];
                    ulonglong2 b4 = v2p[4], b5 = v2p[5], b6 = v2p[6], b7 = v2p[7];
                    u64 b16 = v1p[16];
                    y[0]  = fma2(hp, b0.x, y[0]);   y[1]  = fma2(hp, b0.y, y[1]);
                    y[2]  = fma2(hp, b1v.x, y[2]);  y[3]  = fma2(hp, b1v.y, y[3]);
                    y[4]  = fma2(hp, b2v.x, y[4]);  y[5]  = fma2(hp, b2v.y, y[5]);
                    y[6]  = fma2(hp, b3.x, y[6]);   y[7]  = fma2(hp, b3.y, y[7]);
                    y[8]  = fma2(hp, b4.x, y[8]);   y[9]  = fma2(hp, b4.y, y[9]);
                    y[10] = fma2(hp, b5.x, y[10]);  y[11] = fma2(hp, b5.y, y[11]);
                    y[12] = fma2(hp, b6.x, y[12]);  y[13] = fma2(hp, b6.y, y[13]);
                    y[14] = fma2(hp, b7.x, y[14]);  y[15] = fma2(hp, b7.y, y[15]);
                    y[16] = fma2(hp, b16, y[16]);
                }
                u64* yo = (u64*)(g_yp + ((size_t)fcn * S + row) * Dm);
#pragma unroll
                for (int i = 0; i < 17; i++) yo[i] = y[i];
            }
        }
    }
    gsync(ls);  // 6

    // ---------------- P6: FFN reduce + LN2 + layer-1 QKV ----------------
    if (b * NTHR < S) {
        const float* ipw2 = ipw + 102 * Dm;
        const float* ipb2 = ipb + 102;
        float* ws   = sm;           // 3468
        float* ibs  = sm + 3468;    // 102
        float* l2bs = sm + 3570;    // 34
        float* gs   = sm + 3604;    // 34
        float* bts  = sm + 3638;    // 34
        for (int i = tid; i < 102 * Dm; i += NTHR) ws[i] = ipw2[i];
        if (tid < 102) ibs[tid] = ipb2[tid];
        if (tid < Dm) { l2bs[tid] = l2b[tid]; gs[tid] = g2[tid]; bts[tid] = b2[tid]; }
        __syncthreads();
        int row = b * NTHR + tid;
        if (row < S) {
            float y[Dm];
#pragma unroll
            for (int d = 0; d < Dm; d++) y[d] = g_x[row * Dm + d] + l2bs[d];
#pragma unroll
            for (int g = 0; g < NFSEG; g++) {
                const float* yp = g_yp + ((size_t)g * S + row) * Dm;
#pragma unroll
                for (int d = 0; d < Dm; d++) y[d] += yp[d];
            }
            float m = 0.f;
#pragma unroll
            for (int d = 0; d < Dm; d++) m += y[d];
            m *= (1.0f / Dm);
            float v = 0.f;
#pragma unroll
            for (int d = 0; d < Dm; d++) { float tt = y[d] - m; v = fmaf(tt, tt, v); }
            v *= (1.0f / Dm);
            float inv = rsqrtf(v + EPSV);
            float xr[Dm];
#pragma unroll
            for (int d = 0; d < Dm; d++) {
                xr[d] = (y[d] - m) * inv * gs[d] + bts[d];
                g_x[row * Dm + d] = xr[d];
            }
            const float scale = rsqrtf(17.f);
#pragma unroll 2
            for (int c = 0; c < 102; c++) {
                float acc = ibs[c];
                const float* wp = ws + c * Dm;
#pragma unroll
                for (int d = 0; d < Dm; d++) acc = fmaf(xr[d], wp[d], acc);
                int kind = c / Dm;
                int cc = c % Dm;
                int h = cc / HD, dd = cc % HD;
                int off = (h * S + row) * PH + dd;
                if (kind == 0)      g_q[off] = acc * scale;
                else if (kind == 1) g_k[off] = acc;
                else                g_v[off] = acc;
            }
        }
    }
    gsync(ls);  // 7

    // ---------------- P7: agent attention partials (148 units) ----------------
    {
        int h = b / NSEG2;
        int seg = b % NSEG2;
        int k0 = seg * KSEG2;
        int n = min(KSEG2, S - k0);
        float* Ks = sm;             // 89*20 -> pad to 1792
        float* Vs = sm + 1792;
        const float4* ksrc = (const float4*)(g_k + (h * S + k0) * PH);
        const float4* vsrc = (const float4*)(g_v + (h * S + k0) * PH);
        float4* kdst = (float4*)Ks; float4* vdst = (float4*)Vs;
        for (int i = tid; i < n * 5; i += NTHR) { kdst[i] = ksrc[i]; vdst[i] = vsrc[i]; }
        __syncthreads();
        if (tid < HW) {
            int start = g_agent * HW;
            u64 q[9], acc[9];
            const u64* qp = (const u64*)(g_q + (h * S + start + tid) * PH);
#pragma unroll
            for (int i = 0; i < 9; i++) { q[i] = qp[i]; acc[i] = 0ULL; }
            float ssum = 0.f;
            const ulonglong2* K2 = (const ulonglong2*)Ks;
            const ulonglong2* V2 = (const ulonglong2*)Vs;
            for (int kk = 0; kk < n; kk++) {
                ulonglong2 ka = K2[0], kb = K2[1], kc = K2[2], kd = K2[3];
                u64 ke = K2[4].x;
                u64 t0 = mul2(q[0], ka.x),  t1 = mul2(q[1], ka.y);
                t0 = fma2(q[2], kb.x, t0);  t1 = fma2(q[3], kb.y, t1);
                t0 = fma2(q[4], kc.x, t0);  t1 = fma2(q[5], kc.y, t1);
                t0 = fma2(q[6], kd.x, t0);  t1 = fma2(q[7], kd.y, t1);
                t0 = fma2(q[8], ke, t0);
                t0 = add2(t0, t1);
                float2 f = unpk(t0);
                float p = __expf(f.x + f.y);
                ssum += p;
                u64 pp = pk(p, p);
                ulonglong2 va = V2[0], vb = V2[1], vc = V2[2], vd = V2[3];
                u64 ve = V2[4].x;
                acc[0] = fma2(pp, va.x, acc[0]); acc[1] = fma2(pp, va.y, acc[1]);
                acc[2] = fma2(pp, vb.x, acc[2]); acc[3] = fma2(pp, vb.y, acc[3]);
                acc[4] = fma2(pp, vc.x, acc[4]); acc[5] = fma2(pp, vc.y, acc[5]);
                acc[6] = fma2(pp, vd.x, acc[6]); acc[7] = fma2(pp, vd.y, acc[7]);
                acc[8] = fma2(pp, ve, acc[8]);
                K2 += 5; V2 += 5;
            }
            u64* pa = (u64*)(g_pacca + ((h * NSEG2 + seg) * HW + tid) * PAC);
#pragma unroll
            for (int i = 0; i < 9; i++) pa[i] = acc[i];
            g_psuma[(h * NSEG2 + seg) * HW + tid] = ssum;
        }
    }
    gsync(ls);  // 8

    // ---------------- P8: agent reduce + out_proj + LN -> g_xa (block 0) ----------------
    if (b == 0) {
        const float* opw2 = opw + Dm * Dm;
        const float* opb2 = opb + Dm;
        const float* g12 = g1 + Dm;
        const float* b12 = b1 + Dm;
        float* os  = sm;            // 2754
        float* ws  = sm + 2754;     // 1156
        float* obs_ = sm + 3910;    // 34
        float* gs  = sm + 3944;     // 34
        float* bts = sm + 3978;     // 34
        for (int e = tid; e < HW * Dm; e += NTHR) {
            int r = e / Dm, c = e % Dm;
            int h = c / HD, d = c % HD;
            float a = 0.f, smm = 0.f;
            for (int g = 0; g < NSEG2; g++) {
                a   += g_pacca[((h * NSEG2 + g) * HW + r) * PAC + d];
                smm += g_psuma[(h * NSEG2 + g) * HW + r];
            }
            os[e] = a / smm;
        }
        for (int i = tid; i < Dm * Dm; i += NTHR) ws[i] = opw2[i];
        if (tid < Dm) { obs_[tid] = opb2[tid]; gs[tid] = g12[tid]; bts[tid] = b12[tid]; }
        __syncthreads();
        if (tid < HW) {
            int s = g_agent * HW + tid;
            float orow[Dm], y[Dm];
#pragma unroll
            for (int d = 0; d < Dm; d++) orow[d] = os[tid * Dm + d];
#pragma unroll 2
            for (int d = 0; d < Dm; d++) {
                float a = obs_[d] + g_x[s * Dm + d];
                const float* wp = ws + d * Dm;
#pragma unroll
                for (int k = 0; k < Dm; k++) a = fmaf(orow[k], wp[k], a);
                y[d] = a;
            }
            float m = 0.f;
#pragma unroll
            for (int d = 0; d < Dm; d++) m += y[d];
            m *= (1.0f / Dm);
            float v = 0.f;
#pragma unroll
            for (int d = 0; d < Dm; d++) { float tt = y[d] - m; v = fmaf(tt, tt, v); }
            v *= (1.0f / Dm);
            float inv = rsqrtf(v + EPSV);
#pragma unroll
            for (int d = 0; d < Dm; d++) g_xa[tid * Dm + d] = (y[d] - m) * inv * gs[d] + bts[d];
        }
    }
    gsync(ls);  // 9

    // ---------------- P9: agent FFN partials (32 blocks) ----------------
    if (b < NFSEG2) {
        const float* l1w2 = l1w + FFd * Dm;
        const float* l1b2 = l1b + FFd;
        const float* l2w2 = l2w + Dm * FFd;
        float* W1s = sm;            // 64*36
        float* W2s = sm + 2304;     // 64*36
        float* b1s = sm + 4608;     // 64
        int fbase = b * FSEG2;
        for (int e = tid; e < FSEG2 * Dm; e += NTHR) {
            int f = e / Dm, d = e % Dm;
            W1s[f * 36 + d] = l1w2[(fbase + f) * Dm + d];
            W2s[f * 36 + d] = l2w2[d * FFd + fbase + f];
        }
        for (int e = tid; e < FSEG2; e += NTHR) b1s[e] = l1b2[fbase + e];
        __syncthreads();
        if (tid < HW) {
            u64 xr[17], y[17];
            const u64* p = (const u64*)(g_xa + tid * Dm);
#pragma unroll
            for (int i = 0; i < 17; i++) { xr[i] = p[i]; y[i] = 0ULL; }
#pragma unroll 2
            for (int f = 0; f < FSEG2; f++) {
                const ulonglong2* w2p = (const ulonglong2*)(W1s + f * 36);
                const u64*        w1p = (const u64*)(W1s + f * 36);
                ulonglong2 a0 = w2p[0], a1 = w2p[1], a2 = w2p[2], a3 = w2p[3];
                ulonglong2 a4 = w2p[4], a5 = w2p[5], a6 = w2p[6], a7 = w2p[7];
                u64 a16 = w1p[16];
                u64 t0 = mul2(xr[0], a0.x),  t1 = mul2(xr[1], a0.y);
                t0 = fma2(xr[2], a1.x, t0);  t1 = fma2(xr[3], a1.y, t1);
                t0 = fma2(xr[4], a2.x, t0);  t1 = fma2(xr[5], a2.y, t1);
                t0 = fma2(xr[6], a3.x, t0);  t1 = fma2(xr[7], a3.y, t1);
                t0 = fma2(xr[8], a4.x, t0);  t1 = fma2(xr[9], a4.y, t1);
                t0 = fma2(xr[10], a5.x, t0); t1 = fma2(xr[11], a5.y, t1);
                t0 = fma2(xr[12], a6.x, t0); t1 = fma2(xr[13], a6.y, t1);
                t0 = fma2(xr[14], a7.x, t0); t1 = fma2(xr[15], a7.y, t1);
                t0 = fma2(xr[16], a16, t0);
                t0 = add2(t0, t1);
                float2 fh = unpk(t0);
                float hrelu = fmaxf(fh.x + fh.y + b1s[f], 0.f);
                u64 hp = pk(hrelu, hrelu);
                const ulonglong2* v2p = (const ulonglong2*)(W2s + f * 36);
                const u64*        v1p = (const u64*)(W2s + f * 36);
                ulonglong2 b0 = v2p[0], b1v = v2p[1], b2v = v2p[2], b3 = v2p[3];
                ulonglong2 b4 = v2p[4], b5 = v2p[5], b6 = v2p[6], b7 = v2p[7];
                u64 b16 = v1p[16];
                y[0]  = fma2(hp, b0.x, y[0]);   y[1]  = fma2(hp, b0.y, y[1]);
                y[2]  = fma2(hp, b1v.x, y[2]);  y[3]  = fma2(hp, b1v.y, y[3]);
                y[4]  = fma2(hp, b2v.x, y[4]);  y[5]  = fma2(hp, b2v.y, y[5]);
                y[6]  = fma2(hp, b3.x, y[6]);   y[7]  = fma2(hp, b3.y, y[7]);
                y[8]  = fma2(hp, b4.x, y[8]);   y[9]  = fma2(hp, b4.y, y[9]);
                y[10] = fma2(hp, b5.x, y[10]);  y[11] = fma2(hp, b5.y, y[11]);
                y[12] = fma2(hp, b6.x, y[12]);  y[13] = fma2(hp, b6.y, y[13]);
                y[14] = fma2(hp, b7.x, y[14]);  y[15] = fma2(hp, b7.y, y[15]);
                y[16] = fma2(hp, b16, y[16]);
            }
            u64* yo = (u64*)(g_ypa + ((size_t)b * HW + tid) * Dm);
#pragma unroll
            for (int i = 0; i < 17; i++) yo[i] = y[i];
        }
    }
    gsync(ls);  // 10 (even -> sense returns to 0)

    // ---------------- P10: agent FFN reduce + LN + mean -> out (block 0) ----------------
    if (b == 0) {
        const float* l2b2 = l2b + Dm;
        const float* g22 = g2 + Dm;
        const float* b22 = b2 + Dm;
        float* rows = sm;           // 2754
        if (tid < HW) {
            float y[Dm];
#pragma unroll
            for (int d = 0; d < Dm; d++) y[d] = g_xa[tid * Dm + d] + l2b2[d];
            for (int g = 0; g < NFSEG2; g++) {
                const float* yp = g_ypa + ((size_t)g * HW + tid) * Dm;
#pragma unroll
                for (int d = 0; d < Dm; d++) y[d] += yp[d];
            }
            float m = 0.f;
#pragma unroll
            for (int d = 0; d < Dm; d++) m += y[d];
            m *= (1.0f / Dm);
            float v = 0.f;
#pragma unroll
            for (int d = 0; d < Dm; d++) { float tt = y[d] - m; v = fmaf(tt, tt, v); }
            v *= (1.0f / Dm);
            float inv = rsqrtf(v + EPSV);
#pragma unroll
            for (int d = 0; d < Dm; d++) rows[tid * Dm + d] = (y[d] - m) * inv * g22[d] + b22[d];
        }
        __syncthreads();
        if (tid < Dm) {
            float s = 0.f;
            for (int r = 0; r < HW; r++) s += rows[r * Dm + tid];
            out[tid] = s * (1.0f / 81.0f);
        }
    }
}

// ---------------------------------------------------------------------------
extern "C" void kernel_launch(void* const* d_in, const int* in_sizes, int n_in,
                              void* d_out, int out_size) {
    const float* obs = (const float*)d_in[0];
    const float* c1w = (const float*)d_in[1];
    const float* c1b = (const float*)d_in[2];
    const float* c2w = (const float*)d_in[3];
    const float* c2b = (const float*)d_in[4];
    const float* ipw = (const float*)d_in[5];
    const float* ipb = (const float*)d_in[6];
    const float* opw = (const float*)d_in[7];
    const float* opb = (const float*)d_in[8];
    const float* l1w = (const float*)d_in[9];
    const float* l1b = (const float*)d_in[10];
    const float* l2w = (const float*)d_in[11];
    const float* l2b = (const float*)d_in[12];
    const float* g1  = (const float*)d_in[13];
    const float* b1  = (const float*)d_in[14];
    const float* g2  = (const float*)d_in[15];
    const float* b2  = (const float*)d_in[16];
    float* out = (float*)d_out;

    mega<<<GRID, NTHR>>>(obs, c1w, c1b, c2w, c2b, ipw, ipb, opw, opb,
                         l1w, l1b, l2w, l2b, g1, b1, g2, b2, out);
}

// round 7
// speedup vs baseline: 3.0742x; 1.0387x over previous
#include <cuda_runtime.h>

#define S      6561
#define Dm     34
#define HD     17
#define PH     20
#define PAC    18
#define FFd    2048
#define NH     2
#define HW     81
#define EPSV   1e-5f
#define ESTR   (NH * HW * HW)
// layer-0 FFN tiling
#define NFSEG  8
#define FSEG   256
#define FCHK0  64
// layer-1 agent attention
#define NSEG2  127
#define KSEG2  52
// agent FFN split
#define NFSEG2 32
#define FSEG2  64

typedef unsigned long long u64;

// ---- packed fp32 helpers ----
__device__ __forceinline__ u64 fma2(u64 a, u64 b, u64 c) {
    u64 d; asm("fma.rn.f32x2 %0, %1, %2, %3;" : "=l"(d) : "l"(a), "l"(b), "l"(c)); return d;
}
__device__ __forceinline__ u64 mul2(u64 a, u64 b) {
    u64 d; asm("mul.rn.f32x2 %0, %1, %2;" : "=l"(d) : "l"(a), "l"(b)); return d;
}
__device__ __forceinline__ u64 add2(u64 a, u64 b) {
    u64 d; asm("add.rn.f32x2 %0, %1, %2;" : "=l"(d) : "l"(a), "l"(b)); return d;
}
__device__ __forceinline__ float2 unpk(u64 v) {
    float2 f; asm("mov.b64 {%0, %1}, %2;" : "=f"(f.x), "=f"(f.y) : "l"(v)); return f;
}
__device__ __forceinline__ u64 pk(float x, float y) {
    u64 v; asm("mov.b64 %0, {%1, %2};" : "=l"(v) : "f"(x), "f"(y)); return v;
}

// ---- device-global scratch ----
__device__ int   g_agent;
__device__ __align__(16) float g_emb[HW * 16];
__device__ __align__(16) float g_x[S * Dm];
__device__ __align__(16) float g_q[NH * S * PH];
__device__ __align__(16) float g_k[NH * S * PH];
__device__ __align__(16) float g_v[NH * S * PH];
__device__ __align__(16) float g_o[S * Dm];
__device__ __align__(16) float g_yp[NFSEG * S * Dm];
__device__ __align__(16) float g_QA[NH * HW * HD];
__device__ __align__(16) float g_QB[NH * HW * HD];
__device__ __align__(16) float g_KA[NH * HW * HD];
__device__ __align__(16) float g_KB[NH * HW * HD];
__device__ __align__(16) float g_VA[NH * HW * HD];
__device__ __align__(16) float g_VB[NH * HW * HD];
__device__ __align__(16) float g_E[4 * ESTR];
__device__ __align__(16) float g_pacca[NH * NSEG2 * HW * PAC];
__device__ float g_psuma[NH * NSEG2 * HW];
__device__ __align__(16) float g_xa[HW * Dm];
__device__ __align__(16) float g_ypa[NFSEG2 * HW * Dm];

// ---------------------------------------------------------------------------
// K1: convs + argmax
// ---------------------------------------------------------------------------
__global__ void conv_prep(const float* __restrict__ obs,
                          const float* __restrict__ w1, const float* __restrict__ b1,
                          const float* __restrict__ w2, const float* __restrict__ b2) {
    __shared__ float so[2 * 81];
    __shared__ float c1[16 * 81];
    int tid = threadIdx.x;
    for (int i = tid; i < 162; i += blockDim.x) so[i] = obs[i];
    __syncthreads();
    if (tid == 0) {
        float mx = so[0]; int mi = 0;
        for (int i = 1; i < 81; i++) if (so[i] > mx) { mx = so[i]; mi = i; }
        g_agent = mi;
    }
    for (int idx = tid; idx < 16 * 81; idx += blockDim.x) {
        int ch = idx / 81, pos = idx % 81, r = pos / 9, c = pos % 9;
        float acc = b1[ch];
        for (int ci = 0; ci < 2; ci++)
            for (int dr = 0; dr < 3; dr++) {
                int rr = r + dr - 1; if (rr < 0 || rr >= 9) continue;
                for (int dc = 0; dc < 3; dc++) {
                    int cc = c + dc - 1; if (cc < 0 || cc >= 9) continue;
                    acc += so[ci * 81 + rr * 9 + cc] * w1[((ch * 2 + ci) * 3 + dr) * 3 + dc];
                }
            }
        c1[idx] = fmaxf(acc, 0.f);
    }
    __syncthreads();
    for (int idx = tid; idx < 16 * 81; idx += blockDim.x) {
        int ch = idx / 81, pos = idx % 81, r = pos / 9, c = pos % 9;
        float acc = b2[ch];
        for (int ci = 0; ci < 16; ci++)
            for (int dr = 0; dr < 3; dr++) {
                int rr = r + dr - 1; if (rr < 0 || rr >= 9) continue;
                for (int dc = 0; dc < 3; dc++) {
                    int cc = c + dc - 1; if (cc < 0 || cc >= 9) continue;
                    acc += c1[ci * 81 + rr * 9 + cc] * w2[((ch * 16 + ci) * 3 + dr) * 3 + dc];
                }
            }
        g_emb[pos * 16 + ch] = fmaxf(acc, 0.f);
    }
}

// ---------------------------------------------------------------------------
// K2: layer-0 basis QKV
// ---------------------------------------------------------------------------
__global__ void basis_qkv(const float* __restrict__ ipw, const float* __restrict__ ipb) {
    int idx = blockIdx.x * blockDim.x + threadIdx.x;
    if (idx >= 162 * 102) return;
    int v = idx / 102, c = idx % 102;
    const float* wr = ipw + c * Dm;
    float acc;
    if (v < 81) {
        int i = v;
        acc = ipb[c];
#pragma unroll
        for (int d = 0; d < 16; d++) acc = fmaf(g_emb[i * 16 + d], wr[d], acc);
        acc = fmaf((float)(i / 9) * 0.25f, wr[32], acc);
        acc = fmaf((float)(i % 9) * 0.25f, wr[33], acc);
    } else {
        int j = v - 81;
        acc = 0.f;
#pragma unroll
        for (int d = 0; d < 16; d++) acc = fmaf(g_emb[j * 16 + d], wr[16 + d], acc);
        acc = fmaf(-(float)(j / 9) * 0.25f, wr[32], acc);
        acc = fmaf(-(float)(j % 9) * 0.25f, wr[33], acc);
    }
    int kind = c / Dm;
    int cc = c % Dm;
    int h = cc / HD, dd = cc % HD;
    int off = (h * HW + (v % 81)) * HD + dd;
    if (kind == 0) {
        float sv = acc * rsqrtf(17.f);
        if (v < 81) g_QA[off] = sv; else g_QB[off] = sv;
    } else if (kind == 1) {
        if (v < 81) g_KA[off] = acc; else g_KB[off] = acc;
    } else {
        if (v < 81) g_VA[off] = acc; else g_VB[off] = acc;
    }
}

// ---------------------------------------------------------------------------
// K3: exp(logit) matrices
// ---------------------------------------------------------------------------
__global__ void logits_exp() {
    int idx = blockIdx.x * blockDim.x + threadIdx.x;
    if (idx >= 4 * ESTR) return;
    int p = idx / ESTR;
    int r = idx % ESTR;
    int h = r / (HW * HW);
    int q2 = r % (HW * HW);
    int i = q2 / HW, m = q2 % HW;
    const float* L = ((p < 2) ? g_QA : g_QB) + (h * HW + i) * HD;
    const float* R = ((p & 1) ? g_KB : g_KA) + (h * HW + m) * HD;
    float dot = 0.f;
#pragma unroll
    for (int d = 0; d < HD; d++) dot = fmaf(L[d], R[d], dot);
    g_E[idx] = __expf(dot);
}

// ---------------------------------------------------------------------------
// K4: structured attention -> g_o
// ---------------------------------------------------------------------------
__global__ void __launch_bounds__(128) attn_struct() {
    __shared__ float sea[HW], seb[HW];
    __shared__ __align__(16) float sva[HW * 18];
    __shared__ __align__(16) float svb[HW * 18];
    int tid = threadIdx.x;
    int i = blockIdx.x, h = blockIdx.y;
    for (int t = tid; t < HW; t += 128) {
        sea[t] = g_E[0 * ESTR + (h * HW + i) * HW + t];
        seb[t] = g_E[1 * ESTR + (h * HW + i) * HW + t];
    }
    for (int t = tid; t < HW * 18; t += 128) {
        int m = t / 18, d = t % 18;
        sva[t] = (d < HD) ? g_VA[(h * HW + m) * HD + d] : 0.f;
        svb[t] = (d < HD) ? g_VB[(h * HW + m) * HD + d] : 0.f;
    }
    __syncthreads();
    int j = tid;
    if (j >= HW) return;
    const float* ecr = g_E + 2 * ESTR + (h * HW + j) * HW;
    const float* edr = g_E + 3 * ESTR + (h * HW + j) * HW;
    float zm = 0.f, zn = 0.f;
    u64 wa[9], wb[9];
#pragma unroll
    for (int k = 0; k < 9; k++) { wa[k] = 0ULL; wb[k] = 0ULL; }
    for (int m = 0; m < HW; m++) {
        float f = sea[m] * ecr[m];
        zm += f;
        u64 fp = pk(f, f);
        const u64* vr = (const u64*)(sva + m * 18);
#pragma unroll
        for (int k = 0; k < 9; k++) wa[k] = fma2(fp, vr[k], wa[k]);
    }
    for (int n = 0; n < HW; n++) {
        float g = seb[n] * edr[n];
        zn += g;
        u64 gp = pk(g, g);
        const u64* vr = (const u64*)(svb + n * 18);
#pragma unroll
        for (int k = 0; k < 9; k++) wb[k] = fma2(gp, vr[k], wb[k]);
    }
    float inv = 1.0f / (zm * zn);
    float* od = g_o + (i * HW + j) * Dm + h * HD;
#pragma unroll
    for (int k = 0; k < 9; k++) {
        float2 A = unpk(wa[k]), B = unpk(wb[k]);
        int d = 2 * k;
        od[d] = (A.x * zn + B.x * zm) * inv;
        if (d + 1 < HD) od[d + 1] = (A.y * zn + B.y * zm) * inv;
    }
}

// ---------------------------------------------------------------------------
// K5: tokens (inline) + out_proj + residual + LN1 -> g_x
// ---------------------------------------------------------------------------
__global__ void __launch_bounds__(128) tokens_proj_ln(const float* __restrict__ opw,
                                                      const float* __restrict__ opb,
                                                      const float* __restrict__ gg,
                                                      const float* __restrict__ bb) {
    __shared__ float embs[1296];
    __shared__ float ws[Dm * Dm];
    __shared__ float bs[Dm], gs[Dm], bts[Dm];
    int tid = threadIdx.x;
    for (int i = tid; i < 1296; i += 128) embs[i] = g_emb[i];
    for (int i = tid; i < Dm * Dm; i += 128) ws[i] = opw[i];
    if (tid < Dm) { bs[tid] = opb[tid]; gs[tid] = gg[tid]; bts[tid] = bb[tid]; }
    __syncthreads();
    int t = blockIdx.x * 128 + tid;
    if (t >= S) return;
    int i = t / HW, j = t % HW;
    float x[Dm], orow[Dm], y[Dm];
#pragma unroll
    for (int d = 0; d < 16; d++) x[d] = embs[i * 16 + d];
#pragma unroll
    for (int d = 0; d < 16; d++) x[16 + d] = embs[j * 16 + d];
    x[32] = ((float)(i / 9) - (float)(j / 9)) * 0.25f;
    x[33] = ((float)(i % 9) - (float)(j % 9)) * 0.25f;
#pragma unroll
    for (int d = 0; d < Dm; d++) orow[d] = g_o[t * Dm + d];
#pragma unroll 2
    for (int d = 0; d < Dm; d++) {
        float a = bs[d] + x[d];
        const float* wp = ws + d * Dm;
#pragma unroll
        for (int k = 0; k < Dm; k++) a = fmaf(orow[k], wp[k], a);
        y[d] = a;
    }
    float m = 0.f;
#pragma unroll
    for (int d = 0; d < Dm; d++) m += y[d];
    m *= (1.0f / Dm);
    float v = 0.f;
#pragma unroll
    for (int d = 0; d < Dm; d++) { float tt = y[d] - m; v = fmaf(tt, tt, v); }
    v *= (1.0f / Dm);
    float inv = rsqrtf(v + EPSV);
#pragma unroll
    for (int d = 0; d < Dm; d++) g_x[t * Dm + d] = (y[d] - m) * inv * gs[d] + bts[d];
}

// ---------------------------------------------------------------------------
// K6: layer-0 FFN partials — occupancy-tuned: 1 row/thread, 3 blocks/SM,
// FCHK0=64 weight chunks. grid (52, 1, 8) x 128 threads.
// ---------------------------------------------------------------------------
__global__ void __launch_bounds__(128, 3) ffn0(const float* __restrict__ l1w,
                                               const float* __restrict__ l1b,
                                               const float* __restrict__ l2w) {
    __shared__ __align__(16) float W1s[FCHK0 * 36];
    __shared__ __align__(16) float W2s[FCHK0 * 36];
    __shared__ float b1s[FCHK0];
    int tid = threadIdx.x;
    int row = blockIdx.x * 128 + tid;
    int fbase = blockIdx.z * FSEG;
    bool act = row < S;
    u64 xr[17], y[17];
#pragma unroll
    for (int i = 0; i < 17; i++) { xr[i] = 0ULL; y[i] = 0ULL; }
    if (act) {
        const u64* p = (const u64*)(g_x + row * Dm);
#pragma unroll
        for (int i = 0; i < 17; i++) xr[i] = p[i];
    }
    for (int fc = fbase; fc < fbase + FSEG; fc += FCHK0) {
        for (int e = tid; e < FCHK0 * Dm; e += 128) {
            int f = e / Dm, d = e % Dm;
            W1s[f * 36 + d] = l1w[(fc + f) * Dm + d];
            W2s[f * 36 + d] = l2w[d * FFd + fc + f];
        }
        if (tid < FCHK0) b1s[tid] = l1b[fc + tid];
        __syncthreads();
#pragma unroll 2
        for (int f = 0; f < FCHK0; f++) {
            const ulonglong2* w2p = (const ulonglong2*)(W1s + f * 36);
            const u64*        w1p = (const u64*)(W1s + f * 36);
            ulonglong2 a0 = w2p[0], a1 = w2p[1], a2 = w2p[2], a3 = w2p[3];
            ulonglong2 a4 = w2p[4], a5 = w2p[5], a6 = w2p[6], a7 = w2p[7];
            u64 a16 = w1p[16];
            u64 t0 = mul2(xr[0], a0.x),  t1 = mul2(xr[1], a0.y);
            t0 = fma2(xr[2], a1.x, t0);  t1 = fma2(xr[3], a1.y, t1);
            t0 = fma2(xr[4], a2.x, t0);  t1 = fma2(xr[5], a2.y, t1);
            t0 = fma2(xr[6], a3.x, t0);  t1 = fma2(xr[7], a3.y, t1);
            t0 = fma2(xr[8], a4.x, t0);  t1 = fma2(xr[9], a4.y, t1);
            t0 = fma2(xr[10], a5.x, t0); t1 = fma2(xr[11], a5.y, t1);
            t0 = fma2(xr[12], a6.x, t0); t1 = fma2(xr[13], a6.y, t1);
            t0 = fma2(xr[14], a7.x, t0); t1 = fma2(xr[15], a7.y, t1);
            t0 = fma2(xr[16], a16, t0);
            t0 = add2(t0, t1);
            float2 fh = unpk(t0);
            float hrelu = fmaxf(fh.x + fh.y + b1s[f], 0.f);
            u64 hp = pk(hrelu, hrelu);
            const ulonglong2* v2p = (const ulonglong2*)(W2s + f * 36);
            const u64*        v1p = (const u64*)(W2s + f * 36);
            ulonglong2 b0 = v2p[0], b1v = v2p[1], b2v = v2p[2], b3 = v2p[3];
            ulonglong2 b4 = v2p[4], b5 = v2p[5], b6 = v2p[6], b7 = v2p[7];
            u64 b16 = v1p[16];
            y[0]  = fma2(hp, b0.x, y[0]);   y[1]  = fma2(hp, b0.y, y[1]);
            y[2]  = fma2(hp, b1v.x, y[2]);  y[3]  = fma2(hp, b1v.y, y[3]);
            y[4]  = fma2(hp, b2v.x, y[4]);  y[5]  = fma2(hp, b2v.y, y[5]);
            y[6]  = fma2(hp, b3.x, y[6]);   y[7]  = fma2(hp, b3.y, y[7]);
            y[8]  = fma2(hp, b4.x, y[8]);   y[9]  = fma2(hp, b4.y, y[9]);
            y[10] = fma2(hp, b5.x, y[10]);  y[11] = fma2(hp, b5.y, y[11]);
            y[12] = fma2(hp, b6.x, y[12]);  y[13] = fma2(hp, b6.y, y[13]);
            y[14] = fma2(hp, b7.x, y[14]);  y[15] = fma2(hp, b7.y, y[15]);
            y[16] = fma2(hp, b16, y[16]);
        }
        __syncthreads();
    }
    if (act) {
        u64* yo = (u64*)(g_yp + ((size_t)blockIdx.z * S + row) * Dm);
#pragma unroll
        for (int i = 0; i < 17; i++) yo[i] = y[i];
    }
}

// ---------------------------------------------------------------------------
// K7: FFN reduce + LN2 + layer-1 QKV fused. grid 206 x 256 thr, 32 rows/block.
// ---------------------------------------------------------------------------
__global__ void __launch_bounds__(256) ffnred_qkv(const float* __restrict__ ipw2,
                                                  const float* __restrict__ ipb2,
                                                  const float* __restrict__ l2b,
                                                  const float* __restrict__ gg,
                                                  const float* __restrict__ bb) {
    __shared__ float xs[Dm * 32];      // transposed post-LN rows
    __shared__ float ws[102 * Dm];
    __shared__ float bs[102];
    __shared__ __align__(16) float pre[32 * 36];
    __shared__ float l2bs[Dm], gs[Dm], bts[Dm];
    int tid = threadIdx.x;
    int row0 = blockIdx.x * 32;
    for (int i = tid; i < 102 * Dm; i += 256) ws[i] = ipw2[i];
    if (tid < 102) bs[tid] = ipb2[tid];
    if (tid < Dm) { l2bs[tid] = l2b[tid]; gs[tid] = gg[tid]; bts[tid] = bb[tid]; }
    // cooperative segment reduce: 32 rows x 17 u64
    for (int e = tid; e < 32 * 17; e += 256) {
        int r = e / 17, k = e % 17;
        int row = row0 + r;
        if (row < S) {
            u64 acc = ((const u64*)(g_x + row * Dm))[k];
#pragma unroll
            for (int g = 0; g < NFSEG; g++)
                acc = add2(acc, ((const u64*)(g_yp + ((size_t)g * S + row) * Dm))[k]);
            ((u64*)(pre + r * 36))[k] = acc;
        }
    }
    __syncthreads();
    // LN per row (threads 0..31), write transposed xs + g_x
    if (tid < 32 && row0 + tid < S) {
        float y[Dm];
#pragma unroll
        for (int d = 0; d < Dm; d++) y[d] = pre[tid * 36 + d] + l2bs[d];
        float m = 0.f;
#pragma unroll
        for (int d = 0; d < Dm; d++) m += y[d];
        m *= (1.0f / Dm);
        float v = 0.f;
#pragma unroll
        for (int d = 0; d < Dm; d++) { float tt = y[d] - m; v = fmaf(tt, tt, v); }
        v *= (1.0f / Dm);
        float inv = rsqrtf(v + EPSV);
        int row = row0 + tid;
#pragma unroll
        for (int d = 0; d < Dm; d++) {
            float xv = (y[d] - m) * inv * gs[d] + bts[d];
            xs[d * 32 + tid] = xv;
            g_x[row * Dm + d] = xv;
        }
    }
    __syncthreads();
    // QKV: warp-per-column
    const float scale = rsqrtf(17.f);
    int lane = tid & 31, w = tid >> 5;
    int s = row0 + lane;
    for (int cc = w; cc < 102; cc += 8) {
        float acc = bs[cc];
        const float* wp = ws + cc * Dm;
#pragma unroll
        for (int d = 0; d < Dm; d++) acc = fmaf(xs[d * 32 + lane], wp[d], acc);
        if (s < S) {
            int kind = cc / Dm;
            int c2 = cc % Dm;
            int h = c2 / HD, dd = c2 % HD;
            int off = (h * S + s) * PH + dd;
            if (kind == 0)      g_q[off] = acc * scale;
            else if (kind == 1) g_k[off] = acc;
            else                g_v[off] = acc;
        }
    }
}

// ---------------------------------------------------------------------------
// K8: agent attention partials: 81 queries, keys split 127 ways
// ---------------------------------------------------------------------------
__global__ void __launch_bounds__(128) attn_agent() {
    __shared__ __align__(16) float Ks[KSEG2 * PH];
    __shared__ __align__(16) float Vs[KSEG2 * PH];
    int tid = threadIdx.x;
    int seg = blockIdx.x, h = blockIdx.y;
    int k0 = seg * KSEG2;
    int n = min(KSEG2, S - k0);
    int start = g_agent * HW;

    const float4* ksrc = (const float4*)(g_k + (h * S + k0) * PH);
    const float4* vsrc = (const float4*)(g_v + (h * S + k0) * PH);
    float4* kdst = (float4*)Ks; float4* vdst = (float4*)Vs;
    for (int i = tid; i < n * 5; i += 128) { kdst[i] = ksrc[i]; vdst[i] = vsrc[i]; }
    __syncthreads();

    if (tid >= HW) return;
    u64 q[9], acc[9];
    const u64* qp = (const u64*)(g_q + (h * S + start + tid) * PH);
#pragma unroll
    for (int i = 0; i < 9; i++) { q[i] = qp[i]; acc[i] = 0ULL; }
    float ssum = 0.f;
    const ulonglong2* K2 = (const ulonglong2*)Ks;
    const ulonglong2* V2 = (const ulonglong2*)Vs;
    for (int kk = 0; kk < n; kk++) {
        ulonglong2 ka = K2[0], kb = K2[1], kc = K2[2], kd = K2[3];
        u64 ke = K2[4].x;
        u64 t0 = mul2(q[0], ka.x),  t1 = mul2(q[1], ka.y);
        t0 = fma2(q[2], kb.x, t0);  t1 = fma2(q[3], kb.y, t1);
        t0 = fma2(q[4], kc.x, t0);  t1 = fma2(q[5], kc.y, t1);
        t0 = fma2(q[6], kd.x, t0);  t1 = fma2(q[7], kd.y, t1);
        t0 = fma2(q[8], ke, t0);
        t0 = add2(t0, t1);
        float2 f = unpk(t0);
        float p = __expf(f.x + f.y);
        ssum += p;
        u64 pp = pk(p, p);
        ulonglong2 va = V2[0], vb = V2[1], vc = V2[2], vd = V2[3];
        u64 ve = V2[4].x;
        acc[0] = fma2(pp, va.x, acc[0]); acc[1] = fma2(pp, va.y, acc[1]);
        acc[2] = fma2(pp, vb.x, acc[2]); acc[3] = fma2(pp, vb.y, acc[3]);
        acc[4] = fma2(pp, vc.x, acc[4]); acc[5] = fma2(pp, vc.y, acc[5]);
        acc[6] = fma2(pp, vd.x, acc[6]); acc[7] = fma2(pp, vd.y, acc[7]);
        acc[8] = fma2(pp, ve, acc[8]);
        K2 += 5; V2 += 5;
    }
    u64* pa = (u64*)(g_pacca + ((h * NSEG2 + seg) * HW + tid) * PAC);
#pragma unroll
    for (int i = 0; i < 9; i++) pa[i] = acc[i];
    g_psuma[(h * NSEG2 + seg) * HW + tid] = ssum;
}

// ---------------------------------------------------------------------------
// K9: combine agent attention segments -> g_xa staging (reuse g_o front)
// ---------------------------------------------------------------------------
__device__ __align__(16) float g_oa[HW * Dm];
__global__ void attn_reduce_agent() {
    int e = blockIdx.x * blockDim.x + threadIdx.x;
    if (e >= HW * Dm) return;
    int r = e / Dm, c = e % Dm;
    int h = c / HD, d = c % HD;
    float a = 0.f, sm = 0.f;
    for (int g = 0; g < NSEG2; g++) {
        a  += g_pacca[((h * NSEG2 + g) * HW + r) * PAC + d];
        sm += g_psuma[(h * NSEG2 + g) * HW + r];
    }
    g_oa[r * Dm + c] = a / sm;
}

// ---------------------------------------------------------------------------
// K10: agent out_proj + residual + LN -> g_xa
// ---------------------------------------------------------------------------
__global__ void __launch_bounds__(128) proj_ln_agent(const float* __restrict__ opw,
                                                     const float* __restrict__ opb,
                                                     const float* __restrict__ gg,
                                                     const float* __restrict__ bb) {
    __shared__ float ws[Dm * Dm];
    __shared__ float bs[Dm], gs[Dm], bts[Dm];
    int tid = threadIdx.x;
    for (int i = tid; i < Dm * Dm; i += blockDim.x) ws[i] = opw[i];
    if (tid < Dm) { bs[tid] = opb[tid]; gs[tid] = gg[tid]; bts[tid] = bb[tid]; }
    __syncthreads();
    if (tid >= HW) return;
    int s = g_agent * HW + tid;
    float orow[Dm], y[Dm];
#pragma unroll
    for (int d = 0; d < Dm; d++) orow[d] = g_oa[tid * Dm + d];
#pragma unroll 2
    for (int d = 0; d < Dm; d++) {
        float a = bs[d] + g_x[s * Dm + d];
        const float* wp = ws + d * Dm;
#pragma unroll
        for (int k = 0; k < Dm; k++) a = fmaf(orow[k], wp[k], a);
        y[d] = a;
    }
    float m = 0.f;
#pragma unroll
    for (int d = 0; d < Dm; d++) m += y[d];
    m *= (1.0f / Dm);
    float v = 0.f;
#pragma unroll
    for (int d = 0; d < Dm; d++) { float t = y[d] - m; v = fmaf(t, t, v); }
    v *= (1.0f / Dm);
    float inv = rsqrtf(v + EPSV);
#pragma unroll
    for (int d = 0; d < Dm; d++) g_xa[tid * Dm + d] = (y[d] - m) * inv * gs[d] + bts[d];
}

// ---------------------------------------------------------------------------
// K11: agent FFN partials
// ---------------------------------------------------------------------------
__global__ void __launch_bounds__(128) ffn_agent(const float* __restrict__ l1w,
                                                 const float* __restrict__ l1b,
                                                 const float* __restrict__ l2w) {
    __shared__ __align__(16) float W1s[FSEG2 * 36];
    __shared__ __align__(16) float W2s[FSEG2 * 36];
    __shared__ float b1s[FSEG2];
    int tid = threadIdx.x;
    int fbase = blockIdx.x * FSEG2;
    for (int e = tid; e < FSEG2 * Dm; e += 128) {
        int f = e / Dm, d = e % Dm;
        W1s[f * 36 + d] = l1w[(fbase + f) * Dm + d];
        W2s[f * 36 + d] = l2w[d * FFd + fbase + f];
    }
    if (tid < FSEG2) b1s[tid] = l1b[fbase + tid];
    __syncthreads();
    if (tid >= HW) return;
    u64 xr[17], y[17];
    const u64* p = (const u64*)(g_xa + tid * Dm);
#pragma unroll
    for (int i = 0; i < 17; i++) { xr[i] = p[i]; y[i] = 0ULL; }
#pragma unroll 2
    for (int f = 0; f < FSEG2; f++) {
        const ulonglong2* w2p = (const ulonglong2*)(W1s + f * 36);
        const u64*        w1p = (const u64*)(W1s + f * 36);
        ulonglong2 a0 = w2p[0], a1 = w2p[1], a2 = w2p[2], a3 = w2p[3];
        ulonglong2 a4 = w2p[4], a5 = w2p[5], a6 = w2p[6], a7 = w2p[7];
        u64 a16 = w1p[16];
        u64 t0 = mul2(xr[0], a0.x),  t1 = mul2(xr[1], a0.y);
        t0 = fma2(xr[2], a1.x, t0);  t1 = fma2(xr[3], a1.y, t1);
        t0 = fma2(xr[4], a2.x, t0);  t1 = fma2(xr[5], a2.y, t1);
        t0 = fma2(xr[6], a3.x, t0);  t1 = fma2(xr[7], a3.y, t1);
        t0 = fma2(xr[8], a4.x, t0);  t1 = fma2(xr[9], a4.y, t1);
        t0 = fma2(xr[10], a5.x, t0); t1 = fma2(xr[11], a5.y, t1);
        t0 = fma2(xr[12], a6.x, t0); t1 = fma2(xr[13], a6.y, t1);
        t0 = fma2(xr[14], a7.x, t0); t1 = fma2(xr[15], a7.y, t1);
        t0 = fma2(xr[16], a16, t0);
        t0 = add2(t0, t1);
        float2 fh = unpk(t0);
        float hrelu = fmaxf(fh.x + fh.y + b1s[f], 0.f);
        u64 hp = pk(hrelu, hrelu);
        const ulonglong2* v2p = (const ulonglong2*)(W2s + f * 36);
        const u64*        v1p = (const u64*)(W2s + f * 36);
        ulonglong2 b0 = v2p[0], b1v = v2p[1], b2v = v2p[2], b3 = v2p[3];
        ulonglong2 b4 = v2p[4], b5 = v2p[5], b6 = v2p[6], b7 = v2p[7];
        u64 b16 = v1p[16];
        y[0]  = fma2(hp, b0.x, y[0]);   y[1]  = fma2(hp, b0.y, y[1]);
        y[2]  = fma2(hp, b1v.x, y[2]);  y[3]  = fma2(hp, b1v.y, y[3]);
        y[4]  = fma2(hp, b2v.x, y[4]);  y[5]  = fma2(hp, b2v.y, y[5]);
        y[6]  = fma2(hp, b3.x, y[6]);   y[7]  = fma2(hp, b3.y, y[7]);
        y[8]  = fma2(hp, b4.x, y[8]);   y[9]  = fma2(hp, b4.y, y[9]);
        y[10] = fma2(hp, b5.x, y[10]);  y[11] = fma2(hp, b5.y, y[11]);
        y[12] = fma2(hp, b6.x, y[12]);  y[13] = fma2(hp, b6.y, y[13]);
        y[14] = fma2(hp, b7.x, y[14]);  y[15] = fma2(hp, b7.y, y[15]);
        y[16] = fma2(hp, b16, y[16]);
    }
    u64* yo = (u64*)(g_ypa + ((size_t)blockIdx.x * HW + tid) * Dm);
#pragma unroll
    for (int i = 0; i < 17; i++) yo[i] = y[i];
}

// ---------------------------------------------------------------------------
// K12: agent FFN reduce + LN + final mean -> out
// ---------------------------------------------------------------------------
__global__ void __launch_bounds__(128) agent_final(const float* __restrict__ l2b,
                                                   const float* __restrict__ gg,
                                                   const float* __restrict__ bb,
                                                   float* __restrict__ out) {
    __shared__ float rows[HW * Dm];
    int tid = threadIdx.x;
    if (tid < HW) {
        float y[Dm];
#pragma unroll
        for (int d = 0; d < Dm; d++) y[d] = g_xa[tid * Dm + d] + l2b[d];
        for (int g = 0; g < NFSEG2; g++) {
            const float* yp = g_ypa + ((size_t)g * HW + tid) * Dm;
#pragma unroll
            for (int d = 0; d < Dm; d++) y[d] += yp[d];
        }
        float m = 0.f;
#pragma unroll
        for (int d = 0; d < Dm; d++) m += y[d];
        m *= (1.0f / Dm);
        float v = 0.f;
#pragma unroll
        for (int d = 0; d < Dm; d++) { float t = y[d] - m; v = fmaf(t, t, v); }
        v *= (1.0f / Dm);
        float inv = rsqrtf(v + EPSV);
#pragma unroll
        for (int d = 0; d < Dm; d++) rows[tid * Dm + d] = (y[d] - m) * inv * gg[d] + bb[d];
    }
    __syncthreads();
    if (tid < Dm) {
        float s = 0.f;
        for (int r = 0; r < HW; r++) s += rows[r * Dm + tid];
        out[tid] = s * (1.0f / 81.0f);
    }
}

// ---------------------------------------------------------------------------
extern "C" void kernel_launch(void* const* d_in, const int* in_sizes, int n_in,
                              void* d_out, int out_size) {
    const float* obs = (const float*)d_in[0];
    const float* c1w = (const float*)d_in[1];
    const float* c1b = (const float*)d_in[2];
    const float* c2w = (const float*)d_in[3];
    const float* c2b = (const float*)d_in[4];
    const float* ipw = (const float*)d_in[5];
    const float* ipb = (const float*)d_in[6];
    const float* opw = (const float*)d_in[7];
    const float* opb = (const float*)d_in[8];
    const float* l1w = (const float*)d_in[9];
    const float* l1b = (const float*)d_in[10];
    const float* l2w = (const float*)d_in[11];
    const float* l2b = (const float*)d_in[12];
    const float* g1  = (const float*)d_in[13];
    const float* b1  = (const float*)d_in[14];
    const float* g2  = (const float*)d_in[15];
    const float* b2  = (const float*)d_in[16];
    float* out = (float*)d_out;

    conv_prep<<<1, 128>>>(obs, c1w, c1b, c2w, c2b);

    // layer 0 (structured)
    basis_qkv<<<(162 * 102 + 127) / 128, 128>>>(ipw, ipb);
    logits_exp<<<(4 * ESTR + 127) / 128, 128>>>();
    attn_struct<<<dim3(HW, NH), 128>>>();
    tokens_proj_ln<<<(S + 127) / 128, 128>>>(opw, opb, g1, b1);
    ffn0<<<dim3((S + 127) / 128, 1, NFSEG), 128>>>(l1w, l1b, l2w);
    ffnred_qkv<<<(S + 31) / 32, 256>>>(ipw + 102 * Dm, ipb + 102, l2b, g2, b2);

    // layer 1 (agent-only)
    attn_agent<<<dim3(NSEG2, NH), 128>>>();
    attn_reduce_agent<<<(HW * Dm + 127) / 128, 128>>>();
    proj_ln_agent<<<1, 128>>>(opw + Dm * Dm, opb + Dm, g1 + Dm, b1 + Dm);
    ffn_agent<<<NFSEG2, 128>>>(l1w + FFd * Dm, l1b + FFd, l2w + Dm * FFd);
    agent_final<<<1, 128>>>(l2b + Dm, g2 + Dm, b2 + Dm, out);
}

// round 8
// speedup vs baseline: 3.2269x; 1.0496x over previous
#include <cuda_runtime.h>

#define S      6561
#define Dm     34
#define HD     17
#define PH     20
#define PAC    18
#define FFd    2048
#define NH     2
#define HW     81
#define EPSV   1e-5f
#define ESTR   (NH * HW * HW)
// layer-0 FFN tiling
#define NFSEG  8
#define FSEG   256
#define FCHK0  64
// layer-1 agent attention
#define NSEG2  127
#define KSEG2  52
// agent FFN split
#define NFSEG2 32
#define FSEG2  64

typedef unsigned long long u64;

// ---- packed fp32 helpers ----
__device__ __forceinline__ u64 fma2(u64 a, u64 b, u64 c) {
    u64 d; asm("fma.rn.f32x2 %0, %1, %2, %3;" : "=l"(d) : "l"(a), "l"(b), "l"(c)); return d;
}
__device__ __forceinline__ u64 mul2(u64 a, u64 b) {
    u64 d; asm("mul.rn.f32x2 %0, %1, %2;" : "=l"(d) : "l"(a), "l"(b)); return d;
}
__device__ __forceinline__ u64 add2(u64 a, u64 b) {
    u64 d; asm("add.rn.f32x2 %0, %1, %2;" : "=l"(d) : "l"(a), "l"(b)); return d;
}
__device__ __forceinline__ float2 unpk(u64 v) {
    float2 f; asm("mov.b64 {%0, %1}, %2;" : "=f"(f.x), "=f"(f.y) : "l"(v)); return f;
}
__device__ __forceinline__ u64 pk(float x, float y) {
    u64 v; asm("mov.b64 %0, {%1, %2};" : "=l"(v) : "f"(x), "f"(y)); return v;
}

// ---- device-global scratch ----
__device__ int   g_agent;
__device__ __align__(16) float g_emb[HW * 16];
__device__ __align__(16) float g_x[S * Dm];
__device__ __align__(16) float g_q[NH * S * PH];
__device__ __align__(16) float g_k[NH * S * PH];
__device__ __align__(16) float g_v[NH * S * PH];
__device__ __align__(16) float g_o[S * Dm];
__device__ __align__(16) float g_yp[NFSEG * S * Dm];
__device__ __align__(16) float g_QA[NH * HW * HD];
__device__ __align__(16) float g_QB[NH * HW * HD];
__device__ __align__(16) float g_KA[NH * HW * HD];
__device__ __align__(16) float g_KB[NH * HW * HD];
__device__ __align__(16) float g_VA[NH * HW * HD];
__device__ __align__(16) float g_VB[NH * HW * HD];
__device__ __align__(16) float g_E[4 * ESTR];
__device__ __align__(16) float g_pacca[NH * NSEG2 * HW * PAC];
__device__ float g_psuma[NH * NSEG2 * HW];
__device__ __align__(16) float g_xa[HW * Dm];
__device__ __align__(16) float g_ypa[NFSEG2 * HW * Dm];
__device__ __align__(16) float g_oa[HW * Dm];

// ---------------------------------------------------------------------------
// K1: convs + argmax
// ---------------------------------------------------------------------------
__global__ void conv_prep(const float* __restrict__ obs,
                          const float* __restrict__ w1, const float* __restrict__ b1,
                          const float* __restrict__ w2, const float* __restrict__ b2) {
    __shared__ float so[2 * 81];
    __shared__ float c1[16 * 81];
    int tid = threadIdx.x;
    for (int i = tid; i < 162; i += blockDim.x) so[i] = obs[i];
    __syncthreads();
    if (tid == 0) {
        float mx = so[0]; int mi = 0;
        for (int i = 1; i < 81; i++) if (so[i] > mx) { mx = so[i]; mi = i; }
        g_agent = mi;
    }
    for (int idx = tid; idx < 16 * 81; idx += blockDim.x) {
        int ch = idx / 81, pos = idx % 81, r = pos / 9, c = pos % 9;
        float acc = b1[ch];
        for (int ci = 0; ci < 2; ci++)
            for (int dr = 0; dr < 3; dr++) {
                int rr = r + dr - 1; if (rr < 0 || rr >= 9) continue;
                for (int dc = 0; dc < 3; dc++) {
                    int cc = c + dc - 1; if (cc < 0 || cc >= 9) continue;
                    acc += so[ci * 81 + rr * 9 + cc] * w1[((ch * 2 + ci) * 3 + dr) * 3 + dc];
                }
            }
        c1[idx] = fmaxf(acc, 0.f);
    }
    __syncthreads();
    for (int idx = tid; idx < 16 * 81; idx += blockDim.x) {
        int ch = idx / 81, pos = idx % 81, r = pos / 9, c = pos % 9;
        float acc = b2[ch];
        for (int ci = 0; ci < 16; ci++)
            for (int dr = 0; dr < 3; dr++) {
                int rr = r + dr - 1; if (rr < 0 || rr >= 9) continue;
                for (int dc = 0; dc < 3; dc++) {
                    int cc = c + dc - 1; if (cc < 0 || cc >= 9) continue;
                    acc += c1[ci * 81 + rr * 9 + cc] * w2[((ch * 16 + ci) * 3 + dr) * 3 + dc];
                }
            }
        g_emb[pos * 16 + ch] = fmaxf(acc, 0.f);
    }
}

// ---------------------------------------------------------------------------
// K2: layer-0 basis QKV
// ---------------------------------------------------------------------------
__global__ void basis_qkv(const float* __restrict__ ipw, const float* __restrict__ ipb) {
    int idx = blockIdx.x * blockDim.x + threadIdx.x;
    if (idx >= 162 * 102) return;
    int v = idx / 102, c = idx % 102;
    const float* wr = ipw + c * Dm;
    float acc;
    if (v < 81) {
        int i = v;
        acc = ipb[c];
#pragma unroll
        for (int d = 0; d < 16; d++) acc = fmaf(g_emb[i * 16 + d], wr[d], acc);
        acc = fmaf((float)(i / 9) * 0.25f, wr[32], acc);
        acc = fmaf((float)(i % 9) * 0.25f, wr[33], acc);
    } else {
        int j = v - 81;
        acc = 0.f;
#pragma unroll
        for (int d = 0; d < 16; d++) acc = fmaf(g_emb[j * 16 + d], wr[16 + d], acc);
        acc = fmaf(-(float)(j / 9) * 0.25f, wr[32], acc);
        acc = fmaf(-(float)(j % 9) * 0.25f, wr[33], acc);
    }
    int kind = c / Dm;
    int cc = c % Dm;
    int h = cc / HD, dd = cc % HD;
    int off = (h * HW + (v % 81)) * HD + dd;
    if (kind == 0) {
        float sv = acc * rsqrtf(17.f);
        if (v < 81) g_QA[off] = sv; else g_QB[off] = sv;
    } else if (kind == 1) {
        if (v < 81) g_KA[off] = acc; else g_KB[off] = acc;
    } else {
        if (v < 81) g_VA[off] = acc; else g_VB[off] = acc;
    }
}

// ---------------------------------------------------------------------------
// K3: exp(logit) matrices
// ---------------------------------------------------------------------------
__global__ void logits_exp() {
    int idx = blockIdx.x * blockDim.x + threadIdx.x;
    if (idx >= 4 * ESTR) return;
    int p = idx / ESTR;
    int r = idx % ESTR;
    int h = r / (HW * HW);
    int q2 = r % (HW * HW);
    int i = q2 / HW, m = q2 % HW;
    const float* L = ((p < 2) ? g_QA : g_QB) + (h * HW + i) * HD;
    const float* R = ((p & 1) ? g_KB : g_KA) + (h * HW + m) * HD;
    float dot = 0.f;
#pragma unroll
    for (int d = 0; d < HD; d++) dot = fmaf(L[d], R[d], dot);
    g_E[idx] = __expf(dot);
}

// ---------------------------------------------------------------------------
// K4: structured attention -> g_o.  512 threads, 4-way split:
// quad 0/1: A-part (EA*EC, VA) over m halves; quad 2/3: B-part over n halves.
// ---------------------------------------------------------------------------
__global__ void __launch_bounds__(512) attn_struct() {
    __shared__ float sea[HW], seb[HW];
    __shared__ __align__(16) float sva[HW * 18];
    __shared__ __align__(16) float svb[HW * 18];
    __shared__ float psum[4 * HW];
    __shared__ __align__(16) u64 pacc[4 * HW * 9];
    int tid = threadIdx.x;
    int i = blockIdx.x, h = blockIdx.y;
    for (int t = tid; t < HW; t += 512) {
        sea[t] = g_E[0 * ESTR + (h * HW + i) * HW + t];
        seb[t] = g_E[1 * ESTR + (h * HW + i) * HW + t];
    }
    for (int t = tid; t < HW * 18; t += 512) {
        int m = t / 18, d = t % 18;
        sva[t] = (d < HD) ? g_VA[(h * HW + m) * HD + d] : 0.f;
        svb[t] = (d < HD) ? g_VB[(h * HW + m) * HD + d] : 0.f;
    }
    __syncthreads();
    int quad = tid >> 7;
    int j = tid & 127;
    if (j < HW) {
        bool isA = quad < 2;
        int lo = (quad & 1) ? 41 : 0;
        int hi = (quad & 1) ? HW : 41;
        const float* er = g_E + (isA ? 2 : 3) * ESTR + (h * HW + j) * HW;
        const float* se = isA ? sea : seb;
        const float* sv = isA ? sva : svb;
        float z = 0.f;
        u64 w[9];
#pragma unroll
        for (int k = 0; k < 9; k++) w[k] = 0ULL;
        for (int m = lo; m < hi; m++) {
            float f = se[m] * er[m];
            z += f;
            u64 fp = pk(f, f);
            const u64* vr = (const u64*)(sv + m * 18);
#pragma unroll
            for (int k = 0; k < 9; k++) w[k] = fma2(fp, vr[k], w[k]);
        }
        psum[quad * HW + j] = z;
        u64* pw = pacc + (quad * HW + j) * 9;
#pragma unroll
        for (int k = 0; k < 9; k++) pw[k] = w[k];
    }
    __syncthreads();
    if (tid < HW) {
        int jj = tid;
        float zm = psum[jj] + psum[HW + jj];
        float zn = psum[2 * HW + jj] + psum[3 * HW + jj];
        const u64* p0 = pacc + jj * 9;
        const u64* p1 = pacc + (HW + jj) * 9;
        const u64* p2 = pacc + (2 * HW + jj) * 9;
        const u64* p3 = pacc + (3 * HW + jj) * 9;
        float inv = 1.0f / (zm * zn);
        float* od = g_o + (i * HW + jj) * Dm + h * HD;
#pragma unroll
        for (int k = 0; k < 9; k++) {
            float2 A = unpk(add2(p0[k], p1[k]));
            float2 B = unpk(add2(p2[k], p3[k]));
            int d = 2 * k;
            od[d] = (A.x * zn + B.x * zm) * inv;
            if (d + 1 < HD) od[d + 1] = (A.y * zn + B.y * zm) * inv;
        }
    }
}

// ---------------------------------------------------------------------------
// K5: tokens + out_proj + residual + LN1 -> g_x.  64 tokens/block, d split in 2.
// ---------------------------------------------------------------------------
__global__ void __launch_bounds__(128) tokens_proj_ln(const float* __restrict__ opw,
                                                      const float* __restrict__ opb,
                                                      const float* __restrict__ gg,
                                                      const float* __restrict__ bb) {
    __shared__ float embs[1296];
    __shared__ float ws[Dm * Dm];
    __shared__ float bs[Dm], gs[Dm], bts[Dm];
    __shared__ float ys[64 * 36];
    int tid = threadIdx.x;
    for (int i = tid; i < 1296; i += 128) embs[i] = g_emb[i];
    for (int i = tid; i < Dm * Dm; i += 128) ws[i] = opw[i];
    if (tid < Dm) { bs[tid] = opb[tid]; gs[tid] = gg[tid]; bts[tid] = bb[tid]; }
    __syncthreads();
    int half = tid >> 6;
    int lt = tid & 63;
    int t = blockIdx.x * 64 + lt;
    if (t < S) {
        int i = t / HW, j = t % HW;
        float orow[Dm];
#pragma unroll
        for (int d = 0; d < Dm; d++) orow[d] = g_o[t * Dm + d];
        int dlo = half * 17;
#pragma unroll 1
        for (int d = dlo; d < dlo + 17; d++) {
            float xv;
            if (d < 16)       xv = embs[i * 16 + d];
            else if (d < 32)  xv = embs[j * 16 + (d - 16)];
            else if (d == 32) xv = ((float)(i / 9) - (float)(j / 9)) * 0.25f;
            else              xv = ((float)(i % 9) - (float)(j % 9)) * 0.25f;
            float a = bs[d] + xv;
            const float* wp = ws + d * Dm;
#pragma unroll
            for (int k = 0; k < Dm; k++) a = fmaf(orow[k], wp[k], a);
            ys[lt * 36 + d] = a;
        }
    }
    __syncthreads();
    if (half == 0 && t < S) {
        float y[Dm];
#pragma unroll
        for (int d = 0; d < Dm; d++) y[d] = ys[lt * 36 + d];
        float m = 0.f;
#pragma unroll
        for (int d = 0; d < Dm; d++) m += y[d];
        m *= (1.0f / Dm);
        float v = 0.f;
#pragma unroll
        for (int d = 0; d < Dm; d++) { float tt = y[d] - m; v = fmaf(tt, tt, v); }
        v *= (1.0f / Dm);
        float inv = rsqrtf(v + EPSV);
#pragma unroll
        for (int d = 0; d < Dm; d++) g_x[t * Dm + d] = (y[d] - m) * inv * gs[d] + bts[d];
    }
}

// ---------------------------------------------------------------------------
// K6: layer-0 FFN partials (unchanged from R7)
// ---------------------------------------------------------------------------
__global__ void __launch_bounds__(128, 3) ffn0(const float* __restrict__ l1w,
                                               const float* __restrict__ l1b,
                                               const float* __restrict__ l2w) {
    __shared__ __align__(16) float W1s[FCHK0 * 36];
    __shared__ __align__(16) float W2s[FCHK0 * 36];
    __shared__ float b1s[FCHK0];
    int tid = threadIdx.x;
    int row = blockIdx.x * 128 + tid;
    int fbase = blockIdx.z * FSEG;
    bool act = row < S;
    u64 xr[17], y[17];
#pragma unroll
    for (int i = 0; i < 17; i++) { xr[i] = 0ULL; y[i] = 0ULL; }
    if (act) {
        const u64* p = (const u64*)(g_x + row * Dm);
#pragma unroll
        for (int i = 0; i < 17; i++) xr[i] = p[i];
    }
    for (int fc = fbase; fc < fbase + FSEG; fc += FCHK0) {
        for (int e = tid; e < FCHK0 * Dm; e += 128) {
            int f = e / Dm, d = e % Dm;
            W1s[f * 36 + d] = l1w[(fc + f) * Dm + d];
            W2s[f * 36 + d] = l2w[d * FFd + fc + f];
        }
        if (tid < FCHK0) b1s[tid] = l1b[fc + tid];
        __syncthreads();
#pragma unroll 2
        for (int f = 0; f < FCHK0; f++) {
            const ulonglong2* w2p = (const ulonglong2*)(W1s + f * 36);
            const u64*        w1p = (const u64*)(W1s + f * 36);
            ulonglong2 a0 = w2p[0], a1 = w2p[1], a2 = w2p[2], a3 = w2p[3];
            ulonglong2 a4 = w2p[4], a5 = w2p[5], a6 = w2p[6], a7 = w2p[7];
            u64 a16 = w1p[16];
            u64 t0 = mul2(xr[0], a0.x),  t1 = mul2(xr[1], a0.y);
            t0 = fma2(xr[2], a1.x, t0);  t1 = fma2(xr[3], a1.y, t1);
            t0 = fma2(xr[4], a2.x, t0);  t1 = fma2(xr[5], a2.y, t1);
            t0 = fma2(xr[6], a3.x, t0);  t1 = fma2(xr[7], a3.y, t1);
            t0 = fma2(xr[8], a4.x, t0);  t1 = fma2(xr[9], a4.y, t1);
            t0 = fma2(xr[10], a5.x, t0); t1 = fma2(xr[11], a5.y, t1);
            t0 = fma2(xr[12], a6.x, t0); t1 = fma2(xr[13], a6.y, t1);
            t0 = fma2(xr[14], a7.x, t0); t1 = fma2(xr[15], a7.y, t1);
            t0 = fma2(xr[16], a16, t0);
            t0 = add2(t0, t1);
            float2 fh = unpk(t0);
            float hrelu = fmaxf(fh.x + fh.y + b1s[f], 0.f);
            u64 hp = pk(hrelu, hrelu);
            const ulonglong2* v2p = (const ulonglong2*)(W2s + f * 36);
            const u64*        v1p = (const u64*)(W2s + f * 36);
            ulonglong2 b0 = v2p[0], b1v = v2p[1], b2v = v2p[2], b3 = v2p[3];
            ulonglong2 b4 = v2p[4], b5 = v2p[5], b6 = v2p[6], b7 = v2p[7];
            u64 b16 = v1p[16];
            y[0]  = fma2(hp, b0.x, y[0]);   y[1]  = fma2(hp, b0.y, y[1]);
            y[2]  = fma2(hp, b1v.x, y[2]);  y[3]  = fma2(hp, b1v.y, y[3]);
            y[4]  = fma2(hp, b2v.x, y[4]);  y[5]  = fma2(hp, b2v.y, y[5]);
            y[6]  = fma2(hp, b3.x, y[6]);   y[7]  = fma2(hp, b3.y, y[7]);
            y[8]  = fma2(hp, b4.x, y[8]);   y[9]  = fma2(hp, b4.y, y[9]);
            y[10] = fma2(hp, b5.x, y[10]);  y[11] = fma2(hp, b5.y, y[11]);
            y[12] = fma2(hp, b6.x, y[12]);  y[13] = fma2(hp, b6.y, y[13]);
            y[14] = fma2(hp, b7.x, y[14]);  y[15] = fma2(hp, b7.y, y[15]);
            y[16] = fma2(hp, b16, y[16]);
        }
        __syncthreads();
    }
    if (act) {
        u64* yo = (u64*)(g_yp + ((size_t)blockIdx.z * S + row) * Dm);
#pragma unroll
        for (int i = 0; i < 17; i++) yo[i] = y[i];
    }
}

// ---------------------------------------------------------------------------
// K7: FFN reduce + LN2 + layer-1 QKV fused (unchanged)
// ---------------------------------------------------------------------------
__global__ void __launch_bounds__(256) ffnred_qkv(const float* __restrict__ ipw2,
                                                  const float* __restrict__ ipb2,
                                                  const float* __restrict__ l2b,
                                                  const float* __restrict__ gg,
                                                  const float* __restrict__ bb) {
    __shared__ float xs[Dm * 32];
    __shared__ float ws[102 * Dm];
    __shared__ float bs[102];
    __shared__ __align__(16) float pre[32 * 36];
    __shared__ float l2bs[Dm], gs[Dm], bts[Dm];
    int tid = threadIdx.x;
    int row0 = blockIdx.x * 32;
    for (int i = tid; i < 102 * Dm; i += 256) ws[i] = ipw2[i];
    if (tid < 102) bs[tid] = ipb2[tid];
    if (tid < Dm) { l2bs[tid] = l2b[tid]; gs[tid] = gg[tid]; bts[tid] = bb[tid]; }
    for (int e = tid; e < 32 * 17; e += 256) {
        int r = e / 17, k = e % 17;
        int row = row0 + r;
        if (row < S) {
            u64 acc = ((const u64*)(g_x + row * Dm))[k];
#pragma unroll
            for (int g = 0; g < NFSEG; g++)
                acc = add2(acc, ((const u64*)(g_yp + ((size_t)g * S + row) * Dm))[k]);
            ((u64*)(pre + r * 36))[k] = acc;
        }
    }
    __syncthreads();
    if (tid < 32 && row0 + tid < S) {
        float y[Dm];
#pragma unroll
        for (int d = 0; d < Dm; d++) y[d] = pre[tid * 36 + d] + l2bs[d];
        float m = 0.f;
#pragma unroll
        for (int d = 0; d < Dm; d++) m += y[d];
        m *= (1.0f / Dm);
        float v = 0.f;
#pragma unroll
        for (int d = 0; d < Dm; d++) { float tt = y[d] - m; v = fmaf(tt, tt, v); }
        v *= (1.0f / Dm);
        float inv = rsqrtf(v + EPSV);
        int row = row0 + tid;
#pragma unroll
        for (int d = 0; d < Dm; d++) {
            float xv = (y[d] - m) * inv * gs[d] + bts[d];
            xs[d * 32 + tid] = xv;
            g_x[row * Dm + d] = xv;
        }
    }
    __syncthreads();
    const float scale = rsqrtf(17.f);
    int lane = tid & 31, w = tid >> 5;
    int s = row0 + lane;
    for (int cc = w; cc < 102; cc += 8) {
        float acc = bs[cc];
        const float* wp = ws + cc * Dm;
#pragma unroll
        for (int d = 0; d < Dm; d++) acc = fmaf(xs[d * 32 + lane], wp[d], acc);
        if (s < S) {
            int kind = cc / Dm;
            int c2 = cc % Dm;
            int h = c2 / HD, dd = c2 % HD;
            int off = (h * S + s) * PH + dd;
            if (kind == 0)      g_q[off] = acc * scale;
            else if (kind == 1) g_k[off] = acc;
            else                g_v[off] = acc;
        }
    }
}

// ---------------------------------------------------------------------------
// K8: agent attention partials (unchanged)
// ---------------------------------------------------------------------------
__global__ void __launch_bounds__(128) attn_agent() {
    __shared__ __align__(16) float Ks[KSEG2 * PH];
    __shared__ __align__(16) float Vs[KSEG2 * PH];
    int tid = threadIdx.x;
    int seg = blockIdx.x, h = blockIdx.y;
    int k0 = seg * KSEG2;
    int n = min(KSEG2, S - k0);
    int start = g_agent * HW;

    const float4* ksrc = (const float4*)(g_k + (h * S + k0) * PH);
    const float4* vsrc = (const float4*)(g_v + (h * S + k0) * PH);
    float4* kdst = (float4*)Ks; float4* vdst = (float4*)Vs;
    for (int i = tid; i < n * 5; i += 128) { kdst[i] = ksrc[i]; vdst[i] = vsrc[i]; }
    __syncthreads();

    if (tid >= HW) return;
    u64 q[9], acc[9];
    const u64* qp = (const u64*)(g_q + (h * S + start + tid) * PH);
#pragma unroll
    for (int i = 0; i < 9; i++) { q[i] = qp[i]; acc[i] = 0ULL; }
    float ssum = 0.f;
    const ulonglong2* K2 = (const ulonglong2*)Ks;
    const ulonglong2* V2 = (const ulonglong2*)Vs;
    for (int kk = 0; kk < n; kk++) {
        ulonglong2 ka = K2[0], kb = K2[1], kc = K2[2], kd = K2[3];
        u64 ke = K2[4].x;
        u64 t0 = mul2(q[0], ka.x),  t1 = mul2(q[1], ka.y);
        t0 = fma2(q[2], kb.x, t0);  t1 = fma2(q[3], kb.y, t1);
        t0 = fma2(q[4], kc.x, t0);  t1 = fma2(q[5], kc.y, t1);
        t0 = fma2(q[6], kd.x, t0);  t1 = fma2(q[7], kd.y, t1);
        t0 = fma2(q[8], ke, t0);
        t0 = add2(t0, t1);
        float2 f = unpk(t0);
        float p = __expf(f.x + f.y);
        ssum += p;
        u64 pp = pk(p, p);
        ulonglong2 va = V2[0], vb = V2[1], vc = V2[2], vd = V2[3];
        u64 ve = V2[4].x;
        acc[0] = fma2(pp, va.x, acc[0]); acc[1] = fma2(pp, va.y, acc[1]);
        acc[2] = fma2(pp, vb.x, acc[2]); acc[3] = fma2(pp, vb.y, acc[3]);
        acc[4] = fma2(pp, vc.x, acc[4]); acc[5] = fma2(pp, vc.y, acc[5]);
        acc[6] = fma2(pp, vd.x, acc[6]); acc[7] = fma2(pp, vd.y, acc[7]);
        acc[8] = fma2(pp, ve, acc[8]);
        K2 += 5; V2 += 5;
    }
    u64* pa = (u64*)(g_pacca + ((h * NSEG2 + seg) * HW + tid) * PAC);
#pragma unroll
    for (int i = 0; i < 9; i++) pa[i] = acc[i];
    g_psuma[(h * NSEG2 + seg) * HW + tid] = ssum;
}

// ---------------------------------------------------------------------------
// K9: combine agent attention segments
// ---------------------------------------------------------------------------
__global__ void attn_reduce_agent() {
    int e = blockIdx.x * blockDim.x + threadIdx.x;
    if (e >= HW * Dm) return;
    int r = e / Dm, c = e % Dm;
    int h = c / HD, d = c % HD;
    float a = 0.f, sm = 0.f;
    for (int g = 0; g < NSEG2; g++) {
        a  += g_pacca[((h * NSEG2 + g) * HW + r) * PAC + d];
        sm += g_psuma[(h * NSEG2 + g) * HW + r];
    }
    g_oa[r * Dm + c] = a / sm;
}

// ---------------------------------------------------------------------------
// K10: agent out_proj + residual + LN -> g_xa
// ---------------------------------------------------------------------------
__global__ void __launch_bounds__(128) proj_ln_agent(const float* __restrict__ opw,
                                                     const float* __restrict__ opb,
                                                     const float* __restrict__ gg,
                                                     const float* __restrict__ bb) {
    __shared__ float ws[Dm * Dm];
    __shared__ float bs[Dm], gs[Dm], bts[Dm];
    int tid = threadIdx.x;
    for (int i = tid; i < Dm * Dm; i += blockDim.x) ws[i] = opw[i];
    if (tid < Dm) { bs[tid] = opb[tid]; gs[tid] = gg[tid]; bts[tid] = bb[tid]; }
    __syncthreads();
    if (tid >= HW) return;
    int s = g_agent * HW + tid;
    float orow[Dm], y[Dm];
#pragma unroll
    for (int d = 0; d < Dm; d++) orow[d] = g_oa[tid * Dm + d];
#pragma unroll 2
    for (int d = 0; d < Dm; d++) {
        float a = bs[d] + g_x[s * Dm + d];
        const float* wp = ws + d * Dm;
#pragma unroll
        for (int k = 0; k < Dm; k++) a = fmaf(orow[k], wp[k], a);
        y[d] = a;
    }
    float m = 0.f;
#pragma unroll
    for (int d = 0; d < Dm; d++) m += y[d];
    m *= (1.0f / Dm);
    float v = 0.f;
#pragma unroll
    for (int d = 0; d < Dm; d++) { float t = y[d] - m; v = fmaf(t, t, v); }
    v *= (1.0f / Dm);
    float inv = rsqrtf(v + EPSV);
#pragma unroll
    for (int d = 0; d < Dm; d++) g_xa[tid * Dm + d] = (y[d] - m) * inv * gs[d] + bts[d];
}

// ---------------------------------------------------------------------------
// K11: agent FFN partials
// ---------------------------------------------------------------------------
__global__ void __launch_bounds__(128) ffn_agent(const float* __restrict__ l1w,
                                                 const float* __restrict__ l1b,
                                                 const float* __restrict__ l2w) {
    __shared__ __align__(16) float W1s[FSEG2 * 36];
    __shared__ __align__(16) float W2s[FSEG2 * 36];
    __shared__ float b1s[FSEG2];
    int tid = threadIdx.x;
    int fbase = blockIdx.x * FSEG2;
    for (int e = tid; e < FSEG2 * Dm; e += 128) {
        int f = e / Dm, d = e % Dm;
        W1s[f * 36 + d] = l1w[(fbase + f) * Dm + d];
        W2s[f * 36 + d] = l2w[d * FFd + fbase + f];
    }
    if (tid < FSEG2) b1s[tid] = l1b[fbase + tid];
    __syncthreads();
    if (tid >= HW) return;
    u64 xr[17], y[17];
    const u64* p = (const u64*)(g_xa + tid * Dm);
#pragma unroll
    for (int i = 0; i < 17; i++) { xr[i] = p[i]; y[i] = 0ULL; }
#pragma unroll 2
    for (int f = 0; f < FSEG2; f++) {
        const ulonglong2* w2p = (const ulonglong2*)(W1s + f * 36);
        const u64*        w1p = (const u64*)(W1s + f * 36);
        ulonglong2 a0 = w2p[0], a1 = w2p[1], a2 = w2p[2], a3 = w2p[3];
        ulonglong2 a4 = w2p[4], a5 = w2p[5], a6 = w2p[6], a7 = w2p[7];
        u64 a16 = w1p[16];
        u64 t0 = mul2(xr[0], a0.x),  t1 = mul2(xr[1], a0.y);
        t0 = fma2(xr[2], a1.x, t0);  t1 = fma2(xr[3], a1.y, t1);
        t0 = fma2(xr[4], a2.x, t0);  t1 = fma2(xr[5], a2.y, t1);
        t0 = fma2(xr[6], a3.x, t0);  t1 = fma2(xr[7], a3.y, t1);
        t0 = fma2(xr[8], a4.x, t0);  t1 = fma2(xr[9], a4.y, t1);
        t0 = fma2(xr[10], a5.x, t0); t1 = fma2(xr[11], a5.y, t1);
        t0 = fma2(xr[12], a6.x, t0); t1 = fma2(xr[13], a6.y, t1);
        t0 = fma2(xr[14], a7.x, t0); t1 = fma2(xr[15], a7.y, t1);
        t0 = fma2(xr[16], a16, t0);
        t0 = add2(t0, t1);
        float2 fh = unpk(t0);
        float hrelu = fmaxf(fh.x + fh.y + b1s[f], 0.f);
        u64 hp = pk(hrelu, hrelu);
        const ulonglong2* v2p = (const ulonglong2*)(W2s + f * 36);
        const u64*        v1p = (const u64*)(W2s + f * 36);
        ulonglong2 b0 = v2p[0], b1v = v2p[1], b2v = v2p[2], b3 = v2p[3];
        ulonglong2 b4 = v2p[4], b5 = v2p[5], b6 = v2p[6], b7 = v2p[7];
        u64 b16 = v1p[16];
        y[0]  = fma2(hp, b0.x, y[0]);   y[1]  = fma2(hp, b0.y, y[1]);
        y[2]  = fma2(hp, b1v.x, y[2]);  y[3]  = fma2(hp, b1v.y, y[3]);
        y[4]  = fma2(hp, b2v.x, y[4]);  y[5]  = fma2(hp, b2v.y, y[5]);
        y[6]  = fma2(hp, b3.x, y[6]);   y[7]  = fma2(hp, b3.y, y[7]);
        y[8]  = fma2(hp, b4.x, y[8]);   y[9]  = fma2(hp, b4.y, y[9]);
        y[10] = fma2(hp, b5.x, y[10]);  y[11] = fma2(hp, b5.y, y[11]);
        y[12] = fma2(hp, b6.x, y[12]);  y[13] = fma2(hp, b6.y, y[13]);
        y[14] = fma2(hp, b7.x, y[14]);  y[15] = fma2(hp, b7.y, y[15]);
        y[16] = fma2(hp, b16, y[16]);
    }
    u64* yo = (u64*)(g_ypa + ((size_t)blockIdx.x * HW + tid) * Dm);
#pragma unroll
    for (int i = 0; i < 17; i++) yo[i] = y[i];
}

// ---------------------------------------------------------------------------
// K12: agent FFN reduce + LN + final mean -> out
// ---------------------------------------------------------------------------
__global__ void __launch_bounds__(128) agent_final(const float* __restrict__ l2b,
                                                   const float* __restrict__ gg,
                                                   const float* __restrict__ bb,
                                                   float* __restrict__ out) {
    __shared__ float rows[HW * Dm];
    int tid = threadIdx.x;
    if (tid < HW) {
        float y[Dm];
#pragma unroll
        for (int d = 0; d < Dm; d++) y[d] = g_xa[tid * Dm + d] + l2b[d];
        for (int g = 0; g < NFSEG2; g++) {
            const float* yp = g_ypa + ((size_t)g * HW + tid) * Dm;
#pragma unroll
            for (int d = 0; d < Dm; d++) y[d] += yp[d];
        }
        float m = 0.f;
#pragma unroll
        for (int d = 0; d < Dm; d++) m += y[d];
        m *= (1.0f / Dm);
        float v = 0.f;
#pragma unroll
        for (int d = 0; d < Dm; d++) { float t = y[d] - m; v = fmaf(t, t, v); }
        v *= (1.0f / Dm);
        float inv = rsqrtf(v + EPSV);
#pragma unroll
        for (int d = 0; d < Dm; d++) rows[tid * Dm + d] = (y[d] - m) * inv * gg[d] + bb[d];
    }
    __syncthreads();
    if (tid < Dm) {
        float s = 0.f;
        for (int r = 0; r < HW; r++) s += rows[r * Dm + tid];
        out[tid] = s * (1.0f / 81.0f);
    }
}

// ---------------------------------------------------------------------------
extern "C" void kernel_launch(void* const* d_in, const int* in_sizes, int n_in,
                              void* d_out, int out_size) {
    const float* obs = (const float*)d_in[0];
    const float* c1w = (const float*)d_in[1];
    const float* c1b = (const float*)d_in[2];
    const float* c2w = (const float*)d_in[3];
    const float* c2b = (const float*)d_in[4];
    const float* ipw = (const float*)d_in[5];
    const float* ipb = (const float*)d_in[6];
    const float* opw = (const float*)d_in[7];
    const float* opb = (const float*)d_in[8];
    const float* l1w = (const float*)d_in[9];
    const float* l1b = (const float*)d_in[10];
    const float* l2w = (const float*)d_in[11];
    const float* l2b = (const float*)d_in[12];
    const float* g1  = (const float*)d_in[13];
    const float* b1  = (const float*)d_in[14];
    const float* g2  = (const float*)d_in[15];
    const float* b2  = (const float*)d_in[16];
    float* out = (float*)d_out;

    conv_prep<<<1, 128>>>(obs, c1w, c1b, c2w, c2b);

    // layer 0 (structured)
    basis_qkv<<<(162 * 102 + 127) / 128, 128>>>(ipw, ipb);
    logits_exp<<<(4 * ESTR + 127) / 128, 128>>>();
    attn_struct<<<dim3(HW, NH), 512>>>();
    tokens_proj_ln<<<(S + 63) / 64, 128>>>(opw, opb, g1, b1);
    ffn0<<<dim3((S + 127) / 128, 1, NFSEG), 128>>>(l1w, l1b, l2w);
    ffnred_qkv<<<(S + 31) / 32, 256>>>(ipw + 102 * Dm, ipb + 102, l2b, g2, b2);

    // layer 1 (agent-only)
    attn_agent<<<dim3(NSEG2, NH), 128>>>();
    attn_reduce_agent<<<(HW * Dm + 127) / 128, 128>>>();
    proj_ln_agent<<<1, 128>>>(opw + Dm * Dm, opb + Dm, g1 + Dm, b1 + Dm);
    ffn_agent<<<NFSEG2, 128>>>(l1w + FFd * Dm, l1b + FFd, l2w + Dm * FFd);
    agent_final<<<1, 128>>>(l2b + Dm, g2 + Dm, b2 + Dm, out);
}

// round 9
// speedup vs baseline: 3.7828x; 1.1723x over previous
#include <cuda_runtime.h>

#define S      6561
#define Dm     34
#define HD     17
#define PH     20
#define PAC    18
#define FFd    2048
#define NH     2
#define HW     81
#define EPSV   1e-5f
#define ESTR   (NH * HW * HW)
// layer-0 FFN tiling
#define NFSEG  8
#define FSEG   256
#define FCHK0  64
// layer-1 agent attention: 2 heads x 74 segs = 148 blocks
#define NSEG2  74
#define KSEG2  89
// agent FFN split
#define NFSEG2 32
#define FSEG2  64

typedef unsigned long long u64;

// ---- packed fp32 helpers ----
__device__ __forceinline__ u64 fma2(u64 a, u64 b, u64 c) {
    u64 d; asm("fma.rn.f32x2 %0, %1, %2, %3;" : "=l"(d) : "l"(a), "l"(b), "l"(c)); return d;
}
__device__ __forceinline__ u64 mul2(u64 a, u64 b) {
    u64 d; asm("mul.rn.f32x2 %0, %1, %2;" : "=l"(d) : "l"(a), "l"(b)); return d;
}
__device__ __forceinline__ u64 add2(u64 a, u64 b) {
    u64 d; asm("add.rn.f32x2 %0, %1, %2;" : "=l"(d) : "l"(a), "l"(b)); return d;
}
__device__ __forceinline__ float2 unpk(u64 v) {
    float2 f; asm("mov.b64 {%0, %1}, %2;" : "=f"(f.x), "=f"(f.y) : "l"(v)); return f;
}
__device__ __forceinline__ u64 pk(float x, float y) {
    u64 v; asm("mov.b64 %0, {%1, %2};" : "=l"(v) : "f"(x), "f"(y)); return v;
}

// ---- device-global scratch ----
__device__ unsigned g_cnt;
__device__ unsigned g_sense;
__device__ int   g_agent;
__device__ __align__(16) float g_emb[HW * 16];
__device__ __align__(16) float g_x[S * Dm];
__device__ __align__(16) float g_q[NH * S * PH];
__device__ __align__(16) float g_k[NH * S * PH];
__device__ __align__(16) float g_v[NH * S * PH];
__device__ __align__(16) float g_o[S * Dm];
__device__ __align__(16) float g_yp[NFSEG * S * Dm];
__device__ __align__(16) float g_QA[NH * HW * HD];
__device__ __align__(16) float g_QB[NH * HW * HD];
__device__ __align__(16) float g_KA[NH * HW * HD];
__device__ __align__(16) float g_KB[NH * HW * HD];
__device__ __align__(16) float g_VA[NH * HW * HD];
__device__ __align__(16) float g_VB[NH * HW * HD];
__device__ __align__(16) float g_E[4 * ESTR];    // EA, EB row-major; EC, ED TRANSPOSED
__device__ __align__(16) float g_pacca[NH * NSEG2 * HW * PAC];
__device__ float g_psuma[NH * NSEG2 * HW];
__device__ __align__(16) float g_xa[HW * Dm];
__device__ __align__(16) float g_ypa[NFSEG2 * HW * Dm];
__device__ __align__(16) float g_oa[HW * Dm];

// ---- sense-reversing grid barrier (all blocks resident) ----
__device__ __forceinline__ void gsync(unsigned& ls) {
    __syncthreads();
    if (threadIdx.x == 0) {
        unsigned ns = ls ^ 1u;
        __threadfence();
        unsigned old = atomicAdd(&g_cnt, 1u);
        if (old == gridDim.x - 1u) {
            g_cnt = 0u;
            __threadfence();
            atomicExch(&g_sense, ns);
        } else {
            while (atomicAdd(&g_sense, 0u) != ns) { __nanosleep(64); }
        }
        ls = ns;
        __threadfence();
    }
    __syncthreads();
}

// ---------------------------------------------------------------------------
// K1 (fused front): conv+argmax -> basis QKV -> exp(logits). grid 148x256.
// EC/ED are stored TRANSPOSED (operand swap) for coalesced consumer reads.
// ---------------------------------------------------------------------------
__global__ void __launch_bounds__(256) front(
    const float* __restrict__ obs,
    const float* __restrict__ c1w, const float* __restrict__ c1b,
    const float* __restrict__ c2w, const float* __restrict__ c2b,
    const float* __restrict__ ipw, const float* __restrict__ ipb)
{
    __shared__ float so[192];
    __shared__ float c1s[1296];
    int tid = threadIdx.x;
    int b = blockIdx.x;
    unsigned ls = 0;

    if (b == 0) {
        for (int i = tid; i < 162; i += 256) so[i] = obs[i];
        __syncthreads();
        if (tid == 0) {
            float mx = so[0]; int mi = 0;
            for (int i = 1; i < 81; i++) if (so[i] > mx) { mx = so[i]; mi = i; }
            g_agent = mi;
        }
        for (int idx = tid; idx < 16 * 81; idx += 256) {
            int ch = idx / 81, pos = idx % 81, r = pos / 9, c = pos % 9;
            float acc = c1b[ch];
            for (int ci = 0; ci < 2; ci++)
                for (int dr = 0; dr < 3; dr++) {
                    int rr = r + dr - 1; if (rr < 0 || rr >= 9) continue;
                    for (int dc = 0; dc < 3; dc++) {
                        int cc = c + dc - 1; if (cc < 0 || cc >= 9) continue;
                        acc += so[ci * 81 + rr * 9 + cc] * c1w[((ch * 2 + ci) * 3 + dr) * 3 + dc];
                    }
                }
            c1s[idx] = fmaxf(acc, 0.f);
        }
        __syncthreads();
        for (int idx = tid; idx < 16 * 81; idx += 256) {
            int ch = idx / 81, pos = idx % 81, r = pos / 9, c = pos % 9;
            float acc = c2b[ch];
            for (int ci = 0; ci < 16; ci++)
                for (int dr = 0; dr < 3; dr++) {
                    int rr = r + dr - 1; if (rr < 0 || rr >= 9) continue;
                    for (int dc = 0; dc < 3; dc++) {
                        int cc = c + dc - 1; if (cc < 0 || cc >= 9) continue;
                        acc += c1s[ci * 81 + rr * 9 + cc] * c2w[((ch * 16 + ci) * 3 + dr) * 3 + dc];
                    }
                }
            g_emb[pos * 16 + ch] = fmaxf(acc, 0.f);
        }
    }
    gsync(ls);  // 1

    // basis QKV
    for (int idx = b * 256 + tid; idx < 162 * 102; idx += 148 * 256) {
        int v = idx / 102, c = idx % 102;
        const float* wr = ipw + c * Dm;
        float acc;
        if (v < 81) {
            int i = v;
            acc = ipb[c];
#pragma unroll
            for (int d = 0; d < 16; d++) acc = fmaf(g_emb[i * 16 + d], wr[d], acc);
            acc = fmaf((float)(i / 9) * 0.25f, wr[32], acc);
            acc = fmaf((float)(i % 9) * 0.25f, wr[33], acc);
        } else {
            int j = v - 81;
            acc = 0.f;
#pragma unroll
            for (int d = 0; d < 16; d++) acc = fmaf(g_emb[j * 16 + d], wr[16 + d], acc);
            acc = fmaf(-(float)(j / 9) * 0.25f, wr[32], acc);
            acc = fmaf(-(float)(j % 9) * 0.25f, wr[33], acc);
        }
        int kind = c / Dm;
        int cc = c % Dm;
        int h = cc / HD, dd = cc % HD;
        int off = (h * HW + (v % 81)) * HD + dd;
        if (kind == 0) {
            float sv = acc * rsqrtf(17.f);
            if (v < 81) g_QA[off] = sv; else g_QB[off] = sv;
        } else if (kind == 1) {
            if (v < 81) g_KA[off] = acc; else g_KB[off] = acc;
        } else {
            if (v < 81) g_VA[off] = acc; else g_VB[off] = acc;
        }
    }
    gsync(ls);  // 2

    // exp(logits). p=0: EA[i,m]=QA_i.KA_m  p=1: EB[i,m]=QA_i.KB_m
    // p=2: ECt[i,m]=KA_i.QB_m (=EC[m,i])   p=3: EDt[i,m]=KB_i.QB_m (=ED[m,i])
    for (int idx = b * 256 + tid; idx < 4 * ESTR; idx += 148 * 256) {
        int p = idx / ESTR;
        int r = idx % ESTR;
        int h = r / (HW * HW);
        int q2 = r % (HW * HW);
        int i = q2 / HW, m = q2 % HW;
        const float* L;
        const float* R;
        if (p == 0)      { L = g_QA + (h * HW + i) * HD; R = g_KA + (h * HW + m) * HD; }
        else if (p == 1) { L = g_QA + (h * HW + i) * HD; R = g_KB + (h * HW + m) * HD; }
        else if (p == 2) { L = g_KA + (h * HW + i) * HD; R = g_QB + (h * HW + m) * HD; }
        else             { L = g_KB + (h * HW + i) * HD; R = g_QB + (h * HW + m) * HD; }
        float dot = 0.f;
#pragma unroll
        for (int d = 0; d < HD; d++) dot = fmaf(L[d], R[d], dot);
        g_E[idx] = __expf(dot);
    }
}

// ---------------------------------------------------------------------------
// K2: structured attention -> g_o. 512 thr, 4-way split; EC/ED transposed
// so et[m*81+j] is coalesced across threads (unroll 4 for MLP).
// ---------------------------------------------------------------------------
__global__ void __launch_bounds__(512) attn_struct() {
    __shared__ float sea[HW], seb[HW];
    __shared__ __align__(16) float sva[HW * 18];
    __shared__ __align__(16) float svb[HW * 18];
    __shared__ float psum[4 * HW];
    __shared__ __align__(16) u64 pacc[4 * HW * 9];
    int tid = threadIdx.x;
    int i = blockIdx.x, h = blockIdx.y;
    for (int t = tid; t < HW; t += 512) {
        sea[t] = g_E[0 * ESTR + (h * HW + i) * HW + t];
        seb[t] = g_E[1 * ESTR + (h * HW + i) * HW + t];
    }
    for (int t = tid; t < HW * 18; t += 512) {
        int m = t / 18, d = t % 18;
        sva[t] = (d < HD) ? g_VA[(h * HW + m) * HD + d] : 0.f;
        svb[t] = (d < HD) ? g_VB[(h * HW + m) * HD + d] : 0.f;
    }
    __syncthreads();
    int quad = tid >> 7;
    int j = tid & 127;
    if (j < HW) {
        bool isA = quad < 2;
        int lo = (quad & 1) ? 41 : 0;
        int hi = (quad & 1) ? HW : 41;
        const float* et = g_E + (isA ? 2 : 3) * ESTR + h * HW * HW + j;
        const float* se = isA ? sea : seb;
        const float* sv = isA ? sva : svb;
        float z = 0.f;
        u64 w[9];
#pragma unroll
        for (int k = 0; k < 9; k++) w[k] = 0ULL;
#pragma unroll 4
        for (int m = lo; m < hi; m++) {
            float f = se[m] * et[m * HW];
            z += f;
            u64 fp = pk(f, f);
            const u64* vr = (const u64*)(sv + m * 18);
#pragma unroll
            for (int k = 0; k < 9; k++) w[k] = fma2(fp, vr[k], w[k]);
        }
        psum[quad * HW + j] = z;
        u64* pw = pacc + (quad * HW + j) * 9;
#pragma unroll
        for (int k = 0; k < 9; k++) pw[k] = w[k];
    }
    __syncthreads();
    if (tid < HW) {
        int jj = tid;
        float zm = psum[jj] + psum[HW + jj];
        float zn = psum[2 * HW + jj] + psum[3 * HW + jj];
        const u64* p0 = pacc + jj * 9;
        const u64* p1 = pacc + (HW + jj) * 9;
        const u64* p2 = pacc + (2 * HW + jj) * 9;
        const u64* p3 = pacc + (3 * HW + jj) * 9;
        float inv = 1.0f / (zm * zn);
        float* od = g_o + (i * HW + jj) * Dm + h * HD;
#pragma unroll
        for (int k = 0; k < 9; k++) {
            float2 A = unpk(add2(p0[k], p1[k]));
            float2 B = unpk(add2(p2[k], p3[k]));
            int d = 2 * k;
            od[d] = (A.x * zn + B.x * zm) * inv;
            if (d + 1 < HD) od[d + 1] = (A.y * zn + B.y * zm) * inv;
        }
    }
}

// ---------------------------------------------------------------------------
// K3: tokens + out_proj + residual + LN1 -> g_x
// ---------------------------------------------------------------------------
__global__ void __launch_bounds__(128) tokens_proj_ln(const float* __restrict__ opw,
                                                      const float* __restrict__ opb,
                                                      const float* __restrict__ gg,
                                                      const float* __restrict__ bb) {
    __shared__ float embs[1296];
    __shared__ float ws[Dm * Dm];
    __shared__ float bs[Dm], gs[Dm], bts[Dm];
    __shared__ float ys[64 * 36];
    int tid = threadIdx.x;
    for (int i = tid; i < 1296; i += 128) embs[i] = g_emb[i];
    for (int i = tid; i < Dm * Dm; i += 128) ws[i] = opw[i];
    if (tid < Dm) { bs[tid] = opb[tid]; gs[tid] = gg[tid]; bts[tid] = bb[tid]; }
    __syncthreads();
    int half = tid >> 6;
    int lt = tid & 63;
    int t = blockIdx.x * 64 + lt;
    if (t < S) {
        int i = t / HW, j = t % HW;
        float orow[Dm];
#pragma unroll
        for (int d = 0; d < Dm; d++) orow[d] = g_o[t * Dm + d];
        int dlo = half * 17;
#pragma unroll 1
        for (int d = dlo; d < dlo + 17; d++) {
            float xv;
            if (d < 16)       xv = embs[i * 16 + d];
            else if (d < 32)  xv = embs[j * 16 + (d - 16)];
            else if (d == 32) xv = ((float)(i / 9) - (float)(j / 9)) * 0.25f;
            else              xv = ((float)(i % 9) - (float)(j % 9)) * 0.25f;
            float a = bs[d] + xv;
            const float* wp = ws + d * Dm;
#pragma unroll
            for (int k = 0; k < Dm; k++) a = fmaf(orow[k], wp[k], a);
            ys[lt * 36 + d] = a;
        }
    }
    __syncthreads();
    if (half == 0 && t < S) {
        float y[Dm];
#pragma unroll
        for (int d = 0; d < Dm; d++) y[d] = ys[lt * 36 + d];
        float m = 0.f;
#pragma unroll
        for (int d = 0; d < Dm; d++) m += y[d];
        m *= (1.0f / Dm);
        float v = 0.f;
#pragma unroll
        for (int d = 0; d < Dm; d++) { float tt = y[d] - m; v = fmaf(tt, tt, v); }
        v *= (1.0f / Dm);
        float inv = rsqrtf(v + EPSV);
#pragma unroll
        for (int d = 0; d < Dm; d++) g_x[t * Dm + d] = (y[d] - m) * inv * gs[d] + bts[d];
    }
}

// ---------------------------------------------------------------------------
// K4: layer-0 FFN partials (3 blocks/SM)
// ---------------------------------------------------------------------------
__global__ void __launch_bounds__(128, 3) ffn0(const float* __restrict__ l1w,
                                               const float* __restrict__ l1b,
                                               const float* __restrict__ l2w) {
    __shared__ __align__(16) float W1s[FCHK0 * 36];
    __shared__ __align__(16) float W2s[FCHK0 * 36];
    __shared__ float b1s[FCHK0];
    int tid = threadIdx.x;
    int row = blockIdx.x * 128 + tid;
    int fbase = blockIdx.z * FSEG;
    bool act = row < S;
    u64 xr[17], y[17];
#pragma unroll
    for (int i = 0; i < 17; i++) { xr[i] = 0ULL; y[i] = 0ULL; }
    if (act) {
        const u64* p = (const u64*)(g_x + row * Dm);
#pragma unroll
        for (int i = 0; i < 17; i++) xr[i] = p[i];
    }
    for (int fc = fbase; fc < fbase + FSEG; fc += FCHK0) {
        for (int e = tid; e < FCHK0 * Dm; e += 128) {
            int f = e / Dm, d = e % Dm;
            W1s[f * 36 + d] = l1w[(fc + f) * Dm + d];
            W2s[f * 36 + d] = l2w[d * FFd + fc + f];
        }
        if (tid < FCHK0) b1s[tid] = l1b[fc + tid];
        __syncthreads();
#pragma unroll 2
        for (int f = 0; f < FCHK0; f++) {
            const ulonglong2* w2p = (const ulonglong2*)(W1s + f * 36);
            const u64*        w1p = (const u64*)(W1s + f * 36);
            ulonglong2 a0 = w2p[0], a1 = w2p[1], a2 = w2p[2], a3 = w2p[3];
            ulonglong2 a4 = w2p[4], a5 = w2p[5], a6 = w2p[6], a7 = w2p[7];
            u64 a16 = w1p[16];
            u64 t0 = mul2(xr[0], a0.x),  t1 = mul2(xr[1], a0.y);
            t0 = fma2(xr[2], a1.x, t0);  t1 = fma2(xr[3], a1.y, t1);
            t0 = fma2(xr[4], a2.x, t0);  t1 = fma2(xr[5], a2.y, t1);
            t0 = fma2(xr[6], a3.x, t0);  t1 = fma2(xr[7], a3.y, t1);
            t0 = fma2(xr[8], a4.x, t0);  t1 = fma2(xr[9], a4.y, t1);
            t0 = fma2(xr[10], a5.x, t0); t1 = fma2(xr[11], a5.y, t1);
            t0 = fma2(xr[12], a6.x, t0); t1 = fma2(xr[13], a6.y, t1);
            t0 = fma2(xr[14], a7.x, t0); t1 = fma2(xr[15], a7.y, t1);
            t0 = fma2(xr[16], a16, t0);
            t0 = add2(t0, t1);
            float2 fh = unpk(t0);
            float hrelu = fmaxf(fh.x + fh.y + b1s[f], 0.f);
            u64 hp = pk(hrelu, hrelu);
            const ulonglong2* v2p = (const ulonglong2*)(W2s + f * 36);
            const u64*        v1p = (const u64*)(W2s + f * 36);
            ulonglong2 b0 = v2p[0], b1v = v2p[1], b2v = v2p[2], b3 = v2p[3];
            ulonglong2 b4 = v2p[4], b5 = v2p[5], b6 = v2p[6], b7 = v2p[7];
            u64 b16 = v1p[16];
            y[0]  = fma2(hp, b0.x, y[0]);   y[1]  = fma2(hp, b0.y, y[1]);
            y[2]  = fma2(hp, b1v.x, y[2]);  y[3]  = fma2(hp, b1v.y, y[3]);
            y[4]  = fma2(hp, b2v.x, y[4]);  y[5]  = fma2(hp, b2v.y, y[5]);
            y[6]  = fma2(hp, b3.x, y[6]);   y[7]  = fma2(hp, b3.y, y[7]);
            y[8]  = fma2(hp, b4.x, y[8]);   y[9]  = fma2(hp, b4.y, y[9]);
            y[10] = fma2(hp, b5.x, y[10]);  y[11] = fma2(hp, b5.y, y[11]);
            y[12] = fma2(hp, b6.x, y[12]);  y[13] = fma2(hp, b6.y, y[13]);
            y[14] = fma2(hp, b7.x, y[14]);  y[15] = fma2(hp, b7.y, y[15]);
            y[16] = fma2(hp, b16, y[16]);
        }
        __syncthreads();
    }
    if (act) {
        u64* yo = (u64*)(g_yp + ((size_t)blockIdx.z * S + row) * Dm);
#pragma unroll
        for (int i = 0; i < 17; i++) yo[i] = y[i];
    }
}

// ---------------------------------------------------------------------------
// K5: FFN reduce + LN2 + layer-1 QKV fused
// ---------------------------------------------------------------------------
__global__ void __launch_bounds__(256) ffnred_qkv(const float* __restrict__ ipw2,
                                                  const float* __restrict__ ipb2,
                                                  const float* __restrict__ l2b,
                                                  const float* __restrict__ gg,
                                                  const float* __restrict__ bb) {
    __shared__ float xs[Dm * 32];
    __shared__ float ws[102 * Dm];
    __shared__ float bs[102];
    __shared__ __align__(16) float pre[32 * 36];
    __shared__ float l2bs[Dm], gs[Dm], bts[Dm];
    int tid = threadIdx.x;
    int row0 = blockIdx.x * 32;
    for (int i = tid; i < 102 * Dm; i += 256) ws[i] = ipw2[i];
    if (tid < 102) bs[tid] = ipb2[tid];
    if (tid < Dm) { l2bs[tid] = l2b[tid]; gs[tid] = gg[tid]; bts[tid] = bb[tid]; }
    for (int e = tid; e < 32 * 17; e += 256) {
        int r = e / 17, k = e % 17;
        int row = row0 + r;
        if (row < S) {
            u64 acc = ((const u64*)(g_x + row * Dm))[k];
#pragma unroll
            for (int g = 0; g < NFSEG; g++)
                acc = add2(acc, ((const u64*)(g_yp + ((size_t)g * S + row) * Dm))[k]);
            ((u64*)(pre + r * 36))[k] = acc;
        }
    }
    __syncthreads();
    if (tid < 32 && row0 + tid < S) {
        float y[Dm];
#pragma unroll
        for (int d = 0; d < Dm; d++) y[d] = pre[tid * 36 + d] + l2bs[d];
        float m = 0.f;
#pragma unroll
        for (int d = 0; d < Dm; d++) m += y[d];
        m *= (1.0f / Dm);
        float v = 0.f;
#pragma unroll
        for (int d = 0; d < Dm; d++) { float tt = y[d] - m; v = fmaf(tt, tt, v); }
        v *= (1.0f / Dm);
        float inv = rsqrtf(v + EPSV);
        int row = row0 + tid;
#pragma unroll
        for (int d = 0; d < Dm; d++) {
            float xv = (y[d] - m) * inv * gs[d] + bts[d];
            xs[d * 32 + tid] = xv;
            g_x[row * Dm + d] = xv;
        }
    }
    __syncthreads();
    const float scale = rsqrtf(17.f);
    int lane = tid & 31, w = tid >> 5;
    int s = row0 + lane;
    for (int cc = w; cc < 102; cc += 8) {
        float acc = bs[cc];
        const float* wp = ws + cc * Dm;
#pragma unroll
        for (int d = 0; d < Dm; d++) acc = fmaf(xs[d * 32 + lane], wp[d], acc);
        if (s < S) {
            int kind = cc / Dm;
            int c2 = cc % Dm;
            int h = c2 / HD, dd = c2 % HD;
            int off = (h * S + s) * PH + dd;
            if (kind == 0)      g_q[off] = acc * scale;
            else if (kind == 1) g_k[off] = acc;
            else                g_v[off] = acc;
        }
    }
}

// ---------------------------------------------------------------------------
// K6 (fused agent tail): attn partials -> reduce -> proj+LN -> FFN -> final.
// grid 148x256 (all resident), 4 grid syncs (even -> barrier state restored).
// ---------------------------------------------------------------------------
__global__ void __launch_bounds__(256) agent_tail(
    const float* __restrict__ opw2, const float* __restrict__ opb2,
    const float* __restrict__ g12,  const float* __restrict__ b12,
    const float* __restrict__ l1w2, const float* __restrict__ l1b2,
    const float* __restrict__ l2w2, const float* __restrict__ l2b2,
    const float* __restrict__ g22,  const float* __restrict__ b22,
    float* __restrict__ out)
{
    __shared__ __align__(16) float sm[4800];
    int tid = threadIdx.x;
    int b = blockIdx.x;
    unsigned ls = 0;

    // P1: attention partials (148 units = 2 heads x 74 segs)
    {
        int h = b / NSEG2;
        int seg = b % NSEG2;
        int k0 = seg * KSEG2;
        int n = min(KSEG2, S - k0);
        float* Ks = sm;
        float* Vs = sm + 1800;
        const float4* ksrc = (const float4*)(g_k + (h * S + k0) * PH);
        const float4* vsrc = (const float4*)(g_v + (h * S + k0) * PH);
        float4* kdst = (float4*)Ks; float4* vdst = (float4*)Vs;
        for (int i = tid; i < n * 5; i += 256) { kdst[i] = ksrc[i]; vdst[i] = vsrc[i]; }
        __syncthreads();
        if (tid < HW) {
            int start = g_agent * HW;
            u64 q[9], acc[9];
            const u64* qp = (const u64*)(g_q + (h * S + start + tid) * PH);
#pragma unroll
            for (int i = 0; i < 9; i++) { q[i] = qp[i]; acc[i] = 0ULL; }
            float ssum = 0.f;
            const ulonglong2* K2 = (const ulonglong2*)Ks;
            const ulonglong2* V2 = (const ulonglong2*)Vs;
            for (int kk = 0; kk < n; kk++) {
                ulonglong2 ka = K2[0], kb = K2[1], kc = K2[2], kd = K2[3];
                u64 ke = K2[4].x;
                u64 t0 = mul2(q[0], ka.x),  t1 = mul2(q[1], ka.y);
                t0 = fma2(q[2], kb.x, t0);  t1 = fma2(q[3], kb.y, t1);
                t0 = fma2(q[4], kc.x, t0);  t1 = fma2(q[5], kc.y, t1);
                t0 = fma2(q[6], kd.x, t0);  t1 = fma2(q[7], kd.y, t1);
                t0 = fma2(q[8], ke, t0);
                t0 = add2(t0, t1);
                float2 f = unpk(t0);
                float p = __expf(f.x + f.y);
                ssum += p;
                u64 pp = pk(p, p);
                ulonglong2 va = V2[0], vb = V2[1], vc = V2[2], vd = V2[3];
                u64 ve = V2[4].x;
                acc[0] = fma2(pp, va.x, acc[0]); acc[1] = fma2(pp, va.y, acc[1]);
                acc[2] = fma2(pp, vb.x, acc[2]); acc[3] = fma2(pp, vb.y, acc[3]);
                acc[4] = fma2(pp, vc.x, acc[4]); acc[5] = fma2(pp, vc.y, acc[5]);
                acc[6] = fma2(pp, vd.x, acc[6]); acc[7] = fma2(pp, vd.y, acc[7]);
                acc[8] = fma2(pp, ve, acc[8]);
                K2 += 5; V2 += 5;
            }
            u64* pa = (u64*)(g_pacca + ((h * NSEG2 + seg) * HW + tid) * PAC);
#pragma unroll
            for (int i = 0; i < 9; i++) pa[i] = acc[i];
            g_psuma[(h * NSEG2 + seg) * HW + tid] = ssum;
        }
    }
    gsync(ls);  // 1

    // P2: segment reduce -> g_oa (blocks 0..10)
    {
        int e = b * 256 + tid;
        if (b < 11 && e < HW * Dm) {
            int r = e / Dm, c = e % Dm;
            int h = c / HD, d = c % HD;
            float a = 0.f, smm = 0.f;
#pragma unroll 4
            for (int g = 0; g < NSEG2; g++) {
                a   += g_pacca[((h * NSEG2 + g) * HW + r) * PAC + d];
                smm += g_psuma[(h * NSEG2 + g) * HW + r];
            }
            g_oa[e] = a / smm;
        }
    }
    gsync(ls);  // 2

    // P3: out_proj + residual + LN -> g_xa (block 0)
    if (b == 0) {
        float* ws  = sm;
        float* bs  = sm + 1156;
        float* gs  = sm + 1190;
        float* bts = sm + 1224;
        for (int i = tid; i < Dm * Dm; i += 256) ws[i] = opw2[i];
        if (tid < Dm) { bs[tid] = opb2[tid]; gs[tid] = g12[tid]; bts[tid] = b12[tid]; }
        __syncthreads();
        if (tid < HW) {
            int s = g_agent * HW + tid;
            float orow[Dm], y[Dm];
#pragma unroll
            for (int d = 0; d < Dm; d++) orow[d] = g_oa[tid * Dm + d];
#pragma unroll 2
            for (int d = 0; d < Dm; d++) {
                float a = bs[d] + g_x[s * Dm + d];
                const float* wp = ws + d * Dm;
#pragma unroll
                for (int k = 0; k < Dm; k++) a = fmaf(orow[k], wp[k], a);
                y[d] = a;
            }
            float m = 0.f;
#pragma unroll
            for (int d = 0; d < Dm; d++) m += y[d];
            m *= (1.0f / Dm);
            float v = 0.f;
#pragma unroll
            for (int d = 0; d < Dm; d++) { float tt = y[d] - m; v = fmaf(tt, tt, v); }
            v *= (1.0f / Dm);
            float inv = rsqrtf(v + EPSV);
#pragma unroll
            for (int d = 0; d < Dm; d++) g_xa[tid * Dm + d] = (y[d] - m) * inv * gs[d] + bts[d];
        }
    }
    gsync(ls);  // 3

    // P4: agent FFN partials (blocks 0..31)
    if (b < NFSEG2) {
        float* W1s = sm;            // 2304
        float* W2s = sm + 2304;     // 2304
        float* b1s = sm + 4608;     // 64
        int fbase = b * FSEG2;
        for (int e = tid; e < FSEG2 * Dm; e += 256) {
            int f = e / Dm, d = e % Dm;
            W1s[f * 36 + d] = l1w2[(fbase + f) * Dm + d];
            W2s[f * 36 + d] = l2w2[d * FFd + fbase + f];
        }
        if (tid < FSEG2) b1s[tid] = l1b2[fbase + tid];
        __syncthreads();
        if (tid < HW) {
            u64 xr[17], y[17];
            const u64* p = (const u64*)(g_xa + tid * Dm);
#pragma unroll
            for (int i = 0; i < 17; i++) { xr[i] = p[i]; y[i] = 0ULL; }
#pragma unroll 2
            for (int f = 0; f < FSEG2; f++) {
                const ulonglong2* w2p = (const ulonglong2*)(W1s + f * 36);
                const u64*        w1p = (const u64*)(W1s + f * 36);
                ulonglong2 a0 = w2p[0], a1 = w2p[1], a2 = w2p[2], a3 = w2p[3];
                ulonglong2 a4 = w2p[4], a5 = w2p[5], a6 = w2p[6], a7 = w2p[7];
                u64 a16 = w1p[16];
                u64 t0 = mul2(xr[0], a0.x),  t1 = mul2(xr[1], a0.y);
                t0 = fma2(xr[2], a1.x, t0);  t1 = fma2(xr[3], a1.y, t1);
                t0 = fma2(xr[4], a2.x, t0);  t1 = fma2(xr[5], a2.y, t1);
                t0 = fma2(xr[6], a3.x, t0);  t1 = fma2(xr[7], a3.y, t1);
                t0 = fma2(xr[8], a4.x, t0);  t1 = fma2(xr[9], a4.y, t1);
                t0 = fma2(xr[10], a5.x, t0); t1 = fma2(xr[11], a5.y, t1);
                t0 = fma2(xr[12], a6.x, t0); t1 = fma2(xr[13], a6.y, t1);
                t0 = fma2(xr[14], a7.x, t0); t1 = fma2(xr[15], a7.y, t1);
                t0 = fma2(xr[16], a16, t0);
                t0 = add2(t0, t1);
                float2 fh = unpk(t0);
                float hrelu = fmaxf(fh.x + fh.y + b1s[f], 0.f);
                u64 hp = pk(hrelu, hrelu);
                const ulonglong2* v2p = (const ulonglong2*)(W2s + f * 36);
                const u64*        v1p = (const u64*)(W2s + f * 36);
                ulonglong2 b0 = v2p[0], b1v = v2p[1], b2v = v2p[2], b3 = v2p[3];
                ulonglong2 b4 = v2p[4], b5 = v2p[5], b6 = v2p[6], b7 = v2p[7];
                u64 b16 = v1p[16];
                y[0]  = fma2(hp, b0.x, y[0]);   y[1]  = fma2(hp, b0.y, y[1]);
                y[2]  = fma2(hp, b1v.x, y[2]);  y[3]  = fma2(hp, b1v.y, y[3]);
                y[4]  = fma2(hp, b2v.x, y[4]);  y[5]  = fma2(hp, b2v.y, y[5]);
                y[6]  = fma2(hp, b3.x, y[6]);   y[7]  = fma2(hp, b3.y, y[7]);
                y[8]  = fma2(hp, b4.x, y[8]);   y[9]  = fma2(hp, b4.y, y[9]);
                y[10] = fma2(hp, b5.x, y[10]);  y[11] = fma2(hp, b5.y, y[11]);
                y[12] = fma2(hp, b6.x, y[12]);  y[13] = fma2(hp, b6.y, y[13]);
                y[14] = fma2(hp, b7.x, y[14]);  y[15] = fma2(hp, b7.y, y[15]);
                y[16] = fma2(hp, b16, y[16]);
            }
            u64* yo = (u64*)(g_ypa + ((size_t)b * HW + tid) * Dm);
#pragma unroll
            for (int i = 0; i < 17; i++) yo[i] = y[i];
        }
    }
    gsync(ls);  // 4

    // P5: agent FFN reduce + LN + final mean -> out (block 0)
    if (b == 0) {
        float* rows = sm;   // 2754
        if (tid < HW) {
            float y[Dm];
#pragma unroll
            for (int d = 0; d < Dm; d++) y[d] = g_xa[tid * Dm + d] + l2b2[d];
            for (int g = 0; g < NFSEG2; g++) {
                const float* yp = g_ypa + ((size_t)g * HW + tid) * Dm;
#pragma unroll
                for (int d = 0; d < Dm; d++) y[d] += yp[d];
            }
            float m = 0.f;
#pragma unroll
            for (int d = 0; d < Dm; d++) m += y[d];
            m *= (1.0f / Dm);
            float v = 0.f;
#pragma unroll
            for (int d = 0; d < Dm; d++) { float tt = y[d] - m; v = fmaf(tt, tt, v); }
            v *= (1.0f / Dm);
            float inv = rsqrtf(v + EPSV);
#pragma unroll
            for (int d = 0; d < Dm; d++) rows[tid * Dm + d] = (y[d] - m) * inv * g22[d] + b22[d];
        }
        __syncthreads();
        if (tid < Dm) {
            float s = 0.f;
            for (int r = 0; r < HW; r++) s += rows[r * Dm + tid];
            out[tid] = s * (1.0f / 81.0f);
        }
    }
}

// ---------------------------------------------------------------------------
extern "C" void kernel_launch(void* const* d_in, const int* in_sizes, int n_in,
                              void* d_out, int out_size) {
    const float* obs = (const float*)d_in[0];
    const float* c1w = (const float*)d_in[1];
    const float* c1b = (const float*)d_in[2];
    const float* c2w = (const float*)d_in[3];
    const float* c2b = (const float*)d_in[4];
    const float* ipw = (const float*)d_in[5];
    const float* ipb = (const float*)d_in[6];
    const float* opw = (const float*)d_in[7];
    const float* opb = (const float*)d_in[8];
    const float* l1w = (const float*)d_in[9];
    const float* l1b = (const float*)d_in[10];
    const float* l2w = (const float*)d_in[11];
    const float* l2b = (const float*)d_in[12];
    const float* g1  = (const float*)d_in[13];
    const float* b1  = (const float*)d_in[14];
    const float* g2  = (const float*)d_in[15];
    const float* b2  = (const float*)d_in[16];
    float* out = (float*)d_out;

    front<<<148, 256>>>(obs, c1w, c1b, c2w, c2b, ipw, ipb);
    attn_struct<<<dim3(HW, NH), 512>>>();
    tokens_proj_ln<<<(S + 63) / 64, 128>>>(opw, opb, g1, b1);
    ffn0<<<dim3((S + 127) / 128, 1, NFSEG), 128>>>(l1w, l1b, l2w);
    ffnred_qkv<<<(S + 31) / 32, 256>>>(ipw + 102 * Dm, ipb + 102, l2b, g2, b2);
    agent_tail<<<148, 256>>>(opw + Dm * Dm, opb + Dm, g1 + Dm, b1 + Dm,
                             l1w + FFd * Dm, l1b + FFd, l2w + Dm * FFd, l2b + Dm,
                             g2 + Dm, b2 + Dm, out);
}

// round 10
// speedup vs baseline: 3.8722x; 1.0236x over previous
#include <cuda_runtime.h>

#define S      6561
#define Dm     34
#define HD     17
#define PH     20
#define PAC    18
#define FFd    2048
#define NH     2
#define HW     81
#define EPSV   1e-5f
#define ESTR   (NH * HW * HW)
// layer-0 FFN tiling
#define NFSEG  8
#define FSEG   256
#define FCHK0  64
// layer-1 agent attention: 2 heads x 74 segs = 148 blocks
#define NSEG2  74
#define KSEG2  89
// agent FFN split
#define NFSEG2 32
#define FSEG2  64

typedef unsigned long long u64;

// ---- packed fp32 helpers ----
__device__ __forceinline__ u64 fma2(u64 a, u64 b, u64 c) {
    u64 d; asm("fma.rn.f32x2 %0, %1, %2, %3;" : "=l"(d) : "l"(a), "l"(b), "l"(c)); return d;
}
__device__ __forceinline__ u64 mul2(u64 a, u64 b) {
    u64 d; asm("mul.rn.f32x2 %0, %1, %2;" : "=l"(d) : "l"(a), "l"(b)); return d;
}
__device__ __forceinline__ u64 add2(u64 a, u64 b) {
    u64 d; asm("add.rn.f32x2 %0, %1, %2;" : "=l"(d) : "l"(a), "l"(b)); return d;
}
__device__ __forceinline__ float2 unpk(u64 v) {
    float2 f; asm("mov.b64 {%0, %1}, %2;" : "=f"(f.x), "=f"(f.y) : "l"(v)); return f;
}
__device__ __forceinline__ u64 pk(float x, float y) {
    u64 v; asm("mov.b64 %0, {%1, %2};" : "=l"(v) : "f"(x), "f"(y)); return v;
}

// ---- device-global scratch ----
__device__ unsigned g_cnt;
__device__ unsigned g_sense;
__device__ int   g_agent;
__device__ __align__(16) float g_emb[HW * 16];
__device__ __align__(16) float g_x[S * Dm];
__device__ __align__(16) float g_q[NH * S * PH];
__device__ __align__(16) float g_k[NH * S * PH];
__device__ __align__(16) float g_v[NH * S * PH];
__device__ __align__(16) float g_o[S * Dm];
__device__ __align__(16) float g_yp[NFSEG * S * Dm];
__device__ __align__(16) float g_QA[NH * HW * HD];
__device__ __align__(16) float g_QB[NH * HW * HD];
__device__ __align__(16) float g_KA[NH * HW * HD];
__device__ __align__(16) float g_KB[NH * HW * HD];
__device__ __align__(16) float g_VA[NH * HW * HD];
__device__ __align__(16) float g_VB[NH * HW * HD];
__device__ __align__(16) float g_E[4 * ESTR];    // EA, EB row-major; EC, ED TRANSPOSED
__device__ __align__(16) float g_pacca[NH * NSEG2 * HW * PAC];
__device__ float g_psuma[NH * NSEG2 * HW];
__device__ __align__(16) float g_xa[HW * Dm];
__device__ __align__(16) float g_ypa[NFSEG2 * HW * Dm];
__device__ __align__(16) float g_oa[HW * Dm];

// ---- sense-reversing grid barrier (all blocks resident) ----
__device__ __forceinline__ void gsync(unsigned& ls) {
    __syncthreads();
    if (threadIdx.x == 0) {
        unsigned ns = ls ^ 1u;
        __threadfence();
        unsigned old = atomicAdd(&g_cnt, 1u);
        if (old == gridDim.x - 1u) {
            g_cnt = 0u;
            __threadfence();
            atomicExch(&g_sense, ns);
        } else {
            while (atomicAdd(&g_sense, 0u) != ns) { __nanosleep(64); }
        }
        ls = ns;
        __threadfence();
    }
    __syncthreads();
}

// ---------------------------------------------------------------------------
// K1 (fused front): conv+argmax -> basis QKV -> exp(logits). grid 148x256.
// ---------------------------------------------------------------------------
__global__ void __launch_bounds__(256) front(
    const float* __restrict__ obs,
    const float* __restrict__ c1w, const float* __restrict__ c1b,
    const float* __restrict__ c2w, const float* __restrict__ c2b,
    const float* __restrict__ ipw, const float* __restrict__ ipb)
{
    __shared__ float so[192];
    __shared__ float c1s[1296];
    int tid = threadIdx.x;
    int b = blockIdx.x;
    unsigned ls = 0;

    if (b == 0) {
        for (int i = tid; i < 162; i += 256) so[i] = obs[i];
        __syncthreads();
        if (tid == 0) {
            float mx = so[0]; int mi = 0;
            for (int i = 1; i < 81; i++) if (so[i] > mx) { mx = so[i]; mi = i; }
            g_agent = mi;
        }
        for (int idx = tid; idx < 16 * 81; idx += 256) {
            int ch = idx / 81, pos = idx % 81, r = pos / 9, c = pos % 9;
            float acc = c1b[ch];
            for (int ci = 0; ci < 2; ci++)
                for (int dr = 0; dr < 3; dr++) {
                    int rr = r + dr - 1; if (rr < 0 || rr >= 9) continue;
                    for (int dc = 0; dc < 3; dc++) {
                        int cc = c + dc - 1; if (cc < 0 || cc >= 9) continue;
                        acc += so[ci * 81 + rr * 9 + cc] * c1w[((ch * 2 + ci) * 3 + dr) * 3 + dc];
                    }
                }
            c1s[idx] = fmaxf(acc, 0.f);
        }
        __syncthreads();
        for (int idx = tid; idx < 16 * 81; idx += 256) {
            int ch = idx / 81, pos = idx % 81, r = pos / 9, c = pos % 9;
            float acc = c2b[ch];
            for (int ci = 0; ci < 16; ci++)
                for (int dr = 0; dr < 3; dr++) {
                    int rr = r + dr - 1; if (rr < 0 || rr >= 9) continue;
                    for (int dc = 0; dc < 3; dc++) {
                        int cc = c + dc - 1; if (cc < 0 || cc >= 9) continue;
                        acc += c1s[ci * 81 + rr * 9 + cc] * c2w[((ch * 16 + ci) * 3 + dr) * 3 + dc];
                    }
                }
            g_emb[pos * 16 + ch] = fmaxf(acc, 0.f);
        }
    }
    gsync(ls);  // 1

    for (int idx = b * 256 + tid; idx < 162 * 102; idx += 148 * 256) {
        int v = idx / 102, c = idx % 102;
        const float* wr = ipw + c * Dm;
        float acc;
        if (v < 81) {
            int i = v;
            acc = ipb[c];
#pragma unroll
            for (int d = 0; d < 16; d++) acc = fmaf(g_emb[i * 16 + d], wr[d], acc);
            acc = fmaf((float)(i / 9) * 0.25f, wr[32], acc);
            acc = fmaf((float)(i % 9) * 0.25f, wr[33], acc);
        } else {
            int j = v - 81;
            acc = 0.f;
#pragma unroll
            for (int d = 0; d < 16; d++) acc = fmaf(g_emb[j * 16 + d], wr[16 + d], acc);
            acc = fmaf(-(float)(j / 9) * 0.25f, wr[32], acc);
            acc = fmaf(-(float)(j % 9) * 0.25f, wr[33], acc);
        }
        int kind = c / Dm;
        int cc = c % Dm;
        int h = cc / HD, dd = cc % HD;
        int off = (h * HW + (v % 81)) * HD + dd;
        if (kind == 0) {
            float sv = acc * rsqrtf(17.f);
            if (v < 81) g_QA[off] = sv; else g_QB[off] = sv;
        } else if (kind == 1) {
            if (v < 81) g_KA[off] = acc; else g_KB[off] = acc;
        } else {
            if (v < 81) g_VA[off] = acc; else g_VB[off] = acc;
        }
    }
    gsync(ls);  // 2

    for (int idx = b * 256 + tid; idx < 4 * ESTR; idx += 148 * 256) {
        int p = idx / ESTR;
        int r = idx % ESTR;
        int h = r / (HW * HW);
        int q2 = r % (HW * HW);
        int i = q2 / HW, m = q2 % HW;
        const float* L;
        const float* R;
        if (p == 0)      { L = g_QA + (h * HW + i) * HD; R = g_KA + (h * HW + m) * HD; }
        else if (p == 1) { L = g_QA + (h * HW + i) * HD; R = g_KB + (h * HW + m) * HD; }
        else if (p == 2) { L = g_KA + (h * HW + i) * HD; R = g_QB + (h * HW + m) * HD; }
        else             { L = g_KB + (h * HW + i) * HD; R = g_QB + (h * HW + m) * HD; }
        float dot = 0.f;
#pragma unroll
        for (int d = 0; d < HD; d++) dot = fmaf(L[d], R[d], dot);
        g_E[idx] = __expf(dot);
    }
}

// ---------------------------------------------------------------------------
// K2: structured attention -> g_o (EC/ED transposed, coalesced)
// ---------------------------------------------------------------------------
__global__ void __launch_bounds__(512) attn_struct() {
    __shared__ float sea[HW], seb[HW];
    __shared__ __align__(16) float sva[HW * 18];
    __shared__ __align__(16) float svb[HW * 18];
    __shared__ float psum[4 * HW];
    __shared__ __align__(16) u64 pacc[4 * HW * 9];
    int tid = threadIdx.x;
    int i = blockIdx.x, h = blockIdx.y;
    for (int t = tid; t < HW; t += 512) {
        sea[t] = g_E[0 * ESTR + (h * HW + i) * HW + t];
        seb[t] = g_E[1 * ESTR + (h * HW + i) * HW + t];
    }
    for (int t = tid; t < HW * 18; t += 512) {
        int m = t / 18, d = t % 18;
        sva[t] = (d < HD) ? g_VA[(h * HW + m) * HD + d] : 0.f;
        svb[t] = (d < HD) ? g_VB[(h * HW + m) * HD + d] : 0.f;
    }
    __syncthreads();
    int quad = tid >> 7;
    int j = tid & 127;
    if (j < HW) {
        bool isA = quad < 2;
        int lo = (quad & 1) ? 41 : 0;
        int hi = (quad & 1) ? HW : 41;
        const float* et = g_E + (isA ? 2 : 3) * ESTR + h * HW * HW + j;
        const float* se = isA ? sea : seb;
        const float* sv = isA ? sva : svb;
        float z = 0.f;
        u64 w[9];
#pragma unroll
        for (int k = 0; k < 9; k++) w[k] = 0ULL;
#pragma unroll 4
        for (int m = lo; m < hi; m++) {
            float f = se[m] * et[m * HW];
            z += f;
            u64 fp = pk(f, f);
            const u64* vr = (const u64*)(sv + m * 18);
#pragma unroll
            for (int k = 0; k < 9; k++) w[k] = fma2(fp, vr[k], w[k]);
        }
        psum[quad * HW + j] = z;
        u64* pw = pacc + (quad * HW + j) * 9;
#pragma unroll
        for (int k = 0; k < 9; k++) pw[k] = w[k];
    }
    __syncthreads();
    if (tid < HW) {
        int jj = tid;
        float zm = psum[jj] + psum[HW + jj];
        float zn = psum[2 * HW + jj] + psum[3 * HW + jj];
        const u64* p0 = pacc + jj * 9;
        const u64* p1 = pacc + (HW + jj) * 9;
        const u64* p2 = pacc + (2 * HW + jj) * 9;
        const u64* p3 = pacc + (3 * HW + jj) * 9;
        float inv = 1.0f / (zm * zn);
        float* od = g_o + (i * HW + jj) * Dm + h * HD;
#pragma unroll
        for (int k = 0; k < 9; k++) {
            float2 A = unpk(add2(p0[k], p1[k]));
            float2 B = unpk(add2(p2[k], p3[k]));
            int d = 2 * k;
            od[d] = (A.x * zn + B.x * zm) * inv;
            if (d + 1 < HD) od[d + 1] = (A.y * zn + B.y * zm) * inv;
        }
    }
}

// ---------------------------------------------------------------------------
// K3: tokens + out_proj + residual + LN1 -> g_x
// ---------------------------------------------------------------------------
__global__ void __launch_bounds__(128) tokens_proj_ln(const float* __restrict__ opw,
                                                      const float* __restrict__ opb,
                                                      const float* __restrict__ gg,
                                                      const float* __restrict__ bb) {
    __shared__ float embs[1296];
    __shared__ float ws[Dm * Dm];
    __shared__ float bs[Dm], gs[Dm], bts[Dm];
    __shared__ float ys[64 * 36];
    int tid = threadIdx.x;
    for (int i = tid; i < 1296; i += 128) embs[i] = g_emb[i];
    for (int i = tid; i < Dm * Dm; i += 128) ws[i] = opw[i];
    if (tid < Dm) { bs[tid] = opb[tid]; gs[tid] = gg[tid]; bts[tid] = bb[tid]; }
    __syncthreads();
    int half = tid >> 6;
    int lt = tid & 63;
    int t = blockIdx.x * 64 + lt;
    if (t < S) {
        int i = t / HW, j = t % HW;
        float orow[Dm];
#pragma unroll
        for (int d = 0; d < Dm; d++) orow[d] = g_o[t * Dm + d];
        int dlo = half * 17;
#pragma unroll 1
        for (int d = dlo; d < dlo + 17; d++) {
            float xv;
            if (d < 16)       xv = embs[i * 16 + d];
            else if (d < 32)  xv = embs[j * 16 + (d - 16)];
            else if (d == 32) xv = ((float)(i / 9) - (float)(j / 9)) * 0.25f;
            else              xv = ((float)(i % 9) - (float)(j % 9)) * 0.25f;
            float a = bs[d] + xv;
            const float* wp = ws + d * Dm;
#pragma unroll
            for (int k = 0; k < Dm; k++) a = fmaf(orow[k], wp[k], a);
            ys[lt * 36 + d] = a;
        }
    }
    __syncthreads();
    if (half == 0 && t < S) {
        float y[Dm];
#pragma unroll
        for (int d = 0; d < Dm; d++) y[d] = ys[lt * 36 + d];
        float m = 0.f;
#pragma unroll
        for (int d = 0; d < Dm; d++) m += y[d];
        m *= (1.0f / Dm);
        float v = 0.f;
#pragma unroll
        for (int d = 0; d < Dm; d++) { float tt = y[d] - m; v = fmaf(tt, tt, v); }
        v *= (1.0f / Dm);
        float inv = rsqrtf(v + EPSV);
#pragma unroll
        for (int d = 0; d < Dm; d++) g_x[t * Dm + d] = (y[d] - m) * inv * gs[d] + bts[d];
    }
}

// ---------------------------------------------------------------------------
// K4: layer-0 FFN partials — 2 rows/thread, 64-thread blocks, 4 blocks/SM.
// Weight LDS amortized over 2 rows (smem-crossbar was the R9 bottleneck).
// grid (52, 1, 8): 128 rows per block x 8 f-segments.
// ---------------------------------------------------------------------------
__global__ void __launch_bounds__(64, 4) ffn0(const float* __restrict__ l1w,
                                              const float* __restrict__ l1b,
                                              const float* __restrict__ l2w) {
    __shared__ __align__(16) float W1s[FCHK0 * 36];
    __shared__ __align__(16) float W2s[FCHK0 * 36];
    __shared__ float b1s[FCHK0];
    int tid = threadIdx.x;
    int row0 = blockIdx.x * 128 + tid;
    int row1 = row0 + 64;
    int fbase = blockIdx.z * FSEG;
    bool a0 = row0 < S, a1 = row1 < S;
    u64 x0[17], x1[17], y0[17], y1[17];
#pragma unroll
    for (int i = 0; i < 17; i++) { x0[i] = 0ULL; x1[i] = 0ULL; y0[i] = 0ULL; y1[i] = 0ULL; }
    if (a0) {
        const u64* p = (const u64*)(g_x + row0 * Dm);
#pragma unroll
        for (int i = 0; i < 17; i++) x0[i] = p[i];
    }
    if (a1) {
        const u64* p = (const u64*)(g_x + row1 * Dm);
#pragma unroll
        for (int i = 0; i < 17; i++) x1[i] = p[i];
    }
    for (int fc = fbase; fc < fbase + FSEG; fc += FCHK0) {
        for (int e = tid; e < FCHK0 * Dm; e += 64) {
            int f = e / Dm, d = e % Dm;
            W1s[f * 36 + d] = l1w[(fc + f) * Dm + d];
            W2s[f * 36 + d] = l2w[d * FFd + fc + f];
        }
        if (tid < FCHK0) b1s[tid] = l1b[fc + tid];
        __syncthreads();
#pragma unroll 2
        for (int f = 0; f < FCHK0; f++) {
            const ulonglong2* w2p = (const ulonglong2*)(W1s + f * 36);
            const u64*        w1p = (const u64*)(W1s + f * 36);
            ulonglong2 a0v = w2p[0], a1v = w2p[1], a2v = w2p[2], a3v = w2p[3];
            ulonglong2 a4v = w2p[4], a5v = w2p[5], a6v = w2p[6], a7v = w2p[7];
            u64 a16 = w1p[16];
            u64 t0 = mul2(x0[0], a0v.x),  t1 = mul2(x0[1], a0v.y);
            u64 u0 = mul2(x1[0], a0v.x),  u1 = mul2(x1[1], a0v.y);
            t0 = fma2(x0[2], a1v.x, t0);  t1 = fma2(x0[3], a1v.y, t1);
            u0 = fma2(x1[2], a1v.x, u0);  u1 = fma2(x1[3], a1v.y, u1);
            t0 = fma2(x0[4], a2v.x, t0);  t1 = fma2(x0[5], a2v.y, t1);
            u0 = fma2(x1[4], a2v.x, u0);  u1 = fma2(x1[5], a2v.y, u1);
            t0 = fma2(x0[6], a3v.x, t0);  t1 = fma2(x0[7], a3v.y, t1);
            u0 = fma2(x1[6], a3v.x, u0);  u1 = fma2(x1[7], a3v.y, u1);
            t0 = fma2(x0[8], a4v.x, t0);  t1 = fma2(x0[9], a4v.y, t1);
            u0 = fma2(x1[8], a4v.x, u0);  u1 = fma2(x1[9], a4v.y, u1);
            t0 = fma2(x0[10], a5v.x, t0); t1 = fma2(x0[11], a5v.y, t1);
            u0 = fma2(x1[10], a5v.x, u0); u1 = fma2(x1[11], a5v.y, u1);
            t0 = fma2(x0[12], a6v.x, t0); t1 = fma2(x0[13], a6v.y, t1);
            u0 = fma2(x1[12], a6v.x, u0); u1 = fma2(x1[13], a6v.y, u1);
            t0 = fma2(x0[14], a7v.x, t0); t1 = fma2(x0[15], a7v.y, t1);
            u0 = fma2(x1[14], a7v.x, u0); u1 = fma2(x1[15], a7v.y, u1);
            t0 = fma2(x0[16], a16, t0);
            u0 = fma2(x1[16], a16, u0);
            t0 = add2(t0, t1);
            u0 = add2(u0, u1);
            float2 fh0 = unpk(t0), fh1 = unpk(u0);
            float h0 = fmaxf(fh0.x + fh0.y + b1s[f], 0.f);
            float h1 = fmaxf(fh1.x + fh1.y + b1s[f], 0.f);
            u64 hp0 = pk(h0, h0), hp1 = pk(h1, h1);
            const ulonglong2* v2p = (const ulonglong2*)(W2s + f * 36);
            const u64*        v1p = (const u64*)(W2s + f * 36);
            ulonglong2 b0v = v2p[0], b1v = v2p[1], b2v = v2p[2], b3v = v2p[3];
            ulonglong2 b4v = v2p[4], b5v = v2p[5], b6v = v2p[6], b7v = v2p[7];
            u64 b16 = v1p[16];
            y0[0]  = fma2(hp0, b0v.x, y0[0]);   y1[0]  = fma2(hp1, b0v.x, y1[0]);
            y0[1]  = fma2(hp0, b0v.y, y0[1]);   y1[1]  = fma2(hp1, b0v.y, y1[1]);
            y0[2]  = fma2(hp0, b1v.x, y0[2]);   y1[2]  = fma2(hp1, b1v.x, y1[2]);
            y0[3]  = fma2(hp0, b1v.y, y0[3]);   y1[3]  = fma2(hp1, b1v.y, y1[3]);
            y0[4]  = fma2(hp0, b2v.x, y0[4]);   y1[4]  = fma2(hp1, b2v.x, y1[4]);
            y0[5]  = fma2(hp0, b2v.y, y0[5]);   y1[5]  = fma2(hp1, b2v.y, y1[5]);
            y0[6]  = fma2(hp0, b3v.x, y0[6]);   y1[6]  = fma2(hp1, b3v.x, y1[6]);
            y0[7]  = fma2(hp0, b3v.y, y0[7]);   y1[7]  = fma2(hp1, b3v.y, y1[7]);
            y0[8]  = fma2(hp0, b4v.x, y0[8]);   y1[8]  = fma2(hp1, b4v.x, y1[8]);
            y0[9]  = fma2(hp0, b4v.y, y0[9]);   y1[9]  = fma2(hp1, b4v.y, y1[9]);
            y0[10] = fma2(hp0, b5v.x, y0[10]);  y1[10] = fma2(hp1, b5v.x, y1[10]);
            y0[11] = fma2(hp0, b5v.y, y0[11]);  y1[11] = fma2(hp1, b5v.y, y1[11]);
            y0[12] = fma2(hp0, b6v.x, y0[12]);  y1[12] = fma2(hp1, b6v.x, y1[12]);
            y0[13] = fma2(hp0, b6v.y, y0[13]);  y1[13] = fma2(hp1, b6v.y, y1[13]);
            y0[14] = fma2(hp0, b7v.x, y0[14]);  y1[14] = fma2(hp1, b7v.x, y1[14]);
            y0[15] = fma2(hp0, b7v.y, y0[15]);  y1[15] = fma2(hp1, b7v.y, y1[15]);
            y0[16] = fma2(hp0, b16, y0[16]);    y1[16] = fma2(hp1, b16, y1[16]);
        }
        __syncthreads();
    }
    if (a0) {
        u64* yo = (u64*)(g_yp + ((size_t)blockIdx.z * S + row0) * Dm);
#pragma unroll
        for (int i = 0; i < 17; i++) yo[i] = y0[i];
    }
    if (a1) {
        u64* yo = (u64*)(g_yp + ((size_t)blockIdx.z * S + row1) * Dm);
#pragma unroll
        for (int i = 0; i < 17; i++) yo[i] = y1[i];
    }
}

// ---------------------------------------------------------------------------
// K5: FFN reduce + LN2 + layer-1 QKV fused
// ---------------------------------------------------------------------------
__global__ void __launch_bounds__(256) ffnred_qkv(const float* __restrict__ ipw2,
                                                  const float* __restrict__ ipb2,
                                                  const float* __restrict__ l2b,
                                                  const float* __restrict__ gg,
                                                  const float* __restrict__ bb) {
    __shared__ float xs[Dm * 32];
    __shared__ float ws[102 * Dm];
    __shared__ float bs[102];
    __shared__ __align__(16) float pre[32 * 36];
    __shared__ float l2bs[Dm], gs[Dm], bts[Dm];
    int tid = threadIdx.x;
    int row0 = blockIdx.x * 32;
    for (int i = tid; i < 102 * Dm; i += 256) ws[i] = ipw2[i];
    if (tid < 102) bs[tid] = ipb2[tid];
    if (tid < Dm) { l2bs[tid] = l2b[tid]; gs[tid] = gg[tid]; bts[tid] = bb[tid]; }
    for (int e = tid; e < 32 * 17; e += 256) {
        int r = e / 17, k = e % 17;
        int row = row0 + r;
        if (row < S) {
            u64 acc = ((const u64*)(g_x + row * Dm))[k];
#pragma unroll
            for (int g = 0; g < NFSEG; g++)
                acc = add2(acc, ((const u64*)(g_yp + ((size_t)g * S + row) * Dm))[k]);
            ((u64*)(pre + r * 36))[k] = acc;
        }
    }
    __syncthreads();
    if (tid < 32 && row0 + tid < S) {
        float y[Dm];
#pragma unroll
        for (int d = 0; d < Dm; d++) y[d] = pre[tid * 36 + d] + l2bs[d];
        float m = 0.f;
#pragma unroll
        for (int d = 0; d < Dm; d++) m += y[d];
        m *= (1.0f / Dm);
        float v = 0.f;
#pragma unroll
        for (int d = 0; d < Dm; d++) { float tt = y[d] - m; v = fmaf(tt, tt, v); }
        v *= (1.0f / Dm);
        float inv = rsqrtf(v + EPSV);
        int row = row0 + tid;
#pragma unroll
        for (int d = 0; d < Dm; d++) {
            float xv = (y[d] - m) * inv * gs[d] + bts[d];
            xs[d * 32 + tid] = xv;
            g_x[row * Dm + d] = xv;
        }
    }
    __syncthreads();
    const float scale = rsqrtf(17.f);
    int lane = tid & 31, w = tid >> 5;
    int s = row0 + lane;
    for (int cc = w; cc < 102; cc += 8) {
        float acc = bs[cc];
        const float* wp = ws + cc * Dm;
#pragma unroll
        for (int d = 0; d < Dm; d++) acc = fmaf(xs[d * 32 + lane], wp[d], acc);
        if (s < S) {
            int kind = cc / Dm;
            int c2 = cc % Dm;
            int h = c2 / HD, dd = c2 % HD;
            int off = (h * S + s) * PH + dd;
            if (kind == 0)      g_q[off] = acc * scale;
            else if (kind == 1) g_k[off] = acc;
            else                g_v[off] = acc;
        }
    }
}

// ---------------------------------------------------------------------------
// K6 (fused agent tail)
// ---------------------------------------------------------------------------
__global__ void __launch_bounds__(256) agent_tail(
    const float* __restrict__ opw2, const float* __restrict__ opb2,
    const float* __restrict__ g12,  const float* __restrict__ b12,
    const float* __restrict__ l1w2, const float* __restrict__ l1b2,
    const float* __restrict__ l2w2, const float* __restrict__ l2b2,
    const float* __restrict__ g22,  const float* __restrict__ b22,
    float* __restrict__ out)
{
    __shared__ __align__(16) float sm[4800];
    int tid = threadIdx.x;
    int b = blockIdx.x;
    unsigned ls = 0;

    {
        int h = b / NSEG2;
        int seg = b % NSEG2;
        int k0 = seg * KSEG2;
        int n = min(KSEG2, S - k0);
        float* Ks = sm;
        float* Vs = sm + 1800;
        const float4* ksrc = (const float4*)(g_k + (h * S + k0) * PH);
        const float4* vsrc = (const float4*)(g_v + (h * S + k0) * PH);
        float4* kdst = (float4*)Ks; float4* vdst = (float4*)Vs;
        for (int i = tid; i < n * 5; i += 256) { kdst[i] = ksrc[i]; vdst[i] = vsrc[i]; }
        __syncthreads();
        if (tid < HW) {
            int start = g_agent * HW;
            u64 q[9], acc[9];
            const u64* qp = (const u64*)(g_q + (h * S + start + tid) * PH);
#pragma unroll
            for (int i = 0; i < 9; i++) { q[i] = qp[i]; acc[i] = 0ULL; }
            float ssum = 0.f;
            const ulonglong2* K2 = (const ulonglong2*)Ks;
            const ulonglong2* V2 = (const ulonglong2*)Vs;
            for (int kk = 0; kk < n; kk++) {
                ulonglong2 ka = K2[0], kb = K2[1], kc = K2[2], kd = K2[3];
                u64 ke = K2[4].x;
                u64 t0 = mul2(q[0], ka.x),  t1 = mul2(q[1], ka.y);
                t0 = fma2(q[2], kb.x, t0);  t1 = fma2(q[3], kb.y, t1);
                t0 = fma2(q[4], kc.x, t0);  t1 = fma2(q[5], kc.y, t1);
                t0 = fma2(q[6], kd.x, t0);  t1 = fma2(q[7], kd.y, t1);
                t0 = fma2(q[8], ke, t0);
                t0 = add2(t0, t1);
                float2 f = unpk(t0);
                float p = __expf(f.x + f.y);
                ssum += p;
                u64 pp = pk(p, p);
                ulonglong2 va = V2[0], vb = V2[1], vc = V2[2], vd = V2[3];
                u64 ve = V2[4].x;
                acc[0] = fma2(pp, va.x, acc[0]); acc[1] = fma2(pp, va.y, acc[1]);
                acc[2] = fma2(pp, vb.x, acc[2]); acc[3] = fma2(pp, vb.y, acc[3]);
                acc[4] = fma2(pp, vc.x, acc[4]); acc[5] = fma2(pp, vc.y, acc[5]);
                acc[6] = fma2(pp, vd.x, acc[6]); acc[7] = fma2(pp, vd.y, acc[7]);
                acc[8] = fma2(pp, ve, acc[8]);
                K2 += 5; V2 += 5;
            }
            u64* pa = (u64*)(g_pacca + ((h * NSEG2 + seg) * HW + tid) * PAC);
#pragma unroll
            for (int i = 0; i < 9; i++) pa[i] = acc[i];
            g_psuma[(h * NSEG2 + seg) * HW + tid] = ssum;
        }
    }
    gsync(ls);  // 1

    {
        int e = b * 256 + tid;
        if (b < 11 && e < HW * Dm) {
            int r = e / Dm, c = e % Dm;
            int h = c / HD, d = c % HD;
            float a = 0.f, smm = 0.f;
#pragma unroll 4
            for (int g = 0; g < NSEG2; g++) {
                a   += g_pacca[((h * NSEG2 + g) * HW + r) * PAC + d];
                smm += g_psuma[(h * NSEG2 + g) * HW + r];
            }
            g_oa[e] = a / smm;
        }
    }
    gsync(ls);  // 2

    if (b == 0) {
        float* ws  = sm;
        float* bs  = sm + 1156;
        float* gs  = sm + 1190;
        float* bts = sm + 1224;
        for (int i = tid; i < Dm * Dm; i += 256) ws[i] = opw2[i];
        if (tid < Dm) { bs[tid] = opb2[tid]; gs[tid] = g12[tid]; bts[tid] = b12[tid]; }
        __syncthreads();
        if (tid < HW) {
            int s = g_agent * HW + tid;
            float orow[Dm], y[Dm];
#pragma unroll
            for (int d = 0; d < Dm; d++) orow[d] = g_oa[tid * Dm + d];
#pragma unroll 2
            for (int d = 0; d < Dm; d++) {
                float a = bs[d] + g_x[s * Dm + d];
                const float* wp = ws + d * Dm;
#pragma unroll
                for (int k = 0; k < Dm; k++) a = fmaf(orow[k], wp[k], a);
                y[d] = a;
            }
            float m = 0.f;
#pragma unroll
            for (int d = 0; d < Dm; d++) m += y[d];
            m *= (1.0f / Dm);
            float v = 0.f;
#pragma unroll
            for (int d = 0; d < Dm; d++) { float tt = y[d] - m; v = fmaf(tt, tt, v); }
            v *= (1.0f / Dm);
            float inv = rsqrtf(v + EPSV);
#pragma unroll
            for (int d = 0; d < Dm; d++) g_xa[tid * Dm + d] = (y[d] - m) * inv * gs[d] + bts[d];
        }
    }
    gsync(ls);  // 3

    if (b < NFSEG2) {
        float* W1s = sm;
        float* W2s = sm + 2304;
        float* b1s = sm + 4608;
        int fbase = b * FSEG2;
        for (int e = tid; e < FSEG2 * Dm; e += 256) {
            int f = e / Dm, d = e % Dm;
            W1s[f * 36 + d] = l1w2[(fbase + f) * Dm + d];
            W2s[f * 36 + d] = l2w2[d * FFd + fbase + f];
        }
        if (tid < FSEG2) b1s[tid] = l1b2[fbase + tid];
        __syncthreads();
        if (tid < HW) {
            u64 xr[17], y[17];
            const u64* p = (const u64*)(g_xa + tid * Dm);
#pragma unroll
            for (int i = 0; i < 17; i++) { xr[i] = p[i]; y[i] = 0ULL; }
#pragma unroll 2
            for (int f = 0; f < FSEG2; f++) {
                const ulonglong2* w2p = (const ulonglong2*)(W1s + f * 36);
                const u64*        w1p = (const u64*)(W1s + f * 36);
                ulonglong2 a0 = w2p[0], a1 = w2p[1], a2 = w2p[2], a3 = w2p[3];
                ulonglong2 a4 = w2p[4], a5 = w2p[5], a6 = w2p[6], a7 = w2p[7];
                u64 a16 = w1p[16];
                u64 t0 = mul2(xr[0], a0.x),  t1 = mul2(xr[1], a0.y);
                t0 = fma2(xr[2], a1.x, t0);  t1 = fma2(xr[3], a1.y, t1);
                t0 = fma2(xr[4], a2.x, t0);  t1 = fma2(xr[5], a2.y, t1);
                t0 = fma2(xr[6], a3.x, t0);  t1 = fma2(xr[7], a3.y, t1);
                t0 = fma2(xr[8], a4.x, t0);  t1 = fma2(xr[9], a4.y, t1);
                t0 = fma2(xr[10], a5.x, t0); t1 = fma2(xr[11], a5.y, t1);
                t0 = fma2(xr[12], a6.x, t0); t1 = fma2(xr[13], a6.y, t1);
                t0 = fma2(xr[14], a7.x, t0); t1 = fma2(xr[15], a7.y, t1);
                t0 = fma2(xr[16], a16, t0);
                t0 = add2(t0, t1);
                float2 fh = unpk(t0);
                float hrelu = fmaxf(fh.x + fh.y + b1s[f], 0.f);
                u64 hp = pk(hrelu, hrelu);
                const ulonglong2* v2p = (const ulonglong2*)(W2s + f * 36);
                const u64*        v1p = (const u64*)(W2s + f * 36);
                ulonglong2 b0 = v2p[0], b1v = v2p[1], b2v = v2p[2], b3 = v2p[3];
                ulonglong2 b4 = v2p[4], b5 = v2p[5], b6 = v2p[6], b7 = v2p[7];
                u64 b16 = v1p[16];
                y[0]  = fma2(hp, b0.x, y[0]);   y[1]  = fma2(hp, b0.y, y[1]);
                y[2]  = fma2(hp, b1v.x, y[2]);  y[3]  = fma2(hp, b1v.y, y[3]);
                y[4]  = fma2(hp, b2v.x, y[4]);  y[5]  = fma2(hp, b2v.y, y[5]);
                y[6]  = fma2(hp, b3.x, y[6]);   y[7]  = fma2(hp, b3.y, y[7]);
                y[8]  = fma2(hp, b4.x, y[8]);   y[9]  = fma2(hp, b4.y, y[9]);
                y[10] = fma2(hp, b5.x, y[10]);  y[11] = fma2(hp, b5.y, y[11]);
                y[12] = fma2(hp, b6.x, y[12]);  y[13] = fma2(hp, b6.y, y[13]);
                y[14] = fma2(hp, b7.x, y[14]);  y[15] = fma2(hp, b7.y, y[15]);
                y[16] = fma2(hp, b16, y[16]);
            }
            u64* yo = (u64*)(g_ypa + ((size_t)b * HW + tid) * Dm);
#pragma unroll
            for (int i = 0; i < 17; i++) yo[i] = y[i];
        }
    }
    gsync(ls);  // 4

    if (b == 0) {
        float* rows = sm;
        if (tid < HW) {
            float y[Dm];
#pragma unroll
            for (int d = 0; d < Dm; d++) y[d] = g_xa[tid * Dm + d] + l2b2[d];
            for (int g = 0; g < NFSEG2; g++) {
                const float* yp = g_ypa + ((size_t)g * HW + tid) * Dm;
#pragma unroll
                for (int d = 0; d < Dm; d++) y[d] += yp[d];
            }
            float m = 0.f;
#pragma unroll
            for (int d = 0; d < Dm; d++) m += y[d];
            m *= (1.0f / Dm);
            float v = 0.f;
#pragma unroll
            for (int d = 0; d < Dm; d++) { float tt = y[d] - m; v = fmaf(tt, tt, v); }
            v *= (1.0f / Dm);
            float inv = rsqrtf(v + EPSV);
#pragma unroll
            for (int d = 0; d < Dm; d++) rows[tid * Dm + d] = (y[d] - m) * inv * g22[d] + b22[d];
        }
        __syncthreads();
        if (tid < Dm) {
            float s = 0.f;
            for (int r = 0; r < HW; r++) s += rows[r * Dm + tid];
            out[tid] = s * (1.0f / 81.0f);
        }
    }
}

// ---------------------------------------------------------------------------
extern "C" void kernel_launch(void* const* d_in, const int* in_sizes, int n_in,
                              void* d_out, int out_size) {
    const float* obs = (const float*)d_in[0];
    const float* c1w = (const float*)d_in[1];
    const float* c1b = (const float*)d_in[2];
    const float* c2w = (const float*)d_in[3];
    const float* c2b = (const float*)d_in[4];
    const float* ipw = (const float*)d_in[5];
    const float* ipb = (const float*)d_in[6];
    const float* opw = (const float*)d_in[7];
    const float* opb = (const float*)d_in[8];
    const float* l1w = (const float*)d_in[9];
    const float* l1b = (const float*)d_in[10];
    const float* l2w = (const float*)d_in[11];
    const float* l2b = (const float*)d_in[12];
    const float* g1  = (const float*)d_in[13];
    const float* b1  = (const float*)d_in[14];
    const float* g2  = (const float*)d_in[15];
    const float* b2  = (const float*)d_in[16];
    float* out = (float*)d_out;

    front<<<148, 256>>>(obs, c1w, c1b, c2w, c2b, ipw, ipb);
    attn_struct<<<dim3(HW, NH), 512>>>();
    tokens_proj_ln<<<(S + 63) / 64, 128>>>(opw, opb, g1, b1);
    ffn0<<<dim3((S + 127) / 128, 1, NFSEG), 64>>>(l1w, l1b, l2w);
    ffnred_qkv<<<(S + 31) / 32, 256>>>(ipw + 102 * Dm, ipb + 102, l2b, g2, b2);
    agent_tail<<<148, 256>>>(opw + Dm * Dm, opb + Dm, g1 + Dm, b1 + Dm,
                             l1w + FFd * Dm, l1b + FFd, l2w + Dm * FFd, l2b + Dm,
                             g2 + Dm, b2 + Dm, out);
}

// round 11
// speedup vs baseline: 3.9527x; 1.0208x over previous
#include <cuda_runtime.h>

#define S      6561
#define Dm     34
#define HD     17
#define PH     20
#define PAC    18
#define FFd    2048
#define NH     2
#define HW     81
#define EPSV   1e-5f
#define ESTR   (NH * HW * HW)
// layer-0 FFN tiling: 16 f-segments of 128, 2 rows/thread, 64-thread blocks
#define NFSEG  16
#define FSEG   128
#define FCHK0  64
// layer-1 agent attention: 2 heads x 74 segs = 148 blocks
#define NSEG2  74
#define KSEG2  89
// agent FFN split
#define NFSEG2 32
#define FSEG2  64

typedef unsigned long long u64;

// ---- packed fp32 helpers ----
__device__ __forceinline__ u64 fma2(u64 a, u64 b, u64 c) {
    u64 d; asm("fma.rn.f32x2 %0, %1, %2, %3;" : "=l"(d) : "l"(a), "l"(b), "l"(c)); return d;
}
__device__ __forceinline__ u64 mul2(u64 a, u64 b) {
    u64 d; asm("mul.rn.f32x2 %0, %1, %2;" : "=l"(d) : "l"(a), "l"(b)); return d;
}
__device__ __forceinline__ u64 add2(u64 a, u64 b) {
    u64 d; asm("add.rn.f32x2 %0, %1, %2;" : "=l"(d) : "l"(a), "l"(b)); return d;
}
__device__ __forceinline__ float2 unpk(u64 v) {
    float2 f; asm("mov.b64 {%0, %1}, %2;" : "=f"(f.x), "=f"(f.y) : "l"(v)); return f;
}
__device__ __forceinline__ u64 pk(float x, float y) {
    u64 v; asm("mov.b64 %0, {%1, %2};" : "=l"(v) : "f"(x), "f"(y)); return v;
}

// ---- device-global scratch ----
__device__ unsigned g_cnt;
__device__ unsigned g_sense;
__device__ int   g_agent;
__device__ __align__(16) float g_emb[HW * 16];
__device__ __align__(16) float g_x[S * Dm];
__device__ __align__(16) float g_q[NH * S * PH];
__device__ __align__(16) float g_k[NH * S * PH];
__device__ __align__(16) float g_v[NH * S * PH];
__device__ __align__(16) float g_o[S * Dm];
__device__ __align__(16) float g_yp[NFSEG * S * Dm];
__device__ __align__(16) float g_QA[NH * HW * HD];
__device__ __align__(16) float g_QB[NH * HW * HD];
__device__ __align__(16) float g_KA[NH * HW * HD];
__device__ __align__(16) float g_KB[NH * HW * HD];
__device__ __align__(16) float g_VA[NH * HW * HD];
__device__ __align__(16) float g_VB[NH * HW * HD];
__device__ __align__(16) float g_E[4 * ESTR];    // EA, EB row-major; EC, ED TRANSPOSED
__device__ __align__(16) float g_pacca[NH * NSEG2 * HW * PAC];
__device__ float g_psuma[NH * NSEG2 * HW];
__device__ __align__(16) float g_xa[HW * Dm];
__device__ __align__(16) float g_ypa[NFSEG2 * HW * Dm];
__device__ __align__(16) float g_oa[HW * Dm];

// ---- sense-reversing grid barrier (all blocks resident) ----
__device__ __forceinline__ void gsync(unsigned& ls) {
    __syncthreads();
    if (threadIdx.x == 0) {
        unsigned ns = ls ^ 1u;
        __threadfence();
        unsigned old = atomicAdd(&g_cnt, 1u);
        if (old == gridDim.x - 1u) {
            g_cnt = 0u;
            __threadfence();
            atomicExch(&g_sense, ns);
        } else {
            while (atomicAdd(&g_sense, 0u) != ns) { __nanosleep(64); }
        }
        ls = ns;
        __threadfence();
    }
    __syncthreads();
}

// ---------------------------------------------------------------------------
// K1 (fused front): conv+argmax -> basis QKV -> exp(logits). grid 148x256.
// ---------------------------------------------------------------------------
__global__ void __launch_bounds__(256) front(
    const float* __restrict__ obs,
    const float* __restrict__ c1w, const float* __restrict__ c1b,
    const float* __restrict__ c2w, const float* __restrict__ c2b,
    const float* __restrict__ ipw, const float* __restrict__ ipb)
{
    __shared__ float so[192];
    __shared__ float c1s[1296];
    int tid = threadIdx.x;
    int b = blockIdx.x;
    unsigned ls = 0;

    if (b == 0) {
        for (int i = tid; i < 162; i += 256) so[i] = obs[i];
        __syncthreads();
        if (tid == 0) {
            float mx = so[0]; int mi = 0;
            for (int i = 1; i < 81; i++) if (so[i] > mx) { mx = so[i]; mi = i; }
            g_agent = mi;
        }
        for (int idx = tid; idx < 16 * 81; idx += 256) {
            int ch = idx / 81, pos = idx % 81, r = pos / 9, c = pos % 9;
            float acc = c1b[ch];
            for (int ci = 0; ci < 2; ci++)
                for (int dr = 0; dr < 3; dr++) {
                    int rr = r + dr - 1; if (rr < 0 || rr >= 9) continue;
                    for (int dc = 0; dc < 3; dc++) {
                        int cc = c + dc - 1; if (cc < 0 || cc >= 9) continue;
                        acc += so[ci * 81 + rr * 9 + cc] * c1w[((ch * 2 + ci) * 3 + dr) * 3 + dc];
                    }
                }
            c1s[idx] = fmaxf(acc, 0.f);
        }
        __syncthreads();
        for (int idx = tid; idx < 16 * 81; idx += 256) {
            int ch = idx / 81, pos = idx % 81, r = pos / 9, c = pos % 9;
            float acc = c2b[ch];
            for (int ci = 0; ci < 16; ci++)
                for (int dr = 0; dr < 3; dr++) {
                    int rr = r + dr - 1; if (rr < 0 || rr >= 9) continue;
                    for (int dc = 0; dc < 3; dc++) {
                        int cc = c + dc - 1; if (cc < 0 || cc >= 9) continue;
                        acc += c1s[ci * 81 + rr * 9 + cc] * c2w[((ch * 16 + ci) * 3 + dr) * 3 + dc];
                    }
                }
            g_emb[pos * 16 + ch] = fmaxf(acc, 0.f);
        }
    }
    gsync(ls);  // 1

    for (int idx = b * 256 + tid; idx < 162 * 102; idx += 148 * 256) {
        int v = idx / 102, c = idx % 102;
        const float* wr = ipw + c * Dm;
        float acc;
        if (v < 81) {
            int i = v;
            acc = ipb[c];
#pragma unroll
            for (int d = 0; d < 16; d++) acc = fmaf(g_emb[i * 16 + d], wr[d], acc);
            acc = fmaf((float)(i / 9) * 0.25f, wr[32], acc);
            acc = fmaf((float)(i % 9) * 0.25f, wr[33], acc);
        } else {
            int j = v - 81;
            acc = 0.f;
#pragma unroll
            for (int d = 0; d < 16; d++) acc = fmaf(g_emb[j * 16 + d], wr[16 + d], acc);
            acc = fmaf(-(float)(j / 9) * 0.25f, wr[32], acc);
            acc = fmaf(-(float)(j % 9) * 0.25f, wr[33], acc);
        }
        int kind = c / Dm;
        int cc = c % Dm;
        int h = cc / HD, dd = cc % HD;
        int off = (h * HW + (v % 81)) * HD + dd;
        if (kind == 0) {
            float sv = acc * rsqrtf(17.f);
            if (v < 81) g_QA[off] = sv; else g_QB[off] = sv;
        } else if (kind == 1) {
            if (v < 81) g_KA[off] = acc; else g_KB[off] = acc;
        } else {
            if (v < 81) g_VA[off] = acc; else g_VB[off] = acc;
        }
    }
    gsync(ls);  // 2

    for (int idx = b * 256 + tid; idx < 4 * ESTR; idx += 148 * 256) {
        int p = idx / ESTR;
        int r = idx % ESTR;
        int h = r / (HW * HW);
        int q2 = r % (HW * HW);
        int i = q2 / HW, m = q2 % HW;
        const float* L;
        const float* R;
        if (p == 0)      { L = g_QA + (h * HW + i) * HD; R = g_KA + (h * HW + m) * HD; }
        else if (p == 1) { L = g_QA + (h * HW + i) * HD; R = g_KB + (h * HW + m) * HD; }
        else if (p == 2) { L = g_KA + (h * HW + i) * HD; R = g_QB + (h * HW + m) * HD; }
        else             { L = g_KB + (h * HW + i) * HD; R = g_QB + (h * HW + m) * HD; }
        float dot = 0.f;
#pragma unroll
        for (int d = 0; d < HD; d++) dot = fmaf(L[d], R[d], dot);
        g_E[idx] = __expf(dot);
    }
}

// ---------------------------------------------------------------------------
// K2: structured attention -> g_o (EC/ED transposed, coalesced)
// ---------------------------------------------------------------------------
__global__ void __launch_bounds__(512) attn_struct() {
    __shared__ float sea[HW], seb[HW];
    __shared__ __align__(16) float sva[HW * 18];
    __shared__ __align__(16) float svb[HW * 18];
    __shared__ float psum[4 * HW];
    __shared__ __align__(16) u64 pacc[4 * HW * 9];
    int tid = threadIdx.x;
    int i = blockIdx.x, h = blockIdx.y;
    for (int t = tid; t < HW; t += 512) {
        sea[t] = g_E[0 * ESTR + (h * HW + i) * HW + t];
        seb[t] = g_E[1 * ESTR + (h * HW + i) * HW + t];
    }
    for (int t = tid; t < HW * 18; t += 512) {
        int m = t / 18, d = t % 18;
        sva[t] = (d < HD) ? g_VA[(h * HW + m) * HD + d] : 0.f;
        svb[t] = (d < HD) ? g_VB[(h * HW + m) * HD + d] : 0.f;
    }
    __syncthreads();
    int quad = tid >> 7;
    int j = tid & 127;
    if (j < HW) {
        bool isA = quad < 2;
        int lo = (quad & 1) ? 41 : 0;
        int hi = (quad & 1) ? HW : 41;
        const float* et = g_E + (isA ? 2 : 3) * ESTR + h * HW * HW + j;
        const float* se = isA ? sea : seb;
        const float* sv = isA ? sva : svb;
        float z = 0.f;
        u64 w[9];
#pragma unroll
        for (int k = 0; k < 9; k++) w[k] = 0ULL;
#pragma unroll 4
        for (int m = lo; m < hi; m++) {
            float f = se[m] * et[m * HW];
            z += f;
            u64 fp = pk(f, f);
            const u64* vr = (const u64*)(sv + m * 18);
#pragma unroll
            for (int k = 0; k < 9; k++) w[k] = fma2(fp, vr[k], w[k]);
        }
        psum[quad * HW + j] = z;
        u64* pw = pacc + (quad * HW + j) * 9;
#pragma unroll
        for (int k = 0; k < 9; k++) pw[k] = w[k];
    }
    __syncthreads();
    if (tid < HW) {
        int jj = tid;
        float zm = psum[jj] + psum[HW + jj];
        float zn = psum[2 * HW + jj] + psum[3 * HW + jj];
        const u64* p0 = pacc + jj * 9;
        const u64* p1 = pacc + (HW + jj) * 9;
        const u64* p2 = pacc + (2 * HW + jj) * 9;
        const u64* p3 = pacc + (3 * HW + jj) * 9;
        float inv = 1.0f / (zm * zn);
        float* od = g_o + (i * HW + jj) * Dm + h * HD;
#pragma unroll
        for (int k = 0; k < 9; k++) {
            float2 A = unpk(add2(p0[k], p1[k]));
            float2 B = unpk(add2(p2[k], p3[k]));
            int d = 2 * k;
            od[d] = (A.x * zn + B.x * zm) * inv;
            if (d + 1 < HD) od[d + 1] = (A.y * zn + B.y * zm) * inv;
        }
    }
}

// ---------------------------------------------------------------------------
// K3: tokens + out_proj + residual + LN1 -> g_x
// ---------------------------------------------------------------------------
__global__ void __launch_bounds__(128) tokens_proj_ln(const float* __restrict__ opw,
                                                      const float* __restrict__ opb,
                                                      const float* __restrict__ gg,
                                                      const float* __restrict__ bb) {
    __shared__ float embs[1296];
    __shared__ float ws[Dm * Dm];
    __shared__ float bs[Dm], gs[Dm], bts[Dm];
    __shared__ float ys[64 * 36];
    int tid = threadIdx.x;
    for (int i = tid; i < 1296; i += 128) embs[i] = g_emb[i];
    for (int i = tid; i < Dm * Dm; i += 128) ws[i] = opw[i];
    if (tid < Dm) { bs[tid] = opb[tid]; gs[tid] = gg[tid]; bts[tid] = bb[tid]; }
    __syncthreads();
    int half = tid >> 6;
    int lt = tid & 63;
    int t = blockIdx.x * 64 + lt;
    if (t < S) {
        int i = t / HW, j = t % HW;
        float orow[Dm];
#pragma unroll
        for (int d = 0; d < Dm; d++) orow[d] = g_o[t * Dm + d];
        int dlo = half * 17;
#pragma unroll 1
        for (int d = dlo; d < dlo + 17; d++) {
            float xv;
            if (d < 16)       xv = embs[i * 16 + d];
            else if (d < 32)  xv = embs[j * 16 + (d - 16)];
            else if (d == 32) xv = ((float)(i / 9) - (float)(j / 9)) * 0.25f;
            else              xv = ((float)(i % 9) - (float)(j % 9)) * 0.25f;
            float a = bs[d] + xv;
            const float* wp = ws + d * Dm;
#pragma unroll
            for (int k = 0; k < Dm; k++) a = fmaf(orow[k], wp[k], a);
            ys[lt * 36 + d] = a;
        }
    }
    __syncthreads();
    if (half == 0 && t < S) {
        float y[Dm];
#pragma unroll
        for (int d = 0; d < Dm; d++) y[d] = ys[lt * 36 + d];
        float m = 0.f;
#pragma unroll
        for (int d = 0; d < Dm; d++) m += y[d];
        m *= (1.0f / Dm);
        float v = 0.f;
#pragma unroll
        for (int d = 0; d < Dm; d++) { float tt = y[d] - m; v = fmaf(tt, tt, v); }
        v *= (1.0f / Dm);
        float inv = rsqrtf(v + EPSV);
#pragma unroll
        for (int d = 0; d < Dm; d++) g_x[t * Dm + d] = (y[d] - m) * inv * gs[d] + bts[d];
    }
}

// ---------------------------------------------------------------------------
// K4: layer-0 FFN partials — 2 rows/thread, 64-thread blocks, 5 blocks/SM,
// NFSEG=16 segments for 1640 warps (~11/SM). grid (52, 1, 16).
// ---------------------------------------------------------------------------
__global__ void __launch_bounds__(64, 5) ffn0(const float* __restrict__ l1w,
                                              const float* __restrict__ l1b,
                                              const float* __restrict__ l2w) {
    __shared__ __align__(16) float W1s[FCHK0 * 36];
    __shared__ __align__(16) float W2s[FCHK0 * 36];
    __shared__ float b1s[FCHK0];
    int tid = threadIdx.x;
    int row0 = blockIdx.x * 128 + tid;
    int row1 = row0 + 64;
    int fbase = blockIdx.z * FSEG;
    bool a0 = row0 < S, a1 = row1 < S;
    u64 x0[17], x1[17], y0[17], y1[17];
#pragma unroll
    for (int i = 0; i < 17; i++) { x0[i] = 0ULL; x1[i] = 0ULL; y0[i] = 0ULL; y1[i] = 0ULL; }
    if (a0) {
        const u64* p = (const u64*)(g_x + row0 * Dm);
#pragma unroll
        for (int i = 0; i < 17; i++) x0[i] = p[i];
    }
    if (a1) {
        const u64* p = (const u64*)(g_x + row1 * Dm);
#pragma unroll
        for (int i = 0; i < 17; i++) x1[i] = p[i];
    }
    for (int fc = fbase; fc < fbase + FSEG; fc += FCHK0) {
        for (int e = tid; e < FCHK0 * Dm; e += 64) {
            int f = e / Dm, d = e % Dm;
            W1s[f * 36 + d] = l1w[(fc + f) * Dm + d];
            W2s[f * 36 + d] = l2w[d * FFd + fc + f];
        }
        if (tid < FCHK0) b1s[tid] = l1b[fc + tid];
        __syncthreads();
#pragma unroll 2
        for (int f = 0; f < FCHK0; f++) {
            const ulonglong2* w2p = (const ulonglong2*)(W1s + f * 36);
            const u64*        w1p = (const u64*)(W1s + f * 36);
            ulonglong2 a0v = w2p[0], a1v = w2p[1], a2v = w2p[2], a3v = w2p[3];
            ulonglong2 a4v = w2p[4], a5v = w2p[5], a6v = w2p[6], a7v = w2p[7];
            u64 a16 = w1p[16];
            u64 t0 = mul2(x0[0], a0v.x),  t1 = mul2(x0[1], a0v.y);
            u64 u0 = mul2(x1[0], a0v.x),  u1 = mul2(x1[1], a0v.y);
            t0 = fma2(x0[2], a1v.x, t0);  t1 = fma2(x0[3], a1v.y, t1);
            u0 = fma2(x1[2], a1v.x, u0);  u1 = fma2(x1[3], a1v.y, u1);
            t0 = fma2(x0[4], a2v.x, t0);  t1 = fma2(x0[5], a2v.y, t1);
            u0 = fma2(x1[4], a2v.x, u0);  u1 = fma2(x1[5], a2v.y, u1);
            t0 = fma2(x0[6], a3v.x, t0);  t1 = fma2(x0[7], a3v.y, t1);
            u0 = fma2(x1[6], a3v.x, u0);  u1 = fma2(x1[7], a3v.y, u1);
            t0 = fma2(x0[8], a4v.x, t0);  t1 = fma2(x0[9], a4v.y, t1);
            u0 = fma2(x1[8], a4v.x, u0);  u1 = fma2(x1[9], a4v.y, u1);
            t0 = fma2(x0[10], a5v.x, t0); t1 = fma2(x0[11], a5v.y, t1);
            u0 = fma2(x1[10], a5v.x, u0); u1 = fma2(x1[11], a5v.y, u1);
            t0 = fma2(x0[12], a6v.x, t0); t1 = fma2(x0[13], a6v.y, t1);
            u0 = fma2(x1[12], a6v.x, u0); u1 = fma2(x1[13], a6v.y, u1);
            t0 = fma2(x0[14], a7v.x, t0); t1 = fma2(x0[15], a7v.y, t1);
            u0 = fma2(x1[14], a7v.x, u0); u1 = fma2(x1[15], a7v.y, u1);
            t0 = fma2(x0[16], a16, t0);
            u0 = fma2(x1[16], a16, u0);
            t0 = add2(t0, t1);
            u0 = add2(u0, u1);
            float2 fh0 = unpk(t0), fh1 = unpk(u0);
            float h0 = fmaxf(fh0.x + fh0.y + b1s[f], 0.f);
            float h1 = fmaxf(fh1.x + fh1.y + b1s[f], 0.f);
            u64 hp0 = pk(h0, h0), hp1 = pk(h1, h1);
            const ulonglong2* v2p = (const ulonglong2*)(W2s + f * 36);
            const u64*        v1p = (const u64*)(W2s + f * 36);
            ulonglong2 b0v = v2p[0], b1v = v2p[1], b2v = v2p[2], b3v = v2p[3];
            ulonglong2 b4v = v2p[4], b5v = v2p[5], b6v = v2p[6], b7v = v2p[7];
            u64 b16 = v1p[16];
            y0[0]  = fma2(hp0, b0v.x, y0[0]);   y1[0]  = fma2(hp1, b0v.x, y1[0]);
            y0[1]  = fma2(hp0, b0v.y, y0[1]);   y1[1]  = fma2(hp1, b0v.y, y1[1]);
            y0[2]  = fma2(hp0, b1v.x, y0[2]);   y1[2]  = fma2(hp1, b1v.x, y1[2]);
            y0[3]  = fma2(hp0, b1v.y, y0[3]);   y1[3]  = fma2(hp1, b1v.y, y1[3]);
            y0[4]  = fma2(hp0, b2v.x, y0[4]);   y1[4]  = fma2(hp1, b2v.x, y1[4]);
            y0[5]  = fma2(hp0, b2v.y, y0[5]);   y1[5]  = fma2(hp1, b2v.y, y1[5]);
            y0[6]  = fma2(hp0, b3v.x, y0[6]);   y1[6]  = fma2(hp1, b3v.x, y1[6]);
            y0[7]  = fma2(hp0, b3v.y, y0[7]);   y1[7]  = fma2(hp1, b3v.y, y1[7]);
            y0[8]  = fma2(hp0, b4v.x, y0[8]);   y1[8]  = fma2(hp1, b4v.x, y1[8]);
            y0[9]  = fma2(hp0, b4v.y, y0[9]);   y1[9]  = fma2(hp1, b4v.y, y1[9]);
            y0[10] = fma2(hp0, b5v.x, y0[10]);  y1[10] = fma2(hp1, b5v.x, y1[10]);
            y0[11] = fma2(hp0, b5v.y, y0[11]);  y1[11] = fma2(hp1, b5v.y, y1[11]);
            y0[12] = fma2(hp0, b6v.x, y0[12]);  y1[12] = fma2(hp1, b6v.x, y1[12]);
            y0[13] = fma2(hp0, b6v.y, y0[13]);  y1[13] = fma2(hp1, b6v.y, y1[13]);
            y0[14] = fma2(hp0, b7v.x, y0[14]);  y1[14] = fma2(hp1, b7v.x, y1[14]);
            y0[15] = fma2(hp0, b7v.y, y0[15]);  y1[15] = fma2(hp1, b7v.y, y1[15]);
            y0[16] = fma2(hp0, b16, y0[16]);    y1[16] = fma2(hp1, b16, y1[16]);
        }
        __syncthreads();
    }
    if (a0) {
        u64* yo = (u64*)(g_yp + ((size_t)blockIdx.z * S + row0) * Dm);
#pragma unroll
        for (int i = 0; i < 17; i++) yo[i] = y0[i];
    }
    if (a1) {
        u64* yo = (u64*)(g_yp + ((size_t)blockIdx.z * S + row1) * Dm);
#pragma unroll
        for (int i = 0; i < 17; i++) yo[i] = y1[i];
    }
}

// ---------------------------------------------------------------------------
// K5: FFN reduce + LN2 + layer-1 QKV fused
// ---------------------------------------------------------------------------
__global__ void __launch_bounds__(256) ffnred_qkv(const float* __restrict__ ipw2,
                                                  const float* __restrict__ ipb2,
                                                  const float* __restrict__ l2b,
                                                  const float* __restrict__ gg,
                                                  const float* __restrict__ bb) {
    __shared__ float xs[Dm * 32];
    __shared__ float ws[102 * Dm];
    __shared__ float bs[102];
    __shared__ __align__(16) float pre[32 * 36];
    __shared__ float l2bs[Dm], gs[Dm], bts[Dm];
    int tid = threadIdx.x;
    int row0 = blockIdx.x * 32;
    for (int i = tid; i < 102 * Dm; i += 256) ws[i] = ipw2[i];
    if (tid < 102) bs[tid] = ipb2[tid];
    if (tid < Dm) { l2bs[tid] = l2b[tid]; gs[tid] = gg[tid]; bts[tid] = bb[tid]; }
    for (int e = tid; e < 32 * 17; e += 256) {
        int r = e / 17, k = e % 17;
        int row = row0 + r;
        if (row < S) {
            u64 acc = ((const u64*)(g_x + row * Dm))[k];
#pragma unroll
            for (int g = 0; g < NFSEG; g++)
                acc = add2(acc, ((const u64*)(g_yp + ((size_t)g * S + row) * Dm))[k]);
            ((u64*)(pre + r * 36))[k] = acc;
        }
    }
    __syncthreads();
    if (tid < 32 && row0 + tid < S) {
        float y[Dm];
#pragma unroll
        for (int d = 0; d < Dm; d++) y[d] = pre[tid * 36 + d] + l2bs[d];
        float m = 0.f;
#pragma unroll
        for (int d = 0; d < Dm; d++) m += y[d];
        m *= (1.0f / Dm);
        float v = 0.f;
#pragma unroll
        for (int d = 0; d < Dm; d++) { float tt = y[d] - m; v = fmaf(tt, tt, v); }
        v *= (1.0f / Dm);
        float inv = rsqrtf(v + EPSV);
        int row = row0 + tid;
#pragma unroll
        for (int d = 0; d < Dm; d++) {
            float xv = (y[d] - m) * inv * gs[d] + bts[d];
            xs[d * 32 + tid] = xv;
            g_x[row * Dm + d] = xv;
        }
    }
    __syncthreads();
    const float scale = rsqrtf(17.f);
    int lane = tid & 31, w = tid >> 5;
    int s = row0 + lane;
    for (int cc = w; cc < 102; cc += 8) {
        float acc = bs[cc];
        const float* wp = ws + cc * Dm;
#pragma unroll
        for (int d = 0; d < Dm; d++) acc = fmaf(xs[d * 32 + lane], wp[d], acc);
        if (s < S) {
            int kind = cc / Dm;
            int c2 = cc % Dm;
            int h = c2 / HD, dd = c2 % HD;
            int off = (h * S + s) * PH + dd;
            if (kind == 0)      g_q[off] = acc * scale;
            else if (kind == 1) g_k[off] = acc;
            else                g_v[off] = acc;
        }
    }
}

// ---------------------------------------------------------------------------
// K6 (fused agent tail)
// ---------------------------------------------------------------------------
__global__ void __launch_bounds__(256) agent_tail(
    const float* __restrict__ opw2, const float* __restrict__ opb2,
    const float* __restrict__ g12,  const float* __restrict__ b12,
    const float* __restrict__ l1w2, const float* __restrict__ l1b2,
    const float* __restrict__ l2w2, const float* __restrict__ l2b2,
    const float* __restrict__ g22,  const float* __restrict__ b22,
    float* __restrict__ out)
{
    __shared__ __align__(16) float sm[4800];
    int tid = threadIdx.x;
    int b = blockIdx.x;
    unsigned ls = 0;

    {
        int h = b / NSEG2;
        int seg = b % NSEG2;
        int k0 = seg * KSEG2;
        int n = min(KSEG2, S - k0);
        float* Ks = sm;
        float* Vs = sm + 1800;
        const float4* ksrc = (const float4*)(g_k + (h * S + k0) * PH);
        const float4* vsrc = (const float4*)(g_v + (h * S + k0) * PH);
        float4* kdst = (float4*)Ks; float4* vdst = (float4*)Vs;
        for (int i = tid; i < n * 5; i += 256) { kdst[i] = ksrc[i]; vdst[i] = vsrc[i]; }
        __syncthreads();
        if (tid < HW) {
            int start = g_agent * HW;
            u64 q[9], acc[9];
            const u64* qp = (const u64*)(g_q + (h * S + start + tid) * PH);
#pragma unroll
            for (int i = 0; i < 9; i++) { q[i] = qp[i]; acc[i] = 0ULL; }
            float ssum = 0.f;
            const ulonglong2* K2 = (const ulonglong2*)Ks;
            const ulonglong2* V2 = (const ulonglong2*)Vs;
            for (int kk = 0; kk < n; kk++) {
                ulonglong2 ka = K2[0], kb = K2[1], kc = K2[2], kd = K2[3];
                u64 ke = K2[4].x;
                u64 t0 = mul2(q[0], ka.x),  t1 = mul2(q[1], ka.y);
                t0 = fma2(q[2], kb.x, t0);  t1 = fma2(q[3], kb.y, t1);
                t0 = fma2(q[4], kc.x, t0);  t1 = fma2(q[5], kc.y, t1);
                t0 = fma2(q[6], kd.x, t0);  t1 = fma2(q[7], kd.y, t1);
                t0 = fma2(q[8], ke, t0);
                t0 = add2(t0, t1);
                float2 f = unpk(t0);
                float p = __expf(f.x + f.y);
                ssum += p;
                u64 pp = pk(p, p);
                ulonglong2 va = V2[0], vb = V2[1], vc = V2[2], vd = V2[3];
                u64 ve = V2[4].x;
                acc[0] = fma2(pp, va.x, acc[0]); acc[1] = fma2(pp, va.y, acc[1]);
                acc[2] = fma2(pp, vb.x, acc[2]); acc[3] = fma2(pp, vb.y, acc[3]);
                acc[4] = fma2(pp, vc.x, acc[4]); acc[5] = fma2(pp, vc.y, acc[5]);
                acc[6] = fma2(pp, vd.x, acc[6]); acc[7] = fma2(pp, vd.y, acc[7]);
                acc[8] = fma2(pp, ve, acc[8]);
                K2 += 5; V2 += 5;
            }
            u64* pa = (u64*)(g_pacca + ((h * NSEG2 + seg) * HW + tid) * PAC);
#pragma unroll
            for (int i = 0; i < 9; i++) pa[i] = acc[i];
            g_psuma[(h * NSEG2 + seg) * HW + tid] = ssum;
        }
    }
    gsync(ls);  // 1

    {
        int e = b * 256 + tid;
        if (b < 11 && e < HW * Dm) {
            int r = e / Dm, c = e % Dm;
            int h = c / HD, d = c % HD;
            float a = 0.f, smm = 0.f;
#pragma unroll 4
            for (int g = 0; g < NSEG2; g++) {
                a   += g_pacca[((h * NSEG2 + g) * HW + r) * PAC + d];
                smm += g_psuma[(h * NSEG2 + g) * HW + r];
            }
            g_oa[e] = a / smm;
        }
    }
    gsync(ls);  // 2

    if (b == 0) {
        float* ws  = sm;
        float* bs  = sm + 1156;
        float* gs  = sm + 1190;
        float* bts = sm + 1224;
        for (int i = tid; i < Dm * Dm; i += 256) ws[i] = opw2[i];
        if (tid < Dm) { bs[tid] = opb2[tid]; gs[tid] = g12[tid]; bts[tid] = b12[tid]; }
        __syncthreads();
        if (tid < HW) {
            int s = g_agent * HW + tid;
            float orow[Dm], y[Dm];
#pragma unroll
            for (int d = 0; d < Dm; d++) orow[d] = g_oa[tid * Dm + d];
#pragma unroll 2
            for (int d = 0; d < Dm; d++) {
                float a = bs[d] + g_x[s * Dm + d];
                const float* wp = ws + d * Dm;
#pragma unroll
                for (int k = 0; k < Dm; k++) a = fmaf(orow[k], wp[k], a);
                y[d] = a;
            }
            float m = 0.f;
#pragma unroll
            for (int d = 0; d < Dm; d++) m += y[d];
            m *= (1.0f / Dm);
            float v = 0.f;
#pragma unroll
            for (int d = 0; d < Dm; d++) { float tt = y[d] - m; v = fmaf(tt, tt, v); }
            v *= (1.0f / Dm);
            float inv = rsqrtf(v + EPSV);
#pragma unroll
            for (int d = 0; d < Dm; d++) g_xa[tid * Dm + d] = (y[d] - m) * inv * gs[d] + bts[d];
        }
    }
    gsync(ls);  // 3

    if (b < NFSEG2) {
        float* W1s = sm;
        float* W2s = sm + 2304;
        float* b1s = sm + 4608;
        int fbase = b * FSEG2;
        for (int e = tid; e < FSEG2 * Dm; e += 256) {
            int f = e / Dm, d = e % Dm;
            W1s[f * 36 + d] = l1w2[(fbase + f) * Dm + d];
            W2s[f * 36 + d] = l2w2[d * FFd + fbase + f];
        }
        if (tid < FSEG2) b1s[tid] = l1b2[fbase + tid];
        __syncthreads();
        if (tid < HW) {
            u64 xr[17], y[17];
            const u64* p = (const u64*)(g_xa + tid * Dm);
#pragma unroll
            for (int i = 0; i < 17; i++) { xr[i] = p[i]; y[i] = 0ULL; }
#pragma unroll 2
            for (int f = 0; f < FSEG2; f++) {
                const ulonglong2* w2p = (const ulonglong2*)(W1s + f * 36);
                const u64*        w1p = (const u64*)(W1s + f * 36);
                ulonglong2 a0 = w2p[0], a1 = w2p[1], a2 = w2p[2], a3 = w2p[3];
                ulonglong2 a4 = w2p[4], a5 = w2p[5], a6 = w2p[6], a7 = w2p[7];
                u64 a16 = w1p[16];
                u64 t0 = mul2(xr[0], a0.x),  t1 = mul2(xr[1], a0.y);
                t0 = fma2(xr[2], a1.x, t0);  t1 = fma2(xr[3], a1.y, t1);
                t0 = fma2(xr[4], a2.x, t0);  t1 = fma2(xr[5], a2.y, t1);
                t0 = fma2(xr[6], a3.x, t0);  t1 = fma2(xr[7], a3.y, t1);
                t0 = fma2(xr[8], a4.x, t0);  t1 = fma2(xr[9], a4.y, t1);
                t0 = fma2(xr[10], a5.x, t0); t1 = fma2(xr[11], a5.y, t1);
                t0 = fma2(xr[12], a6.x, t0); t1 = fma2(xr[13], a6.y, t1);
                t0 = fma2(xr[14], a7.x, t0); t1 = fma2(xr[15], a7.y, t1);
                t0 = fma2(xr[16], a16, t0);
                t0 = add2(t0, t1);
                float2 fh = unpk(t0);
                float hrelu = fmaxf(fh.x + fh.y + b1s[f], 0.f);
                u64 hp = pk(hrelu, hrelu);
                const ulonglong2* v2p = (const ulonglong2*)(W2s + f * 36);
                const u64*        v1p = (const u64*)(W2s + f * 36);
                ulonglong2 b0 = v2p[0], b1v = v2p[1], b2v = v2p[2], b3 = v2p[3];
                ulonglong2 b4 = v2p[4], b5 = v2p[5], b6 = v2p[6], b7 = v2p[7];
                u64 b16 = v1p[16];
                y[0]  = fma2(hp, b0.x, y[0]);   y[1]  = fma2(hp, b0.y, y[1]);
                y[2]  = fma2(hp, b1v.x, y[2]);  y[3]  = fma2(hp, b1v.y, y[3]);
                y[4]  = fma2(hp, b2v.x, y[4]);  y[5]  = fma2(hp, b2v.y, y[5]);
                y[6]  = fma2(hp, b3.x, y[6]);   y[7]  = fma2(hp, b3.y, y[7]);
                y[8]  = fma2(hp, b4.x, y[8]);   y[9]  = fma2(hp, b4.y, y[9]);
                y[10] = fma2(hp, b5.x, y[10]);  y[11] = fma2(hp, b5.y, y[11]);
                y[12] = fma2(hp, b6.x, y[12]);  y[13] = fma2(hp, b6.y, y[13]);
                y[14] = fma2(hp, b7.x, y[14]);  y[15] = fma2(hp, b7.y, y[15]);
                y[16] = fma2(hp, b16, y[16]);
            }
            u64* yo = (u64*)(g_ypa + ((size_t)b * HW + tid) * Dm);
#pragma unroll
            for (int i = 0; i < 17; i++) yo[i] = y[i];
        }
    }
    gsync(ls);  // 4

    if (b == 0) {
        float* rows = sm;
        if (tid < HW) {
            float y[Dm];
#pragma unroll
            for (int d = 0; d < Dm; d++) y[d] = g_xa[tid * Dm + d] + l2b2[d];
            for (int g = 0; g < NFSEG2; g++) {
                const float* yp = g_ypa + ((size_t)g * HW + tid) * Dm;
#pragma unroll
                for (int d = 0; d < Dm; d++) y[d] += yp[d];
            }
            float m = 0.f;
#pragma unroll
            for (int d = 0; d < Dm; d++) m += y[d];
            m *= (1.0f / Dm);
            float v = 0.f;
#pragma unroll
            for (int d = 0; d < Dm; d++) { float tt = y[d] - m; v = fmaf(tt, tt, v); }
            v *= (1.0f / Dm);
            float inv = rsqrtf(v + EPSV);
#pragma unroll
            for (int d = 0; d < Dm; d++) rows[tid * Dm + d] = (y[d] - m) * inv * g22[d] + b22[d];
        }
        __syncthreads();
        if (tid < Dm) {
            float s = 0.f;
            for (int r = 0; r < HW; r++) s += rows[r * Dm + tid];
            out[tid] = s * (1.0f / 81.0f);
        }
    }
}

// ---------------------------------------------------------------------------
extern "C" void kernel_launch(void* const* d_in, const int* in_sizes, int n_in,
                              void* d_out, int out_size) {
    const float* obs = (const float*)d_in[0];
    const float* c1w = (const float*)d_in[1];
    const float* c1b = (const float*)d_in[2];
    const float* c2w = (const float*)d_in[3];
    const float* c2b = (const float*)d_in[4];
    const float* ipw = (const float*)d_in[5];
    const float* ipb = (const float*)d_in[6];
    const float* opw = (const float*)d_in[7];
    const float* opb = (const float*)d_in[8];
    const float* l1w = (const float*)d_in[9];
    const float* l1b = (const float*)d_in[10];
    const float* l2w = (const float*)d_in[11];
    const float* l2b = (const float*)d_in[12];
    const float* g1  = (const float*)d_in[13];
    const float* b1  = (const float*)d_in[14];
    const float* g2  = (const float*)d_in[15];
    const float* b2  = (const float*)d_in[16];
    float* out = (float*)d_out;

    front<<<148, 256>>>(obs, c1w, c1b, c2w, c2b, ipw, ipb);
    attn_struct<<<dim3(HW, NH), 512>>>();
    tokens_proj_ln<<<(S + 63) / 64, 128>>>(opw, opb, g1, b1);
    ffn0<<<dim3((S + 127) / 128, 1, NFSEG), 64>>>(l1w, l1b, l2w);
    ffnred_qkv<<<(S + 31) / 32, 256>>>(ipw + 102 * Dm, ipb + 102, l2b, g2, b2);
    agent_tail<<<148, 256>>>(opw + Dm * Dm, opb + Dm, g1 + Dm, b1 + Dm,
                             l1w + FFd * Dm, l1b + FFd, l2w + Dm * FFd, l2b + Dm,
                             g2 + Dm, b2 + Dm, out);
}